// round 5
// baseline (speedup 1.0000x reference)
#include <cuda_runtime.h>
#include <cuda_bf16.h>
#include <math.h>
#include <stdint.h>

#define N_SEQ 512
#define N_RES 384
#define C_M   256
#define C_OUT 32
#define C_Z   128
#define BC    (N_RES * C_OUT)     /* 12288  (b,c) flattened */
#define NPAIR (N_RES * N_RES)     /* 147456 (b,d) pairs     */
#define KCE   (C_OUT * C_OUT)     /* 1024   (c,e) flattened */

// ---------------- scratch (device globals; no allocation allowed) ----------
__device__ float g_L[(size_t)N_SEQ * BC];            // fp32 [a, bc]
__device__ float g_R[(size_t)N_SEQ * BC];            // fp32 [a, de]
__device__ float g_ninv[NPAIR];
// split-bf16 K-major operands: [bc|de][a]
__device__ __align__(128) __nv_bfloat16 g_Lhi[(size_t)BC * N_SEQ];
__device__ __align__(128) __nv_bfloat16 g_Llo[(size_t)BC * N_SEQ];
__device__ __align__(128) __nv_bfloat16 g_Rhi[(size_t)BC * N_SEQ];
__device__ __align__(128) __nv_bfloat16 g_Rlo[(size_t)BC * N_SEQ];
// W transposed + split: [f][ce]
__device__ __align__(128) __nv_bfloat16 g_Wt_hi[(size_t)C_Z * KCE];
__device__ __align__(128) __nv_bfloat16 g_Wt_lo[(size_t)C_Z * KCE];

// ======================= PTX helpers (baseline sm_80 features) =============
__device__ __forceinline__ uint32_t smem_u32(const void* p) {
    uint32_t a;
    asm("{ .reg .u64 t; cvta.to.shared.u64 t, %1; cvt.u32.u64 %0, t; }"
        : "=r"(a) : "l"(p));
    return a;
}
#define LDSM_X4(r, addr) \
    asm volatile("ldmatrix.sync.aligned.m8n8.x4.shared.b16 {%0,%1,%2,%3}, [%4];" \
                 : "=r"((r)[0]), "=r"((r)[1]), "=r"((r)[2]), "=r"((r)[3]) \
                 : "r"(addr))
#define MMA_BF16(d, a, b0, b1) \
    asm volatile("mma.sync.aligned.m16n8k16.row.col.f32.bf16.bf16.f32 " \
                 "{%0,%1,%2,%3},{%4,%5,%6,%7},{%8,%9},{%0,%1,%2,%3};" \
                 : "+f"((d)[0]), "+f"((d)[1]), "+f"((d)[2]), "+f"((d)[3]) \
                 : "r"((a)[0]), "r"((a)[1]), "r"((a)[2]), "r"((a)[3]), \
                   "r"(b0), "r"(b1))
#define CP_ASYNC16(dst, src) \
    asm volatile("cp.async.cg.shared.global [%0], [%1], 16;" \
                 :: "r"(dst), "l"(src) : "memory")
#define CP_COMMIT() asm volatile("cp.async.commit_group;" ::: "memory")
#define CP_WAIT(n)  asm volatile("cp.async.wait_group %0;" :: "n"(n) : "memory")

// ---------------- Kernel 1: LayerNorm + left/right projection + mask -------
__global__ __launch_bounds__(256) void ln_proj_kernel(
    const float* __restrict__ act, const float* __restrict__ mask,
    const float* __restrict__ ln_scale, const float* __restrict__ ln_offset,
    const float* __restrict__ left_w, const float* __restrict__ left_b,
    const float* __restrict__ right_w, const float* __restrict__ right_b)
{
    int row = blockIdx.x;              // row = a*N_RES + b
    int t = threadIdx.x;
    __shared__ float ys[C_M];
    __shared__ float red[16];
    __shared__ float ps[16][64];

    float x = act[(size_t)row * C_M + t];
    float s = x, s2 = x * x;
    #pragma unroll
    for (int o = 16; o > 0; o >>= 1) {
        s  += __shfl_down_sync(0xffffffffu, s, o);
        s2 += __shfl_down_sync(0xffffffffu, s2, o);
    }
    int wid = t >> 5, lane = t & 31;
    if (lane == 0) { red[wid] = s; red[wid + 8] = s2; }
    __syncthreads();
    float sum = 0.f, sumsq = 0.f;
    #pragma unroll
    for (int i = 0; i < 8; i++) { sum += red[i]; sumsq += red[i + 8]; }
    float mu  = sum * (1.0f / C_M);
    float var = sumsq * (1.0f / C_M) - mu * mu;
    float y = (x - mu) * rsqrtf(var + 1e-5f) * ln_scale[t] + ln_offset[t];
    ys[t] = y;
    __syncthreads();

    int og = t & 15;
    int ch = t >> 4;
    const float* Wp = (og < 8) ? (left_w + og * 4) : (right_w + (og - 8) * 4);
    float p0 = 0.f, p1 = 0.f, p2 = 0.f, p3 = 0.f;
    #pragma unroll
    for (int i = 0; i < 16; i++) {
        int k = ch * 16 + i;
        float4 w4 = *(const float4*)(Wp + (size_t)k * C_OUT);
        float yv = ys[k];
        p0 += yv * w4.x; p1 += yv * w4.y; p2 += yv * w4.z; p3 += yv * w4.w;
    }
    ps[ch][og * 4 + 0] = p0; ps[ch][og * 4 + 1] = p1;
    ps[ch][og * 4 + 2] = p2; ps[ch][og * 4 + 3] = p3;
    __syncthreads();

    if (t < 64) {
        float v = 0.f;
        #pragma unroll
        for (int c = 0; c < 16; c++) v += ps[c][t];
        float m = mask[row];
        int a = row / N_RES, b = row % N_RES;
        size_t idx = (size_t)a * BC + (size_t)b * C_OUT;
        if (t < 32) g_L[idx + t]        = m * (v + left_b[t]);
        else        g_R[idx + (t - 32)] = m * (v + right_b[t - 32]);
    }
}

// ------------- Kernel 1b: transpose + split into bf16 hi/lo [bc][a] --------
__global__ __launch_bounds__(256) void split_tr_kernel()
{
    __shared__ float t[32][65];
    const float* src = blockIdx.z ? g_R : g_L;
    __nv_bfloat16* dh = blockIdx.z ? g_Rhi : g_Lhi;
    __nv_bfloat16* dl = blockIdx.z ? g_Rlo : g_Llo;
    int c0 = blockIdx.x * 64;
    int a0 = blockIdx.y * 32;
    for (int i = threadIdx.x; i < 32 * 64; i += 256) {
        int al = i >> 6, cl = i & 63;
        t[al][cl] = src[(size_t)(a0 + al) * BC + c0 + cl];
    }
    __syncthreads();
    for (int i = threadIdx.x; i < 64 * 32; i += 256) {
        int cl = i >> 5, al = i & 31;
        float x = t[al][cl];
        __nv_bfloat16 hi = __float2bfloat16(x);
        __nv_bfloat16 lo = __float2bfloat16(x - __bfloat162float(hi));
        size_t o = (size_t)(c0 + cl) * N_SEQ + a0 + al;
        dh[o] = hi; dl[o] = lo;
    }
}

// ------ Kernel prep: norm reciprocal (blocks 0..575) + W split (576..703) --
__global__ __launch_bounds__(256) void prep_kernel(
    const float* __restrict__ mask, const float* __restrict__ W)
{
    if (blockIdx.x < 576) {
        int m = blockIdx.x * 256 + threadIdx.x;
        int b = m / N_RES, d = m % N_RES;
        float s = 0.f;
        for (int a = 0; a < N_SEQ; a++)
            s += mask[a * N_RES + b] * mask[a * N_RES + d];
        g_ninv[m] = 1.0f / (1e-3f + s);
    } else {
        __shared__ float t[32][33];
        int bb = blockIdx.x - 576;           // 0..127
        int k0 = (bb & 31) * 32;             // ce tile
        int f0 = (bb >> 5) * 32;             // f tile
        for (int i = threadIdx.x; i < 1024; i += 256) {
            int r = i >> 5, c = i & 31;
            t[r][c] = W[(size_t)(k0 + r) * C_Z + f0 + c];
        }
        __syncthreads();
        for (int i = threadIdx.x; i < 1024; i += 256) {
            int r = i >> 5, c = i & 31;      // r = f local, c = k local
            float x = t[c][r];
            __nv_bfloat16 hi = __float2bfloat16(x);
            __nv_bfloat16 lo = __float2bfloat16(x - __bfloat162float(hi));
            size_t o = (size_t)(f0 + r) * KCE + k0 + c;
            g_Wt_hi[o] = hi; g_Wt_lo[o] = lo;
        }
    }
}

// ============ fused GEMM smem geometry =====================================
#define TILE_B   10240                   /* 128 rows x 80B */
#define STAGE_B  40960                   /* 4 tiles         */
// epilogue regions (reuse/overlay the mainloop stage area)
#define EPI_A_STRIDE 2096                /* 1024 k * 2B + 48 pad (swizzle-free) */
#define EPI_A_HI  0
#define EPI_A_LO  33536                  /* 16 * 2096 */
#define EPI_W     67072
#define EPI_W_STRIDE 144                 /* 64 k * 2B + 16 pad */
#define EPI_W_HALF 18432                 /* 128 * 144 */
#define FUSED_SMEM 103936                /* 67072 + 2*18432 */

// ---------------- Fused kernel: inter tile (128bc x 128de) then x W --------
// grid (96, 96): CTA owns 4 b x 4 d = 16 (b,d) pairs with FULL (c,e) domain.
__global__ __launch_bounds__(256, 2) void fused_gemm()
{
    extern __shared__ __align__(128) char smem[];
    uint32_t sb = smem_u32(smem);
    int tid = threadIdx.x, lane = tid & 31, wid = tid >> 5;
    int i0 = blockIdx.y * 128;     // bc (M)
    int j0 = blockIdx.x * 128;     // de (N)
    int m_base = (wid & 1) * 64, n_base = (wid >> 1) * 32;

    const __nv_bfloat16* base[4] = {
        g_Lhi + (size_t)i0 * N_SEQ, g_Llo + (size_t)i0 * N_SEQ,
        g_Rhi + (size_t)j0 * N_SEQ, g_Rlo + (size_t)j0 * N_SEQ };

    int crow[2], ccol[2];
    uint32_t soff[2]; int goff[2];
    #pragma unroll
    for (int i = 0; i < 2; i++) {
        int ch = tid + (i << 8);
        crow[i] = ch >> 2; ccol[i] = ch & 3;
        soff[i] = (uint32_t)(crow[i] * 80 + ccol[i] * 16);
        goff[i] = crow[i] * N_SEQ + ccol[i] * 8;
    }

    uint32_t arow[4], brow[2];
    #pragma unroll
    for (int mt = 0; mt < 4; mt++)
        arow[mt] = (uint32_t)((m_base + mt * 16 + (lane & 15)) * 80 + (lane >> 4) * 16);
    #pragma unroll
    for (int n2 = 0; n2 < 2; n2++)
        brow[n2] = (uint32_t)((n_base + n2 * 16 + (lane & 15)) * 80 + (lane >> 4) * 16);

    float acc[4][4][4];
    #pragma unroll
    for (int a = 0; a < 4; a++)
        #pragma unroll
        for (int b = 0; b < 4; b++)
            #pragma unroll
            for (int c = 0; c < 4; c++) acc[a][b][c] = 0.f;

    // ---- mainloop: inter tile = L^T R ------------------------------------
    #pragma unroll
    for (int t = 0; t < 4; t++)
        #pragma unroll
        for (int i = 0; i < 2; i++)
            CP_ASYNC16(sb + t * TILE_B + soff[i], base[t] + goff[i]);
    CP_COMMIT();

    for (int kt = 0; kt < 16; kt++) {
        if (kt < 15) {
            uint32_t so = (uint32_t)((kt + 1) & 1) * STAGE_B;
            int go = (kt + 1) * 32;
            #pragma unroll
            for (int t = 0; t < 4; t++)
                #pragma unroll
                for (int i = 0; i < 2; i++)
                    CP_ASYNC16(sb + so + t * TILE_B + soff[i], base[t] + goff[i] + go);
            CP_COMMIT();
            CP_WAIT(1);
        } else {
            CP_WAIT(0);
        }
        __syncthreads();
        uint32_t stb = sb + (uint32_t)(kt & 1) * STAGE_B;
        #pragma unroll
        for (int ks = 0; ks < 2; ks++) {
            uint32_t ko = ks * 32;
            uint32_t bh0[4], bh1[4], bl0[4], bl1[4];
            LDSM_X4(bh0, stb + 2 * TILE_B + brow[0] + ko);
            LDSM_X4(bh1, stb + 2 * TILE_B + brow[1] + ko);
            LDSM_X4(bl0, stb + 3 * TILE_B + brow[0] + ko);
            LDSM_X4(bl1, stb + 3 * TILE_B + brow[1] + ko);
            #pragma unroll
            for (int mt = 0; mt < 4; mt++) {
                uint32_t ah[4], al[4];
                LDSM_X4(ah, stb + arow[mt] + ko);
                LDSM_X4(al, stb + TILE_B + arow[mt] + ko);
                MMA_BF16(acc[mt][0], ah, bh0[0], bh0[2]);
                MMA_BF16(acc[mt][0], ah, bl0[0], bl0[2]);
                MMA_BF16(acc[mt][0], al, bh0[0], bh0[2]);
                MMA_BF16(acc[mt][1], ah, bh0[1], bh0[3]);
                MMA_BF16(acc[mt][1], ah, bl0[1], bl0[3]);
                MMA_BF16(acc[mt][1], al, bh0[1], bh0[3]);
                MMA_BF16(acc[mt][2], ah, bh1[0], bh1[2]);
                MMA_BF16(acc[mt][2], ah, bl1[0], bl1[2]);
                MMA_BF16(acc[mt][2], al, bh1[0], bh1[2]);
                MMA_BF16(acc[mt][3], ah, bh1[1], bh1[3]);
                MMA_BF16(acc[mt][3], ah, bl1[1], bl1[3]);
                MMA_BF16(acc[mt][3], al, bh1[1], bh1[3]);
            }
        }
        __syncthreads();
    }

    // ---- stage inter tile into smem as split-bf16 A_epi [16 p][1024 k] ----
    int g = lane >> 2, tg = lane & 3;
    #pragma unroll
    for (int mt = 0; mt < 4; mt++) {
        #pragma unroll
        for (int h = 0; h < 2; h++) {
            int r = m_base + mt * 16 + g + h * 8;     // tile row: b_local, c
            int bl = r >> 5, c = r & 31;
            #pragma unroll
            for (int nt = 0; nt < 4; nt++) {
                int q = n_base + nt * 8 + tg * 2;     // tile col: d_local, e
                int dl = q >> 5, e = q & 31;
                int p = bl * 4 + dl;
                uint32_t off = (uint32_t)(p * EPI_A_STRIDE + (c * 32 + e) * 2);
                float x = acc[mt][nt][h * 2 + 0], y = acc[mt][nt][h * 2 + 1];
                __nv_bfloat16 hx = __float2bfloat16(x), hy = __float2bfloat16(y);
                __nv_bfloat16 lx = __float2bfloat16(x - __bfloat162float(hx));
                __nv_bfloat16 ly = __float2bfloat16(y - __bfloat162float(hy));
                *(__nv_bfloat162*)(smem + EPI_A_HI + off) = __nv_bfloat162(hx, hy);
                *(__nv_bfloat162*)(smem + EPI_A_LO + off) = __nv_bfloat162(lx, ly);
            }
        }
    }
    __syncthreads();

    // ---- epilogue GEMM: out[16 p][128 f] = A_epi @ Wt^T ------------------
    float accE[2][4];
    #pragma unroll
    for (int o = 0; o < 2; o++)
        #pragma unroll
        for (int c = 0; c < 4; c++) accE[o][c] = 0.f;

    int f_base = wid * 16;
    uint32_t aHi = sb + EPI_A_HI + (uint32_t)((lane & 15) * EPI_A_STRIDE + (lane >> 4) * 16);
    uint32_t aLo = sb + EPI_A_LO + (uint32_t)((lane & 15) * EPI_A_STRIDE + (lane >> 4) * 16);
    uint32_t wRow = sb + EPI_W + (uint32_t)((f_base + (lane & 15)) * EPI_W_STRIDE + (lane >> 4) * 16);

    int r2 = tid >> 1;                 // W-load: 128 rows, 2 thr/row
    int cq = (tid & 1) * 64;           // 64B per half-row per thread
    uint32_t swW = sb + EPI_W + (uint32_t)(r2 * EPI_W_STRIDE + cq);

    for (int kc = 0; kc < 16; kc++) {
        const char* gh = (const char*)(g_Wt_hi + (size_t)r2 * KCE + kc * 64) + cq;
        const char* gl = (const char*)(g_Wt_lo + (size_t)r2 * KCE + kc * 64) + cq;
        #pragma unroll
        for (int u = 0; u < 4; u++) {
            CP_ASYNC16(swW + u * 16, gh + u * 16);
            CP_ASYNC16(swW + EPI_W_HALF + u * 16, gl + u * 16);
        }
        CP_COMMIT();
        CP_WAIT(0);
        __syncthreads();
        #pragma unroll
        for (int ks = 0; ks < 4; ks++) {
            uint32_t ko = (uint32_t)(kc * 128 + ks * 32);   // A byte offset
            uint32_t wo = (uint32_t)(ks * 32);              // W byte offset
            uint32_t ah[4], al[4], bh[4], bl2[4];
            LDSM_X4(ah, aHi + ko);
            LDSM_X4(al, aLo + ko);
            LDSM_X4(bh, wRow + wo);
            LDSM_X4(bl2, wRow + EPI_W_HALF + wo);
            MMA_BF16(accE[0], ah, bh[0], bh[2]);
            MMA_BF16(accE[0], ah, bl2[0], bl2[2]);
            MMA_BF16(accE[0], al, bh[0], bh[2]);
            MMA_BF16(accE[1], ah, bh[1], bh[3]);
            MMA_BF16(accE[1], ah, bl2[1], bl2[3]);
            MMA_BF16(accE[1], al, bh[1], bh[3]);
        }
        __syncthreads();
    }

    // ---- final store: (accE + ob) * ninv ---------------------------------
    // handled via pointer args passed through globals? -> passed as params below
}

// final store needs ob/out; wrap fused_gemm with parameters instead:
__global__ __launch_bounds__(256, 2) void fused_gemm_full(
    const float* __restrict__ ob, float* __restrict__ out)
{
    extern __shared__ __align__(128) char smem[];
    uint32_t sb = smem_u32(smem);
    int tid = threadIdx.x, lane = tid & 31, wid = tid >> 5;
    int i0 = blockIdx.y * 128;
    int j0 = blockIdx.x * 128;
    int m_base = (wid & 1) * 64, n_base = (wid >> 1) * 32;

    const __nv_bfloat16* base[4] = {
        g_Lhi + (size_t)i0 * N_SEQ, g_Llo + (size_t)i0 * N_SEQ,
        g_Rhi + (size_t)j0 * N_SEQ, g_Rlo + (size_t)j0 * N_SEQ };

    int crow[2], ccol[2];
    uint32_t soff[2]; int goff[2];
    #pragma unroll
    for (int i = 0; i < 2; i++) {
        int ch = tid + (i << 8);
        crow[i] = ch >> 2; ccol[i] = ch & 3;
        soff[i] = (uint32_t)(crow[i] * 80 + ccol[i] * 16);
        goff[i] = crow[i] * N_SEQ + ccol[i] * 8;
    }

    uint32_t arow[4], brow[2];
    #pragma unroll
    for (int mt = 0; mt < 4; mt++)
        arow[mt] = (uint32_t)((m_base + mt * 16 + (lane & 15)) * 80 + (lane >> 4) * 16);
    #pragma unroll
    for (int n2 = 0; n2 < 2; n2++)
        brow[n2] = (uint32_t)((n_base + n2 * 16 + (lane & 15)) * 80 + (lane >> 4) * 16);

    float acc[4][4][4];
    #pragma unroll
    for (int a = 0; a < 4; a++)
        #pragma unroll
        for (int b = 0; b < 4; b++)
            #pragma unroll
            for (int c = 0; c < 4; c++) acc[a][b][c] = 0.f;

    #pragma unroll
    for (int t = 0; t < 4; t++)
        #pragma unroll
        for (int i = 0; i < 2; i++)
            CP_ASYNC16(sb + t * TILE_B + soff[i], base[t] + goff[i]);
    CP_COMMIT();

    for (int kt = 0; kt < 16; kt++) {
        if (kt < 15) {
            uint32_t so = (uint32_t)((kt + 1) & 1) * STAGE_B;
            int go = (kt + 1) * 32;
            #pragma unroll
            for (int t = 0; t < 4; t++)
                #pragma unroll
                for (int i = 0; i < 2; i++)
                    CP_ASYNC16(sb + so + t * TILE_B + soff[i], base[t] + goff[i] + go);
            CP_COMMIT();
            CP_WAIT(1);
        } else {
            CP_WAIT(0);
        }
        __syncthreads();
        uint32_t stb = sb + (uint32_t)(kt & 1) * STAGE_B;
        #pragma unroll
        for (int ks = 0; ks < 2; ks++) {
            uint32_t ko = ks * 32;
            uint32_t bh0[4], bh1[4], bl0[4], bl1[4];
            LDSM_X4(bh0, stb + 2 * TILE_B + brow[0] + ko);
            LDSM_X4(bh1, stb + 2 * TILE_B + brow[1] + ko);
            LDSM_X4(bl0, stb + 3 * TILE_B + brow[0] + ko);
            LDSM_X4(bl1, stb + 3 * TILE_B + brow[1] + ko);
            #pragma unroll
            for (int mt = 0; mt < 4; mt++) {
                uint32_t ah[4], al[4];
                LDSM_X4(ah, stb + arow[mt] + ko);
                LDSM_X4(al, stb + TILE_B + arow[mt] + ko);
                MMA_BF16(acc[mt][0], ah, bh0[0], bh0[2]);
                MMA_BF16(acc[mt][0], ah, bl0[0], bl0[2]);
                MMA_BF16(acc[mt][0], al, bh0[0], bh0[2]);
                MMA_BF16(acc[mt][1], ah, bh0[1], bh0[3]);
                MMA_BF16(acc[mt][1], ah, bl0[1], bl0[3]);
                MMA_BF16(acc[mt][1], al, bh0[1], bh0[3]);
                MMA_BF16(acc[mt][2], ah, bh1[0], bh1[2]);
                MMA_BF16(acc[mt][2], ah, bl1[0], bl1[2]);
                MMA_BF16(acc[mt][2], al, bh1[0], bh1[2]);
                MMA_BF16(acc[mt][3], ah, bh1[1], bh1[3]);
                MMA_BF16(acc[mt][3], ah, bl1[1], bl1[3]);
                MMA_BF16(acc[mt][3], al, bh1[1], bh1[3]);
            }
        }
        __syncthreads();
    }

    // stage inter tile to smem as split-bf16 A_epi [16 pairs][1024 k]
    int g = lane >> 2, tg = lane & 3;
    #pragma unroll
    for (int mt = 0; mt < 4; mt++) {
        #pragma unroll
        for (int h = 0; h < 2; h++) {
            int r = m_base + mt * 16 + g + h * 8;
            int bl = r >> 5, c = r & 31;
            #pragma unroll
            for (int nt = 0; nt < 4; nt++) {
                int q = n_base + nt * 8 + tg * 2;
                int dl = q >> 5, e = q & 31;
                int p = bl * 4 + dl;
                uint32_t off = (uint32_t)(p * EPI_A_STRIDE + (c * 32 + e) * 2);
                float x = acc[mt][nt][h * 2 + 0], y = acc[mt][nt][h * 2 + 1];
                __nv_bfloat16 hx = __float2bfloat16(x), hy = __float2bfloat16(y);
                __nv_bfloat16 lx = __float2bfloat16(x - __bfloat162float(hx));
                __nv_bfloat16 ly = __float2bfloat16(y - __bfloat162float(hy));
                *(__nv_bfloat162*)(smem + EPI_A_HI + off) = __nv_bfloat162(hx, hy);
                *(__nv_bfloat162*)(smem + EPI_A_LO + off) = __nv_bfloat162(lx, ly);
            }
        }
    }
    __syncthreads();

    // epilogue GEMM: [16 p x 1024] @ [1024 x 128 f]
    float accE[2][4];
    #pragma unroll
    for (int o = 0; o < 2; o++)
        #pragma unroll
        for (int c = 0; c < 4; c++) accE[o][c] = 0.f;

    int f_base = wid * 16;
    uint32_t aHi = sb + EPI_A_HI + (uint32_t)((lane & 15) * EPI_A_STRIDE + (lane >> 4) * 16);
    uint32_t aLo = sb + EPI_A_LO + (uint32_t)((lane & 15) * EPI_A_STRIDE + (lane >> 4) * 16);
    uint32_t wRow = sb + EPI_W + (uint32_t)((f_base + (lane & 15)) * EPI_W_STRIDE + (lane >> 4) * 16);

    int r2 = tid >> 1;
    int cq = (tid & 1) * 64;
    uint32_t swW = sb + EPI_W + (uint32_t)(r2 * EPI_W_STRIDE + cq);

    for (int kc = 0; kc < 16; kc++) {
        const char* gh = (const char*)(g_Wt_hi + (size_t)r2 * KCE + kc * 64) + cq;
        const char* gl = (const char*)(g_Wt_lo + (size_t)r2 * KCE + kc * 64) + cq;
        #pragma unroll
        for (int u = 0; u < 4; u++) {
            CP_ASYNC16(swW + u * 16, gh + u * 16);
            CP_ASYNC16(swW + EPI_W_HALF + u * 16, gl + u * 16);
        }
        CP_COMMIT();
        CP_WAIT(0);
        __syncthreads();
        #pragma unroll
        for (int ks = 0; ks < 4; ks++) {
            uint32_t ko = (uint32_t)(kc * 128 + ks * 32);
            uint32_t wo = (uint32_t)(ks * 32);
            uint32_t ah[4], al[4], bh[4], bl2[4];
            LDSM_X4(ah, aHi + ko);
            LDSM_X4(al, aLo + ko);
            LDSM_X4(bh, wRow + wo);
            LDSM_X4(bl2, wRow + EPI_W_HALF + wo);
            MMA_BF16(accE[0], ah, bh[0], bh[2]);
            MMA_BF16(accE[0], ah, bl2[0], bl2[2]);
            MMA_BF16(accE[0], al, bh[0], bh[2]);
            MMA_BF16(accE[1], ah, bh[1], bh[3]);
            MMA_BF16(accE[1], ah, bl2[1], bl2[3]);
            MMA_BF16(accE[1], al, bh[1], bh[3]);
        }
        __syncthreads();
    }

    // final store
    int b0 = blockIdx.y * 4, d0 = blockIdx.x * 4;
    #pragma unroll
    for (int h = 0; h < 2; h++) {
        int p = (lane >> 2) + h * 8;
        int mg = (b0 + (p >> 2)) * N_RES + d0 + (p & 3);
        float inv = g_ninv[mg];
        #pragma unroll
        for (int o = 0; o < 2; o++) {
            int f = f_base + o * 8 + (lane & 3) * 2;
            float2 v;
            v.x = (accE[o][h * 2 + 0] + ob[f + 0]) * inv;
            v.y = (accE[o][h * 2 + 1] + ob[f + 1]) * inv;
            *(float2*)&out[(size_t)mg * C_Z + f] = v;
        }
    }
}

// ---------------------------------------------------------------------------
extern "C" void kernel_launch(void* const* d_in, const int* in_sizes, int n_in,
                              void* d_out, int out_size)
{
    const float* act       = (const float*)d_in[0];
    const float* mask      = (const float*)d_in[1];
    const float* ln_scale  = (const float*)d_in[2];
    const float* ln_offset = (const float*)d_in[3];
    const float* left_w    = (const float*)d_in[4];
    const float* left_b    = (const float*)d_in[5];
    const float* right_w   = (const float*)d_in[6];
    const float* right_b   = (const float*)d_in[7];
    const float* output_w  = (const float*)d_in[8];
    const float* output_b  = (const float*)d_in[9];
    float* out = (float*)d_out;

    cudaFuncSetAttribute(fused_gemm_full,
                         cudaFuncAttributeMaxDynamicSharedMemorySize, FUSED_SMEM);

    // order: prep(1), ln_proj(2), split_tr(3), fused(4 = profiler slot)
    prep_kernel<<<576 + 128, 256>>>(mask, output_w);
    ln_proj_kernel<<<N_SEQ * N_RES, 256>>>(act, mask, ln_scale, ln_offset,
                                           left_w, left_b, right_w, right_b);
    split_tr_kernel<<<dim3(BC / 64, N_SEQ / 32, 2), 256>>>();
    fused_gemm_full<<<dim3(N_RES / 4, N_RES / 4), 256, FUSED_SMEM>>>(output_b, out);
}

// round 6
// speedup vs baseline: 1.1376x; 1.1376x over previous
#include <cuda_runtime.h>
#include <cuda_bf16.h>
#include <math.h>
#include <stdint.h>

#define N_SEQ 512
#define N_RES 384
#define C_M   256
#define C_OUT 32
#define C_Z   128
#define BC    (N_RES * C_OUT)     /* 12288  (b,c) flattened */
#define NPAIR (N_RES * N_RES)     /* 147456 (b,d) pairs     */
#define KCE   (C_OUT * C_OUT)     /* 1024   (c,e) flattened */

// ---------------- scratch (device globals; no allocation allowed) ----------
__device__ float g_L[(size_t)N_SEQ * BC];            // fp32 [a, bc]
__device__ float g_R[(size_t)N_SEQ * BC];            // fp32 [a, de]
__device__ float g_ninv[NPAIR];
// split-bf16 K-major operands: [bc|de][a]
__device__ __align__(128) __nv_bfloat16 g_Lhi[(size_t)BC * N_SEQ];
__device__ __align__(128) __nv_bfloat16 g_Llo[(size_t)BC * N_SEQ];
__device__ __align__(128) __nv_bfloat16 g_Rhi[(size_t)BC * N_SEQ];
__device__ __align__(128) __nv_bfloat16 g_Rlo[(size_t)BC * N_SEQ];
// inter, PERMUTED [(b,d),(c,e)], pre-split bf16
__device__ __align__(128) __nv_bfloat16 g_iPhi[(size_t)NPAIR * KCE];  // 302 MB
__device__ __align__(128) __nv_bfloat16 g_iPlo[(size_t)NPAIR * KCE];  // 302 MB
// W transposed + split: [f][ce]
__device__ __align__(128) __nv_bfloat16 g_Wt_hi[(size_t)C_Z * KCE];
__device__ __align__(128) __nv_bfloat16 g_Wt_lo[(size_t)C_Z * KCE];

// ======================= PTX helpers (baseline sm_80 features) =============
__device__ __forceinline__ uint32_t smem_u32(const void* p) {
    uint32_t a;
    asm("{ .reg .u64 t; cvta.to.shared.u64 t, %1; cvt.u32.u64 %0, t; }"
        : "=r"(a) : "l"(p));
    return a;
}
#define LDSM_X4(r, addr) \
    asm volatile("ldmatrix.sync.aligned.m8n8.x4.shared.b16 {%0,%1,%2,%3}, [%4];" \
                 : "=r"((r)[0]), "=r"((r)[1]), "=r"((r)[2]), "=r"((r)[3]) \
                 : "r"(addr))
#define MMA_BF16(d, a, b0, b1) \
    asm volatile("mma.sync.aligned.m16n8k16.row.col.f32.bf16.bf16.f32 " \
                 "{%0,%1,%2,%3},{%4,%5,%6,%7},{%8,%9},{%0,%1,%2,%3};" \
                 : "+f"((d)[0]), "+f"((d)[1]), "+f"((d)[2]), "+f"((d)[3]) \
                 : "r"((a)[0]), "r"((a)[1]), "r"((a)[2]), "r"((a)[3]), \
                   "r"(b0), "r"(b1))
#define CP_ASYNC16(dst, src) \
    asm volatile("cp.async.cg.shared.global [%0], [%1], 16;" \
                 :: "r"(dst), "l"(src) : "memory")
#define CP_COMMIT() asm volatile("cp.async.commit_group;" ::: "memory")
#define CP_WAIT(n)  asm volatile("cp.async.wait_group %0;" :: "n"(n) : "memory")

// ---------------- Kernel 1: LayerNorm + left/right projection + mask -------
__global__ __launch_bounds__(256) void ln_proj_kernel(
    const float* __restrict__ act, const float* __restrict__ mask,
    const float* __restrict__ ln_scale, const float* __restrict__ ln_offset,
    const float* __restrict__ left_w, const float* __restrict__ left_b,
    const float* __restrict__ right_w, const float* __restrict__ right_b)
{
    int row = blockIdx.x;              // row = a*N_RES + b
    int t = threadIdx.x;
    __shared__ float ys[C_M];
    __shared__ float red[16];
    __shared__ float ps[16][64];

    float x = act[(size_t)row * C_M + t];
    float s = x, s2 = x * x;
    #pragma unroll
    for (int o = 16; o > 0; o >>= 1) {
        s  += __shfl_down_sync(0xffffffffu, s, o);
        s2 += __shfl_down_sync(0xffffffffu, s2, o);
    }
    int wid = t >> 5, lane = t & 31;
    if (lane == 0) { red[wid] = s; red[wid + 8] = s2; }
    __syncthreads();
    float sum = 0.f, sumsq = 0.f;
    #pragma unroll
    for (int i = 0; i < 8; i++) { sum += red[i]; sumsq += red[i + 8]; }
    float mu  = sum * (1.0f / C_M);
    float var = sumsq * (1.0f / C_M) - mu * mu;
    float y = (x - mu) * rsqrtf(var + 1e-5f) * ln_scale[t] + ln_offset[t];
    ys[t] = y;
    __syncthreads();

    int og = t & 15;
    int ch = t >> 4;
    const float* Wp = (og < 8) ? (left_w + og * 4) : (right_w + (og - 8) * 4);
    float p0 = 0.f, p1 = 0.f, p2 = 0.f, p3 = 0.f;
    #pragma unroll
    for (int i = 0; i < 16; i++) {
        int k = ch * 16 + i;
        float4 w4 = *(const float4*)(Wp + (size_t)k * C_OUT);
        float yv = ys[k];
        p0 += yv * w4.x; p1 += yv * w4.y; p2 += yv * w4.z; p3 += yv * w4.w;
    }
    ps[ch][og * 4 + 0] = p0; ps[ch][og * 4 + 1] = p1;
    ps[ch][og * 4 + 2] = p2; ps[ch][og * 4 + 3] = p3;
    __syncthreads();

    if (t < 64) {
        float v = 0.f;
        #pragma unroll
        for (int c = 0; c < 16; c++) v += ps[c][t];
        float m = mask[row];
        int a = row / N_RES, b = row % N_RES;
        size_t idx = (size_t)a * BC + (size_t)b * C_OUT;
        if (t < 32) g_L[idx + t]        = m * (v + left_b[t]);
        else        g_R[idx + (t - 32)] = m * (v + right_b[t - 32]);
    }
}

// ------------- Kernel 1b: transpose + split into bf16 hi/lo [bc][a] --------
__global__ __launch_bounds__(256) void split_tr_kernel()
{
    __shared__ float t[32][65];
    const float* src = blockIdx.z ? g_R : g_L;
    __nv_bfloat16* dh = blockIdx.z ? g_Rhi : g_Lhi;
    __nv_bfloat16* dl = blockIdx.z ? g_Rlo : g_Llo;
    int c0 = blockIdx.x * 64;
    int a0 = blockIdx.y * 32;
    for (int i = threadIdx.x; i < 32 * 64; i += 256) {
        int al = i >> 6, cl = i & 63;
        t[al][cl] = src[(size_t)(a0 + al) * BC + c0 + cl];
    }
    __syncthreads();
    for (int i = threadIdx.x; i < 64 * 32; i += 256) {
        int cl = i >> 5, al = i & 31;
        float x = t[al][cl];
        __nv_bfloat16 hi = __float2bfloat16(x);
        __nv_bfloat16 lo = __float2bfloat16(x - __bfloat162float(hi));
        size_t o = (size_t)(c0 + cl) * N_SEQ + a0 + al;
        dh[o] = hi; dl[o] = lo;
    }
}

// ------ Kernel prep: norm reciprocal (blocks 0..575) + W split (576..703) --
__global__ __launch_bounds__(256) void prep_kernel(
    const float* __restrict__ mask, const float* __restrict__ W)
{
    if (blockIdx.x < 576) {
        int m = blockIdx.x * 256 + threadIdx.x;
        int b = m / N_RES, d = m % N_RES;
        float s = 0.f;
        for (int a = 0; a < N_SEQ; a++)
            s += mask[a * N_RES + b] * mask[a * N_RES + d];
        g_ninv[m] = 1.0f / (1e-3f + s);
    } else {
        __shared__ float t[32][33];
        int bb = blockIdx.x - 576;           // 0..127
        int k0 = (bb & 31) * 32;             // ce tile
        int f0 = (bb >> 5) * 32;             // f tile
        for (int i = threadIdx.x; i < 1024; i += 256) {
            int r = i >> 5, c = i & 31;
            t[r][c] = W[(size_t)(k0 + r) * C_Z + f0 + c];
        }
        __syncthreads();
        for (int i = threadIdx.x; i < 1024; i += 256) {
            int r = i >> 5, c = i & 31;
            float x = t[c][r];
            __nv_bfloat16 hi = __float2bfloat16(x);
            __nv_bfloat16 lo = __float2bfloat16(x - __bfloat162float(hi));
            size_t o = (size_t)(f0 + r) * KCE + k0 + c;
            g_Wt_hi[o] = hi; g_Wt_lo[o] = lo;
        }
    }
}

// ============ GEMM smem: 4 tiles x (128 rows x 48B) per stage, 4 stages ====
#define TILE_B  6144                     /* 128 rows * 48B (32B data + 16 pad) */
#define STAGE_B 24576
#define GEMM_SMEM 98304                  /* 4 stages; epilogue reuses this */

// compute one K=16 step on stage base stb (12 LDSM + 48 MMA per warp)
#define GEMM_STEP(stb, arow, brow, acc)                                      \
    do {                                                                     \
        uint32_t bh0[4], bh1[4], bl0[4], bl1[4];                             \
        LDSM_X4(bh0, (stb) + 2 * TILE_B + (brow)[0]);                        \
        LDSM_X4(bh1, (stb) + 2 * TILE_B + (brow)[1]);                        \
        LDSM_X4(bl0, (stb) + 3 * TILE_B + (brow)[0]);                        \
        LDSM_X4(bl1, (stb) + 3 * TILE_B + (brow)[1]);                        \
        _Pragma("unroll")                                                    \
        for (int mt = 0; mt < 4; mt++) {                                     \
            uint32_t ah[4], al[4];                                           \
            LDSM_X4(ah, (stb) + (arow)[mt]);                                 \
            LDSM_X4(al, (stb) + TILE_B + (arow)[mt]);                        \
            MMA_BF16((acc)[mt][0], ah, bh0[0], bh0[2]);                      \
            MMA_BF16((acc)[mt][0], ah, bl0[0], bl0[2]);                      \
            MMA_BF16((acc)[mt][0], al, bh0[0], bh0[2]);                      \
            MMA_BF16((acc)[mt][1], ah, bh0[1], bh0[3]);                      \
            MMA_BF16((acc)[mt][1], ah, bl0[1], bl0[3]);                      \
            MMA_BF16((acc)[mt][1], al, bh0[1], bh0[3]);                      \
            MMA_BF16((acc)[mt][2], ah, bh1[0], bh1[2]);                      \
            MMA_BF16((acc)[mt][2], ah, bl1[0], bl1[2]);                      \
            MMA_BF16((acc)[mt][2], al, bh1[0], bh1[2]);                      \
            MMA_BF16((acc)[mt][3], ah, bh1[1], bh1[3]);                      \
            MMA_BF16((acc)[mt][3], ah, bl1[1], bl1[3]);                      \
            MMA_BF16((acc)[mt][3], al, bh1[1], bh1[3]);                      \
        }                                                                    \
    } while (0)

// ---------------- Kernel 3: GEMM1 = L^T R, 4-stage, coalesced epilogue -----
__global__ __launch_bounds__(256, 2) void gemm1_mma()
{
    extern __shared__ __align__(128) char smem[];
    uint32_t sb = smem_u32(smem);
    int tid = threadIdx.x, lane = tid & 31, wid = tid >> 5;
    int i0 = blockIdx.y * 128;     // bc (M)
    int j0 = blockIdx.x * 128;     // de (N)
    int m_base = (wid & 1) * 64, n_base = (wid >> 1) * 32;

    const __nv_bfloat16* base[4] = {
        g_Lhi + (size_t)i0 * N_SEQ, g_Llo + (size_t)i0 * N_SEQ,
        g_Rhi + (size_t)j0 * N_SEQ, g_Rlo + (size_t)j0 * N_SEQ };

    // cp.async mapping: per thread, one 16B chunk per tile
    int r = tid >> 1, hf = tid & 1;
    uint32_t sdst[4]; const __nv_bfloat16* gsrc[4];
    #pragma unroll
    for (int t = 0; t < 4; t++) {
        sdst[t] = sb + (uint32_t)(t * TILE_B + r * 48 + hf * 16);
        gsrc[t] = base[t] + (size_t)r * N_SEQ + hf * 8;
    }

    uint32_t arow[4], brow[2];
    #pragma unroll
    for (int mt = 0; mt < 4; mt++)
        arow[mt] = (uint32_t)((m_base + mt * 16 + (lane & 15)) * 48 + (lane >> 4) * 16);
    #pragma unroll
    for (int n2 = 0; n2 < 2; n2++)
        brow[n2] = (uint32_t)((n_base + n2 * 16 + (lane & 15)) * 48 + (lane >> 4) * 16);

    float acc[4][4][4];
    #pragma unroll
    for (int a = 0; a < 4; a++)
        #pragma unroll
        for (int b = 0; b < 4; b++)
            #pragma unroll
            for (int c = 0; c < 4; c++) acc[a][b][c] = 0.f;

    // prologue: fill stages 0..2 (K chunks 0..2)
    #pragma unroll
    for (int s = 0; s < 3; s++) {
        #pragma unroll
        for (int t = 0; t < 4; t++)
            CP_ASYNC16(sdst[t] + s * STAGE_B, gsrc[t] + s * 16);
        CP_COMMIT();
    }

    for (int kt = 0; kt < 32; kt++) {
        CP_WAIT(2);
        __syncthreads();
        if (kt + 3 < 32) {
            uint32_t so = (uint32_t)((kt + 3) & 3) * STAGE_B;
            #pragma unroll
            for (int t = 0; t < 4; t++)
                CP_ASYNC16(sdst[t] + so, gsrc[t] + (kt + 3) * 16);
        }
        CP_COMMIT();   // always commit (keeps group accounting uniform)
        uint32_t stb = sb + (uint32_t)(kt & 3) * STAGE_B;
        GEMM_STEP(stb, arow, brow, acc);
    }

    // ---- epilogue: scatter into smem (split-bf16, permuted), then copy ----
    __syncthreads();    // all warps done reading stages before overwrite
    int g = lane >> 2, tg = lane & 3;
    #pragma unroll
    for (int mt = 0; mt < 4; mt++) {
        #pragma unroll
        for (int h = 0; h < 2; h++) {
            int rr = m_base + mt * 16 + g + h * 8;
            int bl = rr >> 5, c = rr & 31;
            #pragma unroll
            for (int nt = 0; nt < 4; nt++) {
                int q = n_base + nt * 8 + tg * 2;
                int dl = q >> 5, e = q & 31;
                int p = bl * 4 + dl;
                uint32_t off = (uint32_t)(p * 2048 + (c * 32 + e) * 2);
                float x = acc[mt][nt][h * 2 + 0], y = acc[mt][nt][h * 2 + 1];
                __nv_bfloat16 hx = __float2bfloat16(x), hy = __float2bfloat16(y);
                __nv_bfloat16 lx = __float2bfloat16(x - __bfloat162float(hx));
                __nv_bfloat16 ly = __float2bfloat16(y - __bfloat162float(hy));
                *(__nv_bfloat162*)(smem + off)         = __nv_bfloat162(hx, hy);
                *(__nv_bfloat162*)(smem + 32768 + off) = __nv_bfloat162(lx, ly);
            }
        }
    }
    __syncthreads();
    // coalesced copy: 16 pairs x 2048B each for hi and lo
    int b0 = blockIdx.y * 4, d0 = blockIdx.x * 4;
    #pragma unroll
    for (int i = 0; i < 8; i++) {
        int qc = tid + 256 * i;              // chunk of 16B, 2048 total
        int p = qc >> 7, off = qc & 127;
        size_t row = (size_t)((b0 + (p >> 2)) * N_RES + d0 + (p & 3)) * KCE + off * 8;
        *(uint4*)(g_iPhi + row) = *(const uint4*)(smem + qc * 16);
        *(uint4*)(g_iPlo + row) = *(const uint4*)(smem + 32768 + qc * 16);
    }
}

// ---------------- Kernel 4: GEMM2 = interP @ Wt^T + b, / norm, 4-stage -----
__global__ __launch_bounds__(256, 2) void gemm2_mma(
    const float* __restrict__ ob, float* __restrict__ out)
{
    extern __shared__ __align__(128) char smem[];
    uint32_t sb = smem_u32(smem);
    int tid = threadIdx.x, lane = tid & 31, wid = tid >> 5;
    int m0 = blockIdx.x * 128;
    int m_base = (wid & 1) * 64, n_base = (wid >> 1) * 32;

    const __nv_bfloat16* base[4] = {
        g_iPhi + (size_t)m0 * KCE, g_iPlo + (size_t)m0 * KCE,
        g_Wt_hi, g_Wt_lo };

    int r = tid >> 1, hf = tid & 1;
    uint32_t sdst[4]; const __nv_bfloat16* gsrc[4];
    #pragma unroll
    for (int t = 0; t < 4; t++) {
        sdst[t] = sb + (uint32_t)(t * TILE_B + r * 48 + hf * 16);
        gsrc[t] = base[t] + (size_t)r * KCE + hf * 8;
    }

    uint32_t arow[4], brow[2];
    #pragma unroll
    for (int mt = 0; mt < 4; mt++)
        arow[mt] = (uint32_t)((m_base + mt * 16 + (lane & 15)) * 48 + (lane >> 4) * 16);
    #pragma unroll
    for (int n2 = 0; n2 < 2; n2++)
        brow[n2] = (uint32_t)((n_base + n2 * 16 + (lane & 15)) * 48 + (lane >> 4) * 16);

    float acc[4][4][4];
    #pragma unroll
    for (int a = 0; a < 4; a++)
        #pragma unroll
        for (int b = 0; b < 4; b++)
            #pragma unroll
            for (int c = 0; c < 4; c++) acc[a][b][c] = 0.f;

    #pragma unroll
    for (int s = 0; s < 3; s++) {
        #pragma unroll
        for (int t = 0; t < 4; t++)
            CP_ASYNC16(sdst[t] + s * STAGE_B, gsrc[t] + s * 16);
        CP_COMMIT();
    }

    for (int kt = 0; kt < 64; kt++) {
        CP_WAIT(2);
        __syncthreads();
        if (kt + 3 < 64) {
            uint32_t so = (uint32_t)((kt + 3) & 3) * STAGE_B;
            #pragma unroll
            for (int t = 0; t < 4; t++)
                CP_ASYNC16(sdst[t] + so, gsrc[t] + (kt + 3) * 16);
        }
        CP_COMMIT();
        uint32_t stb = sb + (uint32_t)(kt & 3) * STAGE_B;
        GEMM_STEP(stb, arow, brow, acc);
    }

    int g = lane >> 2, tg = lane & 3;
    #pragma unroll
    for (int mt = 0; mt < 4; mt++) {
        #pragma unroll
        for (int h = 0; h < 2; h++) {
            int m = m0 + m_base + mt * 16 + g + h * 8;
            float inv = g_ninv[m];
            #pragma unroll
            for (int nt = 0; nt < 4; nt++) {
                int f = n_base + nt * 8 + tg * 2;
                float2 v;
                v.x = (acc[mt][nt][h * 2 + 0] + ob[f + 0]) * inv;
                v.y = (acc[mt][nt][h * 2 + 1] + ob[f + 1]) * inv;
                *(float2*)&out[(size_t)m * C_Z + f] = v;
            }
        }
    }
}

// ---------------------------------------------------------------------------
extern "C" void kernel_launch(void* const* d_in, const int* in_sizes, int n_in,
                              void* d_out, int out_size)
{
    const float* act       = (const float*)d_in[0];
    const float* mask      = (const float*)d_in[1];
    const float* ln_scale  = (const float*)d_in[2];
    const float* ln_offset = (const float*)d_in[3];
    const float* left_w    = (const float*)d_in[4];
    const float* left_b    = (const float*)d_in[5];
    const float* right_w   = (const float*)d_in[6];
    const float* right_b   = (const float*)d_in[7];
    const float* output_w  = (const float*)d_in[8];
    const float* output_b  = (const float*)d_in[9];
    float* out = (float*)d_out;

    cudaFuncSetAttribute(gemm1_mma, cudaFuncAttributeMaxDynamicSharedMemorySize, GEMM_SMEM);
    cudaFuncSetAttribute(gemm2_mma, cudaFuncAttributeMaxDynamicSharedMemorySize, GEMM_SMEM);

    // order: prep(1), ln_proj(2), split_tr(3), gemm1(4 = profiler slot), gemm2(5)
    prep_kernel<<<576 + 128, 256>>>(mask, output_w);
    ln_proj_kernel<<<N_SEQ * N_RES, 256>>>(act, mask, ln_scale, ln_offset,
                                           left_w, left_b, right_w, right_b);
    split_tr_kernel<<<dim3(BC / 64, N_SEQ / 32, 2), 256>>>();
    gemm1_mma<<<dim3(BC / 128, BC / 128), 256, GEMM_SMEM>>>();
    gemm2_mma<<<NPAIR / 128, 256, GEMM_SMEM>>>(output_b, out);
}

// round 7
// speedup vs baseline: 1.1920x; 1.0478x over previous
#include <cuda_runtime.h>
#include <cuda_bf16.h>
#include <math.h>
#include <stdint.h>

#define N_SEQ 512
#define N_RES 384
#define C_M   256
#define C_OUT 32
#define C_Z   128
#define BC    (N_RES * C_OUT)     /* 12288  (b,c) flattened */
#define NPAIR (N_RES * N_RES)     /* 147456 (b,d) pairs     */
#define KCE   (C_OUT * C_OUT)     /* 1024   (c,e) flattened */

// ---------------- scratch (device globals; no allocation allowed) ----------
__device__ float g_L[(size_t)N_SEQ * BC];            // fp32 [a, bc]
__device__ float g_R[(size_t)N_SEQ * BC];            // fp32 [a, de]
__device__ float g_ninv[NPAIR];
// split-bf16 K-major operands: [bc|de][a]
__device__ __align__(128) __nv_bfloat16 g_Lhi[(size_t)BC * N_SEQ];
__device__ __align__(128) __nv_bfloat16 g_Llo[(size_t)BC * N_SEQ];
__device__ __align__(128) __nv_bfloat16 g_Rhi[(size_t)BC * N_SEQ];
__device__ __align__(128) __nv_bfloat16 g_Rlo[(size_t)BC * N_SEQ];
// inter, PERMUTED [(b,d),(c,e)], pre-split bf16
__device__ __align__(128) __nv_bfloat16 g_iPhi[(size_t)NPAIR * KCE];  // 302 MB
__device__ __align__(128) __nv_bfloat16 g_iPlo[(size_t)NPAIR * KCE];  // 302 MB
// W transposed + split: [f][ce]
__device__ __align__(128) __nv_bfloat16 g_Wt_hi[(size_t)C_Z * KCE];
__device__ __align__(128) __nv_bfloat16 g_Wt_lo[(size_t)C_Z * KCE];

// ======================= PTX helpers (baseline sm_80 features) =============
__device__ __forceinline__ uint32_t smem_u32(const void* p) {
    uint32_t a;
    asm("{ .reg .u64 t; cvta.to.shared.u64 t, %1; cvt.u32.u64 %0, t; }"
        : "=r"(a) : "l"(p));
    return a;
}
#define LDSM_X4(r, addr) \
    asm volatile("ldmatrix.sync.aligned.m8n8.x4.shared.b16 {%0,%1,%2,%3}, [%4];" \
                 : "=r"((r)[0]), "=r"((r)[1]), "=r"((r)[2]), "=r"((r)[3]) \
                 : "r"(addr))
#define MMA_BF16(d, a, b0, b1) \
    asm volatile("mma.sync.aligned.m16n8k16.row.col.f32.bf16.bf16.f32 " \
                 "{%0,%1,%2,%3},{%4,%5,%6,%7},{%8,%9},{%0,%1,%2,%3};" \
                 : "+f"((d)[0]), "+f"((d)[1]), "+f"((d)[2]), "+f"((d)[3]) \
                 : "r"((a)[0]), "r"((a)[1]), "r"((a)[2]), "r"((a)[3]), \
                   "r"(b0), "r"(b1))
#define CP_ASYNC16(dst, src) \
    asm volatile("cp.async.cg.shared.global [%0], [%1], 16;" \
                 :: "r"(dst), "l"(src) : "memory")
#define CP_COMMIT() asm volatile("cp.async.commit_group;" ::: "memory")
#define CP_WAIT(n)  asm volatile("cp.async.wait_group %0;" :: "n"(n) : "memory")

// ---------------- Kernel 1: LayerNorm + left/right projection + mask -------
__global__ __launch_bounds__(256) void ln_proj_kernel(
    const float* __restrict__ act, const float* __restrict__ mask,
    const float* __restrict__ ln_scale, const float* __restrict__ ln_offset,
    const float* __restrict__ left_w, const float* __restrict__ left_b,
    const float* __restrict__ right_w, const float* __restrict__ right_b)
{
    int row = blockIdx.x;              // row = a*N_RES + b
    int t = threadIdx.x;
    __shared__ float ys[C_M];
    __shared__ float red[16];
    __shared__ float ps[16][64];

    float x = act[(size_t)row * C_M + t];
    float s = x, s2 = x * x;
    #pragma unroll
    for (int o = 16; o > 0; o >>= 1) {
        s  += __shfl_down_sync(0xffffffffu, s, o);
        s2 += __shfl_down_sync(0xffffffffu, s2, o);
    }
    int wid = t >> 5, lane = t & 31;
    if (lane == 0) { red[wid] = s; red[wid + 8] = s2; }
    __syncthreads();
    float sum = 0.f, sumsq = 0.f;
    #pragma unroll
    for (int i = 0; i < 8; i++) { sum += red[i]; sumsq += red[i + 8]; }
    float mu  = sum * (1.0f / C_M);
    float var = sumsq * (1.0f / C_M) - mu * mu;
    float y = (x - mu) * rsqrtf(var + 1e-5f) * ln_scale[t] + ln_offset[t];
    ys[t] = y;
    __syncthreads();

    int og = t & 15;
    int ch = t >> 4;
    const float* Wp = (og < 8) ? (left_w + og * 4) : (right_w + (og - 8) * 4);
    float p0 = 0.f, p1 = 0.f, p2 = 0.f, p3 = 0.f;
    #pragma unroll
    for (int i = 0; i < 16; i++) {
        int k = ch * 16 + i;
        float4 w4 = *(const float4*)(Wp + (size_t)k * C_OUT);
        float yv = ys[k];
        p0 += yv * w4.x; p1 += yv * w4.y; p2 += yv * w4.z; p3 += yv * w4.w;
    }
    ps[ch][og * 4 + 0] = p0; ps[ch][og * 4 + 1] = p1;
    ps[ch][og * 4 + 2] = p2; ps[ch][og * 4 + 3] = p3;
    __syncthreads();

    if (t < 64) {
        float v = 0.f;
        #pragma unroll
        for (int c = 0; c < 16; c++) v += ps[c][t];
        float m = mask[row];
        int a = row / N_RES, b = row % N_RES;
        size_t idx = (size_t)a * BC + (size_t)b * C_OUT;
        if (t < 32) g_L[idx + t]        = m * (v + left_b[t]);
        else        g_R[idx + (t - 32)] = m * (v + right_b[t - 32]);
    }
}

// ------------- Kernel 1b: transpose + split into bf16 hi/lo [bc][a] --------
__global__ __launch_bounds__(256) void split_tr_kernel()
{
    __shared__ float t[32][65];
    const float* src = blockIdx.z ? g_R : g_L;
    __nv_bfloat16* dh = blockIdx.z ? g_Rhi : g_Lhi;
    __nv_bfloat16* dl = blockIdx.z ? g_Rlo : g_Llo;
    int c0 = blockIdx.x * 64;
    int a0 = blockIdx.y * 32;
    for (int i = threadIdx.x; i < 32 * 64; i += 256) {
        int al = i >> 6, cl = i & 63;
        t[al][cl] = src[(size_t)(a0 + al) * BC + c0 + cl];
    }
    __syncthreads();
    for (int i = threadIdx.x; i < 64 * 32; i += 256) {
        int cl = i >> 5, al = i & 31;
        float x = t[al][cl];
        __nv_bfloat16 hi = __float2bfloat16(x);
        __nv_bfloat16 lo = __float2bfloat16(x - __bfloat162float(hi));
        size_t o = (size_t)(c0 + cl) * N_SEQ + a0 + al;
        dh[o] = hi; dl[o] = lo;
    }
}

// ------ Kernel prep: norm reciprocal (blocks 0..575) + W split (576..703) --
__global__ __launch_bounds__(256) void prep_kernel(
    const float* __restrict__ mask, const float* __restrict__ W)
{
    if (blockIdx.x < 576) {
        int m = blockIdx.x * 256 + threadIdx.x;
        int b = m / N_RES, d = m % N_RES;
        float s = 0.f;
        for (int a = 0; a < N_SEQ; a++)
            s += mask[a * N_RES + b] * mask[a * N_RES + d];
        g_ninv[m] = 1.0f / (1e-3f + s);
    } else {
        __shared__ float t[32][33];
        int bb = blockIdx.x - 576;           // 0..127
        int k0 = (bb & 31) * 32;             // ce tile
        int f0 = (bb >> 5) * 32;             // f tile
        for (int i = threadIdx.x; i < 1024; i += 256) {
            int r = i >> 5, c = i & 31;
            t[r][c] = W[(size_t)(k0 + r) * C_Z + f0 + c];
        }
        __syncthreads();
        for (int i = threadIdx.x; i < 1024; i += 256) {
            int r = i >> 5, c = i & 31;
            float x = t[c][r];
            __nv_bfloat16 hi = __float2bfloat16(x);
            __nv_bfloat16 lo = __float2bfloat16(x - __bfloat162float(hi));
            size_t o = (size_t)(f0 + r) * KCE + k0 + c;
            g_Wt_hi[o] = hi; g_Wt_lo[o] = lo;
        }
    }
}

// ============ GEMM smem: 4 tiles x (128 rows x 80B), 2 stages (KC=32) ======
#define TILE_B  10240                    /* 128 rows * 80B (64B data + 16 pad) */
#define STAGE_B 40960
#define GEMM_SMEM (2 * STAGE_B)          /* 81920; gemm1 epilogue reuses 64KB */

// term-major compute of one KC=32 stage: per k16 half, load ALL fragments,
// then 3 sweeps of 16 independent-accumulator MMAs (no RAW chains).
#define GEMM_STEP_TM(stb, arow, brow, acc)                                   \
    _Pragma("unroll")                                                        \
    for (int ks = 0; ks < 2; ks++) {                                         \
        uint32_t ko = ks * 32;                                               \
        uint32_t ah[4][4], al[4][4], bh[2][4], bl[2][4];                     \
        _Pragma("unroll")                                                    \
        for (int mt = 0; mt < 4; mt++) {                                     \
            LDSM_X4(ah[mt], (stb) + (arow)[mt] + ko);                        \
            LDSM_X4(al[mt], (stb) + TILE_B + (arow)[mt] + ko);               \
        }                                                                    \
        _Pragma("unroll")                                                    \
        for (int n2 = 0; n2 < 2; n2++) {                                     \
            LDSM_X4(bh[n2], (stb) + 2 * TILE_B + (brow)[n2] + ko);           \
            LDSM_X4(bl[n2], (stb) + 3 * TILE_B + (brow)[n2] + ko);           \
        }                                                                    \
        _Pragma("unroll")                                                    \
        for (int mt = 0; mt < 4; mt++)                                       \
            _Pragma("unroll")                                                \
            for (int nt = 0; nt < 4; nt++)                                   \
                MMA_BF16((acc)[mt][nt], ah[mt], bh[nt >> 1][nt & 1],         \
                         bh[nt >> 1][(nt & 1) + 2]);                         \
        _Pragma("unroll")                                                    \
        for (int mt = 0; mt < 4; mt++)                                       \
            _Pragma("unroll")                                                \
            for (int nt = 0; nt < 4; nt++)                                   \
                MMA_BF16((acc)[mt][nt], ah[mt], bl[nt >> 1][nt & 1],         \
                         bl[nt >> 1][(nt & 1) + 2]);                         \
        _Pragma("unroll")                                                    \
        for (int mt = 0; mt < 4; mt++)                                       \
            _Pragma("unroll")                                                \
            for (int nt = 0; nt < 4; nt++)                                   \
                MMA_BF16((acc)[mt][nt], al[mt], bh[nt >> 1][nt & 1],         \
                         bh[nt >> 1][(nt & 1) + 2]);                         \
    }

// ---------------- Kernel 3: GEMM1 = L^T R ----------------------------------
__global__ __launch_bounds__(256, 2) void gemm1_mma()
{
    extern __shared__ __align__(128) char smem[];
    uint32_t sb = smem_u32(smem);
    int tid = threadIdx.x, lane = tid & 31, wid = tid >> 5;
    int i0 = blockIdx.y * 128;     // bc (M)
    int j0 = blockIdx.x * 128;     // de (N)
    int m_base = (wid & 1) * 64, n_base = (wid >> 1) * 32;

    const __nv_bfloat16* base[4] = {
        g_Lhi + (size_t)i0 * N_SEQ, g_Llo + (size_t)i0 * N_SEQ,
        g_Rhi + (size_t)j0 * N_SEQ, g_Rlo + (size_t)j0 * N_SEQ };

    // cp.async: 4 threads per row, 16B each (64B = KC32); 2 rows per thread
    int crow[2], ccol[2];
    uint32_t soff[2]; int goff[2];
    #pragma unroll
    for (int i = 0; i < 2; i++) {
        int ch = tid + (i << 8);
        crow[i] = ch >> 2; ccol[i] = ch & 3;
        soff[i] = (uint32_t)(crow[i] * 80 + ccol[i] * 16);
        goff[i] = crow[i] * N_SEQ + ccol[i] * 8;
    }

    uint32_t arow[4], brow[2];
    #pragma unroll
    for (int mt = 0; mt < 4; mt++)
        arow[mt] = (uint32_t)((m_base + mt * 16 + (lane & 15)) * 80 + (lane >> 4) * 16);
    #pragma unroll
    for (int n2 = 0; n2 < 2; n2++)
        brow[n2] = (uint32_t)((n_base + n2 * 16 + (lane & 15)) * 80 + (lane >> 4) * 16);

    float acc[4][4][4];
    #pragma unroll
    for (int a = 0; a < 4; a++)
        #pragma unroll
        for (int b = 0; b < 4; b++)
            #pragma unroll
            for (int c = 0; c < 4; c++) acc[a][b][c] = 0.f;

    // prologue: stage 0 = K chunk 0
    #pragma unroll
    for (int t = 0; t < 4; t++)
        #pragma unroll
        for (int i = 0; i < 2; i++)
            CP_ASYNC16(sb + t * TILE_B + soff[i], base[t] + goff[i]);
    CP_COMMIT();

    for (int kt = 0; kt < 16; kt++) {
        if (kt < 15) {
            uint32_t so = (uint32_t)((kt + 1) & 1) * STAGE_B;
            int go = (kt + 1) * 32;
            #pragma unroll
            for (int t = 0; t < 4; t++)
                #pragma unroll
                for (int i = 0; i < 2; i++)
                    CP_ASYNC16(sb + so + t * TILE_B + soff[i], base[t] + goff[i] + go);
            CP_COMMIT();
            CP_WAIT(1);
        } else {
            CP_WAIT(0);
        }
        __syncthreads();
        uint32_t stb = sb + (uint32_t)(kt & 1) * STAGE_B;
        GEMM_STEP_TM(stb, arow, brow, acc);
        __syncthreads();
    }

    // ---- epilogue: scatter into smem (split-bf16, permuted), then copy ----
    int g = lane >> 2, tg = lane & 3;
    #pragma unroll
    for (int mt = 0; mt < 4; mt++) {
        #pragma unroll
        for (int h = 0; h < 2; h++) {
            int rr = m_base + mt * 16 + g + h * 8;
            int bl = rr >> 5, c = rr & 31;
            #pragma unroll
            for (int nt = 0; nt < 4; nt++) {
                int q = n_base + nt * 8 + tg * 2;
                int dl = q >> 5, e = q & 31;
                int p = bl * 4 + dl;
                uint32_t off = (uint32_t)(p * 2048 + (c * 32 + e) * 2);
                float x = acc[mt][nt][h * 2 + 0], y = acc[mt][nt][h * 2 + 1];
                __nv_bfloat16 hx = __float2bfloat16(x), hy = __float2bfloat16(y);
                __nv_bfloat16 lx = __float2bfloat16(x - __bfloat162float(hx));
                __nv_bfloat16 ly = __float2bfloat16(y - __bfloat162float(hy));
                *(__nv_bfloat162*)(smem + off)         = __nv_bfloat162(hx, hy);
                *(__nv_bfloat162*)(smem + 32768 + off) = __nv_bfloat162(lx, ly);
            }
        }
    }
    __syncthreads();
    // coalesced copy: 16 pairs x 2048B each for hi and lo
    int b0 = blockIdx.y * 4, d0 = blockIdx.x * 4;
    #pragma unroll
    for (int i = 0; i < 8; i++) {
        int qc = tid + 256 * i;              // 16B chunk id, 2048 total
        int p = qc >> 7, off = qc & 127;
        size_t row = (size_t)((b0 + (p >> 2)) * N_RES + d0 + (p & 3)) * KCE + off * 8;
        *(uint4*)(g_iPhi + row) = *(const uint4*)(smem + qc * 16);
        *(uint4*)(g_iPlo + row) = *(const uint4*)(smem + 32768 + qc * 16);
    }
}

// ---------------- Kernel 4: GEMM2 = interP @ Wt^T + b, / norm --------------
__global__ __launch_bounds__(256, 2) void gemm2_mma(
    const float* __restrict__ ob, float* __restrict__ out)
{
    extern __shared__ __align__(128) char smem[];
    uint32_t sb = smem_u32(smem);
    int tid = threadIdx.x, lane = tid & 31, wid = tid >> 5;
    int m0 = blockIdx.x * 128;
    int m_base = (wid & 1) * 64, n_base = (wid >> 1) * 32;

    const __nv_bfloat16* base[4] = {
        g_iPhi + (size_t)m0 * KCE, g_iPlo + (size_t)m0 * KCE,
        g_Wt_hi, g_Wt_lo };

    int crow[2], ccol[2];
    uint32_t soff[2]; int goff[2];
    #pragma unroll
    for (int i = 0; i < 2; i++) {
        int ch = tid + (i << 8);
        crow[i] = ch >> 2; ccol[i] = ch & 3;
        soff[i] = (uint32_t)(crow[i] * 80 + ccol[i] * 16);
        goff[i] = crow[i] * KCE + ccol[i] * 8;
    }

    uint32_t arow[4], brow[2];
    #pragma unroll
    for (int mt = 0; mt < 4; mt++)
        arow[mt] = (uint32_t)((m_base + mt * 16 + (lane & 15)) * 80 + (lane >> 4) * 16);
    #pragma unroll
    for (int n2 = 0; n2 < 2; n2++)
        brow[n2] = (uint32_t)((n_base + n2 * 16 + (lane & 15)) * 80 + (lane >> 4) * 16);

    float acc[4][4][4];
    #pragma unroll
    for (int a = 0; a < 4; a++)
        #pragma unroll
        for (int b = 0; b < 4; b++)
            #pragma unroll
            for (int c = 0; c < 4; c++) acc[a][b][c] = 0.f;

    #pragma unroll
    for (int t = 0; t < 4; t++)
        #pragma unroll
        for (int i = 0; i < 2; i++)
            CP_ASYNC16(sb + t * TILE_B + soff[i], base[t] + goff[i]);
    CP_COMMIT();

    for (int kt = 0; kt < 32; kt++) {
        if (kt < 31) {
            uint32_t so = (uint32_t)((kt + 1) & 1) * STAGE_B;
            int go = (kt + 1) * 32;
            #pragma unroll
            for (int t = 0; t < 4; t++)
                #pragma unroll
                for (int i = 0; i < 2; i++)
                    CP_ASYNC16(sb + so + t * TILE_B + soff[i], base[t] + goff[i] + go);
            CP_COMMIT();
            CP_WAIT(1);
        } else {
            CP_WAIT(0);
        }
        __syncthreads();
        uint32_t stb = sb + (uint32_t)(kt & 1) * STAGE_B;
        GEMM_STEP_TM(stb, arow, brow, acc);
        __syncthreads();
    }

    int g = lane >> 2, tg = lane & 3;
    #pragma unroll
    for (int mt = 0; mt < 4; mt++) {
        #pragma unroll
        for (int h = 0; h < 2; h++) {
            int m = m0 + m_base + mt * 16 + g + h * 8;
            float inv = g_ninv[m];
            #pragma unroll
            for (int nt = 0; nt < 4; nt++) {
                int f = n_base + nt * 8 + tg * 2;
                float2 v;
                v.x = (acc[mt][nt][h * 2 + 0] + ob[f + 0]) * inv;
                v.y = (acc[mt][nt][h * 2 + 1] + ob[f + 1]) * inv;
                *(float2*)&out[(size_t)m * C_Z + f] = v;
            }
        }
    }
}

// ---------------------------------------------------------------------------
extern "C" void kernel_launch(void* const* d_in, const int* in_sizes, int n_in,
                              void* d_out, int out_size)
{
    const float* act       = (const float*)d_in[0];
    const float* mask      = (const float*)d_in[1];
    const float* ln_scale  = (const float*)d_in[2];
    const float* ln_offset = (const float*)d_in[3];
    const float* left_w    = (const float*)d_in[4];
    const float* left_b    = (const float*)d_in[5];
    const float* right_w   = (const float*)d_in[6];
    const float* right_b   = (const float*)d_in[7];
    const float* output_w  = (const float*)d_in[8];
    const float* output_b  = (const float*)d_in[9];
    float* out = (float*)d_out;

    cudaFuncSetAttribute(gemm1_mma, cudaFuncAttributeMaxDynamicSharedMemorySize, GEMM_SMEM);
    cudaFuncSetAttribute(gemm2_mma, cudaFuncAttributeMaxDynamicSharedMemorySize, GEMM_SMEM);

    // order: prep(1), ln_proj(2), split_tr(3), gemm1(4 = profiler slot), gemm2(5)
    prep_kernel<<<576 + 128, 256>>>(mask, output_w);
    ln_proj_kernel<<<N_SEQ * N_RES, 256>>>(act, mask, ln_scale, ln_offset,
                                           left_w, left_b, right_w, right_b);
    split_tr_kernel<<<dim3(BC / 64, N_SEQ / 32, 2), 256>>>();
    gemm1_mma<<<dim3(BC / 128, BC / 128), 256, GEMM_SMEM>>>();
    gemm2_mma<<<NPAIR / 128, 256, GEMM_SMEM>>>(output_b, out);
}

// round 8
// speedup vs baseline: 1.2767x; 1.0711x over previous
#include <cuda_runtime.h>
#include <cuda_bf16.h>
#include <math.h>
#include <stdint.h>

#define N_SEQ 512
#define N_RES 384
#define C_M   256
#define C_OUT 32
#define C_Z   128
#define BC    (N_RES * C_OUT)     /* 12288  (b,c) flattened */
#define NPAIR (N_RES * N_RES)     /* 147456 (b,d) pairs     */
#define KCE   (C_OUT * C_OUT)     /* 1024   (c,e) flattened */

// ---------------- scratch (device globals; no allocation allowed) ----------
__device__ float g_L[(size_t)N_SEQ * BC];            // fp32 [a, bc]
__device__ float g_R[(size_t)N_SEQ * BC];            // fp32 [a, de]
__device__ float g_ninv[NPAIR];
// split-bf16 K-major operands: [bc|de][a]
__device__ __align__(128) __nv_bfloat16 g_Lhi[(size_t)BC * N_SEQ];
__device__ __align__(128) __nv_bfloat16 g_Llo[(size_t)BC * N_SEQ];
__device__ __align__(128) __nv_bfloat16 g_Rhi[(size_t)BC * N_SEQ];
__device__ __align__(128) __nv_bfloat16 g_Rlo[(size_t)BC * N_SEQ];
// inter, PERMUTED [(b,d),(c,e)], pre-split bf16
__device__ __align__(128) __nv_bfloat16 g_iPhi[(size_t)NPAIR * KCE];  // 302 MB
__device__ __align__(128) __nv_bfloat16 g_iPlo[(size_t)NPAIR * KCE];  // 302 MB
// W transposed + split: [f][ce]
__device__ __align__(128) __nv_bfloat16 g_Wt_hi[(size_t)C_Z * KCE];
__device__ __align__(128) __nv_bfloat16 g_Wt_lo[(size_t)C_Z * KCE];

// ======================= PTX helpers (baseline sm_80 features) =============
__device__ __forceinline__ uint32_t smem_u32(const void* p) {
    uint32_t a;
    asm("{ .reg .u64 t; cvta.to.shared.u64 t, %1; cvt.u32.u64 %0, t; }"
        : "=r"(a) : "l"(p));
    return a;
}
#define LDSM_X4(r, addr) \
    asm volatile("ldmatrix.sync.aligned.m8n8.x4.shared.b16 {%0,%1,%2,%3}, [%4];" \
                 : "=r"((r)[0]), "=r"((r)[1]), "=r"((r)[2]), "=r"((r)[3]) \
                 : "r"(addr))
#define MMA_BF16(d, a, b0, b1) \
    asm volatile("mma.sync.aligned.m16n8k16.row.col.f32.bf16.bf16.f32 " \
                 "{%0,%1,%2,%3},{%4,%5,%6,%7},{%8,%9},{%0,%1,%2,%3};" \
                 : "+f"((d)[0]), "+f"((d)[1]), "+f"((d)[2]), "+f"((d)[3]) \
                 : "r"((a)[0]), "r"((a)[1]), "r"((a)[2]), "r"((a)[3]), \
                   "r"(b0), "r"(b1))
#define CP_ASYNC16(dst, src) \
    asm volatile("cp.async.cg.shared.global [%0], [%1], 16;" \
                 :: "r"(dst), "l"(src) : "memory")
#define CP_COMMIT() asm volatile("cp.async.commit_group;" ::: "memory")
#define CP_WAIT(n)  asm volatile("cp.async.wait_group %0;" :: "n"(n) : "memory")

// XOR swizzle: chunk (m, c) of a [128 rows x 4 chunks-of-16B] tile.
// L = m*4+c -> phys = (L>>3)*128 + ((L&7) ^ ((L>>3)&7))*16.
// Conflict-free for 16-row LDSM phases AND 16B-aligned.
__device__ __forceinline__ uint32_t swz(int m, int c) {
    int L = m * 4 + c;
    return (uint32_t)(((L >> 3) << 7) + ((((L & 7) ^ ((L >> 3) & 7))) << 4));
}

// ---------------- Kernel 1: LayerNorm + left/right projection + mask -------
__global__ __launch_bounds__(256) void ln_proj_kernel(
    const float* __restrict__ act, const float* __restrict__ mask,
    const float* __restrict__ ln_scale, const float* __restrict__ ln_offset,
    const float* __restrict__ left_w, const float* __restrict__ left_b,
    const float* __restrict__ right_w, const float* __restrict__ right_b)
{
    int row = blockIdx.x;              // row = a*N_RES + b
    int t = threadIdx.x;
    __shared__ float ys[C_M];
    __shared__ float red[16];
    __shared__ float ps[16][64];

    float x = act[(size_t)row * C_M + t];
    float s = x, s2 = x * x;
    #pragma unroll
    for (int o = 16; o > 0; o >>= 1) {
        s  += __shfl_down_sync(0xffffffffu, s, o);
        s2 += __shfl_down_sync(0xffffffffu, s2, o);
    }
    int wid = t >> 5, lane = t & 31;
    if (lane == 0) { red[wid] = s; red[wid + 8] = s2; }
    __syncthreads();
    float sum = 0.f, sumsq = 0.f;
    #pragma unroll
    for (int i = 0; i < 8; i++) { sum += red[i]; sumsq += red[i + 8]; }
    float mu  = sum * (1.0f / C_M);
    float var = sumsq * (1.0f / C_M) - mu * mu;
    float y = (x - mu) * rsqrtf(var + 1e-5f) * ln_scale[t] + ln_offset[t];
    ys[t] = y;
    __syncthreads();

    int og = t & 15;
    int ch = t >> 4;
    const float* Wp = (og < 8) ? (left_w + og * 4) : (right_w + (og - 8) * 4);
    float p0 = 0.f, p1 = 0.f, p2 = 0.f, p3 = 0.f;
    #pragma unroll
    for (int i = 0; i < 16; i++) {
        int k = ch * 16 + i;
        float4 w4 = *(const float4*)(Wp + (size_t)k * C_OUT);
        float yv = ys[k];
        p0 += yv * w4.x; p1 += yv * w4.y; p2 += yv * w4.z; p3 += yv * w4.w;
    }
    ps[ch][og * 4 + 0] = p0; ps[ch][og * 4 + 1] = p1;
    ps[ch][og * 4 + 2] = p2; ps[ch][og * 4 + 3] = p3;
    __syncthreads();

    if (t < 64) {
        float v = 0.f;
        #pragma unroll
        for (int c = 0; c < 16; c++) v += ps[c][t];
        float m = mask[row];
        int a = row / N_RES, b = row % N_RES;
        size_t idx = (size_t)a * BC + (size_t)b * C_OUT;
        if (t < 32) g_L[idx + t]        = m * (v + left_b[t]);
        else        g_R[idx + (t - 32)] = m * (v + right_b[t - 32]);
    }
}

// ------------- Kernel 1b: transpose + split into bf16 hi/lo [bc][a] --------
__global__ __launch_bounds__(256) void split_tr_kernel()
{
    __shared__ float t[32][65];
    const float* src = blockIdx.z ? g_R : g_L;
    __nv_bfloat16* dh = blockIdx.z ? g_Rhi : g_Lhi;
    __nv_bfloat16* dl = blockIdx.z ? g_Rlo : g_Llo;
    int c0 = blockIdx.x * 64;
    int a0 = blockIdx.y * 32;
    for (int i = threadIdx.x; i < 32 * 64; i += 256) {
        int al = i >> 6, cl = i & 63;
        t[al][cl] = src[(size_t)(a0 + al) * BC + c0 + cl];
    }
    __syncthreads();
    for (int i = threadIdx.x; i < 64 * 32; i += 256) {
        int cl = i >> 5, al = i & 31;
        float x = t[al][cl];
        __nv_bfloat16 hi = __float2bfloat16(x);
        __nv_bfloat16 lo = __float2bfloat16(x - __bfloat162float(hi));
        size_t o = (size_t)(c0 + cl) * N_SEQ + a0 + al;
        dh[o] = hi; dl[o] = lo;
    }
}

// ------ Kernel prep: norm reciprocal (blocks 0..575) + W split (576..703) --
__global__ __launch_bounds__(256) void prep_kernel(
    const float* __restrict__ mask, const float* __restrict__ W)
{
    if (blockIdx.x < 576) {
        int m = blockIdx.x * 256 + threadIdx.x;
        int b = m / N_RES, d = m % N_RES;
        float s = 0.f;
        for (int a = 0; a < N_SEQ; a++)
            s += mask[a * N_RES + b] * mask[a * N_RES + d];
        g_ninv[m] = 1.0f / (1e-3f + s);
    } else {
        __shared__ float t[32][33];
        int bb = blockIdx.x - 576;           // 0..127
        int k0 = (bb & 31) * 32;             // ce tile
        int f0 = (bb >> 5) * 32;             // f tile
        for (int i = threadIdx.x; i < 1024; i += 256) {
            int r = i >> 5, c = i & 31;
            t[r][c] = W[(size_t)(k0 + r) * C_Z + f0 + c];
        }
        __syncthreads();
        for (int i = threadIdx.x; i < 1024; i += 256) {
            int r = i >> 5, c = i & 31;
            float x = t[c][r];
            __nv_bfloat16 hi = __float2bfloat16(x);
            __nv_bfloat16 lo = __float2bfloat16(x - __bfloat162float(hi));
            size_t o = (size_t)(f0 + r) * KCE + k0 + c;
            g_Wt_hi[o] = hi; g_Wt_lo[o] = lo;
        }
    }
}

// ============ GEMM smem: 4 swizzled tiles x 8KB per stage, 3 stages ========
#define TILE_B  8192                     /* 128 rows x 64B, XOR-swizzled */
#define STAGE_B 32768
#define GEMM_SMEM 98304                  /* 3 stages; gemm1 epilogue reuses */

// term-major compute of one KC=32 stage using precomputed swizzled offsets
#define GEMM_STEP_TM(stb, aoff, boff, acc)                                   \
    _Pragma("unroll")                                                        \
    for (int ks = 0; ks < 2; ks++) {                                         \
        uint32_t ah[4][4], al[4][4], bh[2][4], bl[2][4];                     \
        _Pragma("unroll")                                                    \
        for (int mt = 0; mt < 4; mt++) {                                     \
            LDSM_X4(ah[mt], (stb) + (aoff)[mt][ks]);                         \
            LDSM_X4(al[mt], (stb) + TILE_B + (aoff)[mt][ks]);                \
        }                                                                    \
        _Pragma("unroll")                                                    \
        for (int n2 = 0; n2 < 2; n2++) {                                     \
            LDSM_X4(bh[n2], (stb) + 2 * TILE_B + (boff)[n2][ks]);            \
            LDSM_X4(bl[n2], (stb) + 3 * TILE_B + (boff)[n2][ks]);            \
        }                                                                    \
        _Pragma("unroll")                                                    \
        for (int mt = 0; mt < 4; mt++)                                       \
            _Pragma("unroll")                                                \
            for (int nt = 0; nt < 4; nt++)                                   \
                MMA_BF16((acc)[mt][nt], ah[mt], bh[nt >> 1][nt & 1],         \
                         bh[nt >> 1][(nt & 1) + 2]);                         \
        _Pragma("unroll")                                                    \
        for (int mt = 0; mt < 4; mt++)                                       \
            _Pragma("unroll")                                                \
            for (int nt = 0; nt < 4; nt++)                                   \
                MMA_BF16((acc)[mt][nt], ah[mt], bl[nt >> 1][nt & 1],         \
                         bl[nt >> 1][(nt & 1) + 2]);                         \
        _Pragma("unroll")                                                    \
        for (int mt = 0; mt < 4; mt++)                                       \
            _Pragma("unroll")                                                \
            for (int nt = 0; nt < 4; nt++)                                   \
                MMA_BF16((acc)[mt][nt], al[mt], bh[nt >> 1][nt & 1],         \
                         bh[nt >> 1][(nt & 1) + 2]);                         \
    }

// ---------------- Kernel 3: GEMM1 = L^T R ----------------------------------
__global__ __launch_bounds__(256, 2) void gemm1_mma()
{
    extern __shared__ __align__(128) char smem[];
    uint32_t sb = smem_u32(smem);
    int tid = threadIdx.x, lane = tid & 31, wid = tid >> 5;
    int i0 = blockIdx.y * 128;     // bc (M)
    int j0 = blockIdx.x * 128;     // de (N)
    int m_base = (wid & 1) * 64, n_base = (wid >> 1) * 32;

    const __nv_bfloat16* base[4] = {
        g_Lhi + (size_t)i0 * N_SEQ, g_Llo + (size_t)i0 * N_SEQ,
        g_Rhi + (size_t)j0 * N_SEQ, g_Rlo + (size_t)j0 * N_SEQ };

    // cp.async: chunk ch in [0,512): m = ch>>2, c = ch&3; 2 chunks/thread/tile
    uint32_t soff[2]; int gofs[2];
    #pragma unroll
    for (int i = 0; i < 2; i++) {
        int ch = tid + (i << 8);
        int m = ch >> 2, c = ch & 3;
        soff[i] = swz(m, c);
        gofs[i] = m * N_SEQ + c * 8;
    }

    // swizzled LDSM offsets (per lane, per mt/n2, per k16 half)
    uint32_t aoff[4][2], boff[2][2];
    #pragma unroll
    for (int mt = 0; mt < 4; mt++)
        #pragma unroll
        for (int ks = 0; ks < 2; ks++)
            aoff[mt][ks] = swz(m_base + mt * 16 + (lane & 15), ks * 2 + (lane >> 4));
    #pragma unroll
    for (int n2 = 0; n2 < 2; n2++)
        #pragma unroll
        for (int ks = 0; ks < 2; ks++)
            boff[n2][ks] = swz(n_base + n2 * 16 + (lane & 15), ks * 2 + (lane >> 4));

    float acc[4][4][4];
    #pragma unroll
    for (int a = 0; a < 4; a++)
        #pragma unroll
        for (int b = 0; b < 4; b++)
            #pragma unroll
            for (int c = 0; c < 4; c++) acc[a][b][c] = 0.f;

    // prologue: fill stages 0,1 with K chunks 0,1
    #pragma unroll
    for (int s = 0; s < 2; s++) {
        #pragma unroll
        for (int t = 0; t < 4; t++)
            #pragma unroll
            for (int i = 0; i < 2; i++)
                CP_ASYNC16(sb + s * STAGE_B + t * TILE_B + soff[i],
                           base[t] + gofs[i] + s * 32);
        CP_COMMIT();
    }

    for (int kt = 0; kt < 16; kt++) {
        CP_WAIT(1);
        __syncthreads();
        if (kt + 2 < 16) {
            uint32_t so = (uint32_t)((kt + 2) % 3) * STAGE_B;
            #pragma unroll
            for (int t = 0; t < 4; t++)
                #pragma unroll
                for (int i = 0; i < 2; i++)
                    CP_ASYNC16(sb + so + t * TILE_B + soff[i],
                               base[t] + gofs[i] + (kt + 2) * 32);
        }
        CP_COMMIT();
        uint32_t stb = sb + (uint32_t)(kt % 3) * STAGE_B;
        GEMM_STEP_TM(stb, aoff, boff, acc);
    }

    // ---- epilogue: scatter into smem (split-bf16, permuted), then copy ----
    __syncthreads();
    int g = lane >> 2, tg = lane & 3;
    #pragma unroll
    for (int mt = 0; mt < 4; mt++) {
        #pragma unroll
        for (int h = 0; h < 2; h++) {
            int rr = m_base + mt * 16 + g + h * 8;
            int bl = rr >> 5, c = rr & 31;
            #pragma unroll
            for (int nt = 0; nt < 4; nt++) {
                int q = n_base + nt * 8 + tg * 2;
                int dl = q >> 5, e = q & 31;
                int p = bl * 4 + dl;
                uint32_t off = (uint32_t)(p * 2048 + (c * 32 + e) * 2);
                float x = acc[mt][nt][h * 2 + 0], y = acc[mt][nt][h * 2 + 1];
                __nv_bfloat16 hx = __float2bfloat16(x), hy = __float2bfloat16(y);
                __nv_bfloat16 lx = __float2bfloat16(x - __bfloat162float(hx));
                __nv_bfloat16 ly = __float2bfloat16(y - __bfloat162float(hy));
                *(__nv_bfloat162*)(smem + off)         = __nv_bfloat162(hx, hy);
                *(__nv_bfloat162*)(smem + 32768 + off) = __nv_bfloat162(lx, ly);
            }
        }
    }
    __syncthreads();
    int b0 = blockIdx.y * 4, d0 = blockIdx.x * 4;
    #pragma unroll
    for (int i = 0; i < 8; i++) {
        int qc = tid + 256 * i;              // 16B chunk id, 2048 total
        int p = qc >> 7, off = qc & 127;
        size_t row = (size_t)((b0 + (p >> 2)) * N_RES + d0 + (p & 3)) * KCE + off * 8;
        *(uint4*)(g_iPhi + row) = *(const uint4*)(smem + qc * 16);
        *(uint4*)(g_iPlo + row) = *(const uint4*)(smem + 32768 + qc * 16);
    }
}

// ---------------- Kernel 4: GEMM2 = interP @ Wt^T + b, / norm --------------
__global__ __launch_bounds__(256, 2) void gemm2_mma(
    const float* __restrict__ ob, float* __restrict__ out)
{
    extern __shared__ __align__(128) char smem[];
    uint32_t sb = smem_u32(smem);
    int tid = threadIdx.x, lane = tid & 31, wid = tid >> 5;
    int m0 = blockIdx.x * 128;
    int m_base = (wid & 1) * 64, n_base = (wid >> 1) * 32;

    const __nv_bfloat16* base[4] = {
        g_iPhi + (size_t)m0 * KCE, g_iPlo + (size_t)m0 * KCE,
        g_Wt_hi, g_Wt_lo };

    uint32_t soff[2]; int gofs[2];
    #pragma unroll
    for (int i = 0; i < 2; i++) {
        int ch = tid + (i << 8);
        int m = ch >> 2, c = ch & 3;
        soff[i] = swz(m, c);
        gofs[i] = m * KCE + c * 8;
    }

    uint32_t aoff[4][2], boff[2][2];
    #pragma unroll
    for (int mt = 0; mt < 4; mt++)
        #pragma unroll
        for (int ks = 0; ks < 2; ks++)
            aoff[mt][ks] = swz(m_base + mt * 16 + (lane & 15), ks * 2 + (lane >> 4));
    #pragma unroll
    for (int n2 = 0; n2 < 2; n2++)
        #pragma unroll
        for (int ks = 0; ks < 2; ks++)
            boff[n2][ks] = swz(n_base + n2 * 16 + (lane & 15), ks * 2 + (lane >> 4));

    float acc[4][4][4];
    #pragma unroll
    for (int a = 0; a < 4; a++)
        #pragma unroll
        for (int b = 0; b < 4; b++)
            #pragma unroll
            for (int c = 0; c < 4; c++) acc[a][b][c] = 0.f;

    #pragma unroll
    for (int s = 0; s < 2; s++) {
        #pragma unroll
        for (int t = 0; t < 4; t++)
            #pragma unroll
            for (int i = 0; i < 2; i++)
                CP_ASYNC16(sb + s * STAGE_B + t * TILE_B + soff[i],
                           base[t] + gofs[i] + s * 32);
        CP_COMMIT();
    }

    for (int kt = 0; kt < 32; kt++) {
        CP_WAIT(1);
        __syncthreads();
        if (kt + 2 < 32) {
            uint32_t so = (uint32_t)((kt + 2) % 3) * STAGE_B;
            #pragma unroll
            for (int t = 0; t < 4; t++)
                #pragma unroll
                for (int i = 0; i < 2; i++)
                    CP_ASYNC16(sb + so + t * TILE_B + soff[i],
                               base[t] + gofs[i] + (kt + 2) * 32);
        }
        CP_COMMIT();
        uint32_t stb = sb + (uint32_t)(kt % 3) * STAGE_B;
        GEMM_STEP_TM(stb, aoff, boff, acc);
    }

    int g = lane >> 2, tg = lane & 3;
    #pragma unroll
    for (int mt = 0; mt < 4; mt++) {
        #pragma unroll
        for (int h = 0; h < 2; h++) {
            int m = m0 + m_base + mt * 16 + g + h * 8;
            float inv = g_ninv[m];
            #pragma unroll
            for (int nt = 0; nt < 4; nt++) {
                int f = n_base + nt * 8 + tg * 2;
                float2 v;
                v.x = (acc[mt][nt][h * 2 + 0] + ob[f + 0]) * inv;
                v.y = (acc[mt][nt][h * 2 + 1] + ob[f + 1]) * inv;
                *(float2*)&out[(size_t)m * C_Z + f] = v;
            }
        }
    }
}

// ---------------------------------------------------------------------------
extern "C" void kernel_launch(void* const* d_in, const int* in_sizes, int n_in,
                              void* d_out, int out_size)
{
    const float* act       = (const float*)d_in[0];
    const float* mask      = (const float*)d_in[1];
    const float* ln_scale  = (const float*)d_in[2];
    const float* ln_offset = (const float*)d_in[3];
    const float* left_w    = (const float*)d_in[4];
    const float* left_b    = (const float*)d_in[5];
    const float* right_w   = (const float*)d_in[6];
    const float* right_b   = (const float*)d_in[7];
    const float* output_w  = (const float*)d_in[8];
    const float* output_b  = (const float*)d_in[9];
    float* out = (float*)d_out;

    cudaFuncSetAttribute(gemm1_mma, cudaFuncAttributeMaxDynamicSharedMemorySize, GEMM_SMEM);
    cudaFuncSetAttribute(gemm2_mma, cudaFuncAttributeMaxDynamicSharedMemorySize, GEMM_SMEM);

    // order: prep(1), ln_proj(2), split_tr(3), gemm1(4 = profiler slot), gemm2(5)
    prep_kernel<<<576 + 128, 256>>>(mask, output_w);
    ln_proj_kernel<<<N_SEQ * N_RES, 256>>>(act, mask, ln_scale, ln_offset,
                                           left_w, left_b, right_w, right_b);
    split_tr_kernel<<<dim3(BC / 64, N_SEQ / 32, 2), 256>>>();
    gemm1_mma<<<dim3(BC / 128, BC / 128), 256, GEMM_SMEM>>>();
    gemm2_mma<<<NPAIR / 128, 256, GEMM_SMEM>>>(output_b, out);
}

// round 9
// speedup vs baseline: 1.5188x; 1.1896x over previous
#include <cuda_runtime.h>
#include <cuda_fp16.h>
#include <math.h>
#include <stdint.h>

#define N_SEQ 512
#define N_RES 384
#define C_M   256
#define C_OUT 32
#define C_Z   128
#define BC    (N_RES * C_OUT)     /* 12288  (b,c) flattened */
#define NPAIR (N_RES * N_RES)     /* 147456 (b,d) pairs     */
#define KCE   (C_OUT * C_OUT)     /* 1024   (c,e) flattened */

// ---------------- scratch (device globals; no allocation allowed) ----------
__device__ float g_L[(size_t)N_SEQ * BC];            // fp32 [a, bc]
__device__ float g_R[(size_t)N_SEQ * BC];            // fp32 [a, de]
__device__ float g_ninv[NPAIR];
// fp16 K-major operands: [bc|de][a]
__device__ __align__(128) __half g_Lhi[(size_t)BC * N_SEQ];
__device__ __align__(128) __half g_Llo[(size_t)BC * N_SEQ];
__device__ __align__(128) __half g_Rh [(size_t)BC * N_SEQ];
// inter, PERMUTED [(b,d),(c,e)], pre-split fp16
__device__ __align__(128) __half g_iPhi[(size_t)NPAIR * KCE];  // 302 MB
__device__ __align__(128) __half g_iPlo[(size_t)NPAIR * KCE];  // 302 MB
// W transposed + split: [f][ce]
__device__ __align__(128) __half g_Wt_hi[(size_t)C_Z * KCE];
__device__ __align__(128) __half g_Wt_lo[(size_t)C_Z * KCE];

// ======================= PTX helpers (baseline sm_80 features) =============
__device__ __forceinline__ uint32_t smem_u32(const void* p) {
    uint32_t a;
    asm("{ .reg .u64 t; cvta.to.shared.u64 t, %1; cvt.u32.u64 %0, t; }"
        : "=r"(a) : "l"(p));
    return a;
}
#define LDSM_X4(r, addr) \
    asm volatile("ldmatrix.sync.aligned.m8n8.x4.shared.b16 {%0,%1,%2,%3}, [%4];" \
                 : "=r"((r)[0]), "=r"((r)[1]), "=r"((r)[2]), "=r"((r)[3]) \
                 : "r"(addr))
#define MMA_F16(d, a, b0, b1) \
    asm volatile("mma.sync.aligned.m16n8k16.row.col.f32.f16.f16.f32 " \
                 "{%0,%1,%2,%3},{%4,%5,%6,%7},{%8,%9},{%0,%1,%2,%3};" \
                 : "+f"((d)[0]), "+f"((d)[1]), "+f"((d)[2]), "+f"((d)[3]) \
                 : "r"((a)[0]), "r"((a)[1]), "r"((a)[2]), "r"((a)[3]), \
                   "r"(b0), "r"(b1))
#define CP_ASYNC16(dst, src) \
    asm volatile("cp.async.cg.shared.global [%0], [%1], 16;" \
                 :: "r"(dst), "l"(src) : "memory")
#define CP_COMMIT() asm volatile("cp.async.commit_group;" ::: "memory")
#define CP_WAIT(n)  asm volatile("cp.async.wait_group %0;" :: "n"(n) : "memory")

// XOR swizzle: chunk (m, c) of a [128 rows x 4 chunks-of-16B] tile.
__device__ __forceinline__ uint32_t swz(int m, int c) {
    int L = m * 4 + c;
    return (uint32_t)(((L >> 3) << 7) + ((((L & 7) ^ ((L >> 3) & 7))) << 4));
}

// ---------------- Kernel 1: LayerNorm + left/right projection + mask -------
__global__ __launch_bounds__(256) void ln_proj_kernel(
    const float* __restrict__ act, const float* __restrict__ mask,
    const float* __restrict__ ln_scale, const float* __restrict__ ln_offset,
    const float* __restrict__ left_w, const float* __restrict__ left_b,
    const float* __restrict__ right_w, const float* __restrict__ right_b)
{
    int row = blockIdx.x;              // row = a*N_RES + b
    int t = threadIdx.x;
    __shared__ float ys[C_M];
    __shared__ float red[16];
    __shared__ float ps[16][64];

    float x = act[(size_t)row * C_M + t];
    float s = x, s2 = x * x;
    #pragma unroll
    for (int o = 16; o > 0; o >>= 1) {
        s  += __shfl_down_sync(0xffffffffu, s, o);
        s2 += __shfl_down_sync(0xffffffffu, s2, o);
    }
    int wid = t >> 5, lane = t & 31;
    if (lane == 0) { red[wid] = s; red[wid + 8] = s2; }
    __syncthreads();
    float sum = 0.f, sumsq = 0.f;
    #pragma unroll
    for (int i = 0; i < 8; i++) { sum += red[i]; sumsq += red[i + 8]; }
    float mu  = sum * (1.0f / C_M);
    float var = sumsq * (1.0f / C_M) - mu * mu;
    float y = (x - mu) * rsqrtf(var + 1e-5f) * ln_scale[t] + ln_offset[t];
    ys[t] = y;
    __syncthreads();

    int og = t & 15;
    int ch = t >> 4;
    const float* Wp = (og < 8) ? (left_w + og * 4) : (right_w + (og - 8) * 4);
    float p0 = 0.f, p1 = 0.f, p2 = 0.f, p3 = 0.f;
    #pragma unroll
    for (int i = 0; i < 16; i++) {
        int k = ch * 16 + i;
        float4 w4 = *(const float4*)(Wp + (size_t)k * C_OUT);
        float yv = ys[k];
        p0 += yv * w4.x; p1 += yv * w4.y; p2 += yv * w4.z; p3 += yv * w4.w;
    }
    ps[ch][og * 4 + 0] = p0; ps[ch][og * 4 + 1] = p1;
    ps[ch][og * 4 + 2] = p2; ps[ch][og * 4 + 3] = p3;
    __syncthreads();

    if (t < 64) {
        float v = 0.f;
        #pragma unroll
        for (int c = 0; c < 16; c++) v += ps[c][t];
        float m = mask[row];
        int a = row / N_RES, b = row % N_RES;
        size_t idx = (size_t)a * BC + (size_t)b * C_OUT;
        if (t < 32) g_L[idx + t]        = m * (v + left_b[t]);
        else        g_R[idx + (t - 32)] = m * (v + right_b[t - 32]);
    }
}

// ------------- Kernel 1b: transpose + split/round to fp16 [bc][a] ----------
// z=0: L -> hi+lo split.  z=1: R -> single fp16 (rounded).
__global__ __launch_bounds__(256) void split_tr_kernel()
{
    __shared__ float t[32][65];
    const float* src = blockIdx.z ? g_R : g_L;
    int c0 = blockIdx.x * 64;
    int a0 = blockIdx.y * 32;
    for (int i = threadIdx.x; i < 32 * 64; i += 256) {
        int al = i >> 6, cl = i & 63;
        t[al][cl] = src[(size_t)(a0 + al) * BC + c0 + cl];
    }
    __syncthreads();
    if (blockIdx.z == 0) {
        for (int i = threadIdx.x; i < 64 * 32; i += 256) {
            int cl = i >> 5, al = i & 31;
            float x = t[al][cl];
            __half hi = __float2half_rn(x);
            __half lo = __float2half_rn(x - __half2float(hi));
            size_t o = (size_t)(c0 + cl) * N_SEQ + a0 + al;
            g_Lhi[o] = hi; g_Llo[o] = lo;
        }
    } else {
        for (int i = threadIdx.x; i < 64 * 32; i += 256) {
            int cl = i >> 5, al = i & 31;
            size_t o = (size_t)(c0 + cl) * N_SEQ + a0 + al;
            g_Rh[o] = __float2half_rn(t[al][cl]);
        }
    }
}

// ------ Kernel prep: norm reciprocal (blocks 0..575) + W split (576..703) --
__global__ __launch_bounds__(256) void prep_kernel(
    const float* __restrict__ mask, const float* __restrict__ W)
{
    if (blockIdx.x < 576) {
        int m = blockIdx.x * 256 + threadIdx.x;
        int b = m / N_RES, d = m % N_RES;
        float s = 0.f;
        for (int a = 0; a < N_SEQ; a++)
            s += mask[a * N_RES + b] * mask[a * N_RES + d];
        g_ninv[m] = 1.0f / (1e-3f + s);
    } else {
        __shared__ float t[32][33];
        int bb = blockIdx.x - 576;           // 0..127
        int k0 = (bb & 31) * 32;             // ce tile
        int f0 = (bb >> 5) * 32;             // f tile
        for (int i = threadIdx.x; i < 1024; i += 256) {
            int r = i >> 5, c = i & 31;
            t[r][c] = W[(size_t)(k0 + r) * C_Z + f0 + c];
        }
        __syncthreads();
        for (int i = threadIdx.x; i < 1024; i += 256) {
            int r = i >> 5, c = i & 31;
            float x = t[c][r];
            __half hi = __float2half_rn(x);
            __half lo = __float2half_rn(x - __half2float(hi));
            size_t o = (size_t)(f0 + r) * KCE + k0 + c;
            g_Wt_hi[o] = hi; g_Wt_lo[o] = lo;
        }
    }
}

// ============ smem geometry ================================================
#define TILE_B   8192                    /* 128 rows x 64B, XOR-swizzled */
#define G1_STAGE 24576                   /* 3 tiles: Ahi, Alo, Bh */
#define G1_SMEM  73728                   /* 3 stages; epilogue reuses 64KB */
#define G2_STAGE 32768                   /* 4 tiles: Ahi, Alo, Whi, Wlo */
#define G2_SMEM  98304

// ---------------- Kernel 3: GEMM1 = L^T R (2-term fp16) --------------------
__global__ __launch_bounds__(256, 2) void gemm1_mma()
{
    extern __shared__ __align__(128) char smem[];
    uint32_t sb = smem_u32(smem);
    int tid = threadIdx.x, lane = tid & 31, wid = tid >> 5;
    int i0 = blockIdx.y * 128;     // bc (M)
    int j0 = blockIdx.x * 128;     // de (N)
    int m_base = (wid & 1) * 64, n_base = (wid >> 1) * 32;

    const __half* base[3] = {
        g_Lhi + (size_t)i0 * N_SEQ, g_Llo + (size_t)i0 * N_SEQ,
        g_Rh  + (size_t)j0 * N_SEQ };

    uint32_t soff[2]; int gofs[2];
    #pragma unroll
    for (int i = 0; i < 2; i++) {
        int ch = tid + (i << 8);
        int m = ch >> 2, c = ch & 3;
        soff[i] = swz(m, c);
        gofs[i] = m * N_SEQ + c * 8;
    }

    uint32_t aoff[4][2], boff[2][2];
    #pragma unroll
    for (int mt = 0; mt < 4; mt++)
        #pragma unroll
        for (int ks = 0; ks < 2; ks++)
            aoff[mt][ks] = swz(m_base + mt * 16 + (lane & 15), ks * 2 + (lane >> 4));
    #pragma unroll
    for (int n2 = 0; n2 < 2; n2++)
        #pragma unroll
        for (int ks = 0; ks < 2; ks++)
            boff[n2][ks] = swz(n_base + n2 * 16 + (lane & 15), ks * 2 + (lane >> 4));

    float acc[4][4][4];
    #pragma unroll
    for (int a = 0; a < 4; a++)
        #pragma unroll
        for (int b = 0; b < 4; b++)
            #pragma unroll
            for (int c = 0; c < 4; c++) acc[a][b][c] = 0.f;

    // prologue: stages 0,1 = K chunks 0,1
    #pragma unroll
    for (int s = 0; s < 2; s++) {
        #pragma unroll
        for (int t = 0; t < 3; t++)
            #pragma unroll
            for (int i = 0; i < 2; i++)
                CP_ASYNC16(sb + s * G1_STAGE + t * TILE_B + soff[i],
                           base[t] + gofs[i] + s * 32);
        CP_COMMIT();
    }

    for (int kt = 0; kt < 16; kt++) {
        CP_WAIT(1);
        __syncthreads();
        if (kt + 2 < 16) {
            uint32_t so = (uint32_t)((kt + 2) % 3) * G1_STAGE;
            #pragma unroll
            for (int t = 0; t < 3; t++)
                #pragma unroll
                for (int i = 0; i < 2; i++)
                    CP_ASYNC16(sb + so + t * TILE_B + soff[i],
                               base[t] + gofs[i] + (kt + 2) * 32);
        }
        CP_COMMIT();
        uint32_t stb = sb + (uint32_t)(kt % 3) * G1_STAGE;
        #pragma unroll
        for (int ks = 0; ks < 2; ks++) {
            uint32_t ah[4][4], al[4][4], bh[2][4];
            #pragma unroll
            for (int mt = 0; mt < 4; mt++) {
                LDSM_X4(ah[mt], stb + aoff[mt][ks]);
                LDSM_X4(al[mt], stb + TILE_B + aoff[mt][ks]);
            }
            #pragma unroll
            for (int n2 = 0; n2 < 2; n2++)
                LDSM_X4(bh[n2], stb + 2 * TILE_B + boff[n2][ks]);
            #pragma unroll
            for (int mt = 0; mt < 4; mt++)
                #pragma unroll
                for (int nt = 0; nt < 4; nt++)
                    MMA_F16(acc[mt][nt], ah[mt], bh[nt >> 1][nt & 1],
                            bh[nt >> 1][(nt & 1) + 2]);
            #pragma unroll
            for (int mt = 0; mt < 4; mt++)
                #pragma unroll
                for (int nt = 0; nt < 4; nt++)
                    MMA_F16(acc[mt][nt], al[mt], bh[nt >> 1][nt & 1],
                            bh[nt >> 1][(nt & 1) + 2]);
        }
    }

    // ---- epilogue: scatter into smem (split-fp16, permuted), then copy ----
    __syncthreads();
    int g = lane >> 2, tg = lane & 3;
    #pragma unroll
    for (int mt = 0; mt < 4; mt++) {
        #pragma unroll
        for (int h = 0; h < 2; h++) {
            int rr = m_base + mt * 16 + g + h * 8;
            int bl = rr >> 5, c = rr & 31;
            #pragma unroll
            for (int nt = 0; nt < 4; nt++) {
                int q = n_base + nt * 8 + tg * 2;
                int dl = q >> 5, e = q & 31;
                int p = bl * 4 + dl;
                uint32_t off = (uint32_t)(p * 2048 + (c * 32 + e) * 2);
                float x = acc[mt][nt][h * 2 + 0], y = acc[mt][nt][h * 2 + 1];
                __half hx = __float2half_rn(x), hy = __float2half_rn(y);
                __half lx = __float2half_rn(x - __half2float(hx));
                __half ly = __float2half_rn(y - __half2float(hy));
                *(__half2*)(smem + off)         = __halves2half2(hx, hy);
                *(__half2*)(smem + 32768 + off) = __halves2half2(lx, ly);
            }
        }
    }
    __syncthreads();
    int b0 = blockIdx.y * 4, d0 = blockIdx.x * 4;
    #pragma unroll
    for (int i = 0; i < 8; i++) {
        int qc = tid + 256 * i;              // 16B chunk id, 2048 total
        int p = qc >> 7, off = qc & 127;
        size_t row = (size_t)((b0 + (p >> 2)) * N_RES + d0 + (p & 3)) * KCE + off * 8;
        *(uint4*)(g_iPhi + row) = *(const uint4*)(smem + qc * 16);
        *(uint4*)(g_iPlo + row) = *(const uint4*)(smem + 32768 + qc * 16);
    }
}

// ---------------- Kernel 4: GEMM2 = interP @ Wt^T + b, / norm (3-term) -----
__global__ __launch_bounds__(256, 2) void gemm2_mma(
    const float* __restrict__ ob, float* __restrict__ out)
{
    extern __shared__ __align__(128) char smem[];
    uint32_t sb = smem_u32(smem);
    int tid = threadIdx.x, lane = tid & 31, wid = tid >> 5;
    int m0 = blockIdx.x * 128;
    int m_base = (wid & 1) * 64, n_base = (wid >> 1) * 32;

    const __half* base[4] = {
        g_iPhi + (size_t)m0 * KCE, g_iPlo + (size_t)m0 * KCE,
        g_Wt_hi, g_Wt_lo };

    uint32_t soff[2]; int gofs[2];
    #pragma unroll
    for (int i = 0; i < 2; i++) {
        int ch = tid + (i << 8);
        int m = ch >> 2, c = ch & 3;
        soff[i] = swz(m, c);
        gofs[i] = m * KCE + c * 8;
    }

    uint32_t aoff[4][2], boff[2][2];
    #pragma unroll
    for (int mt = 0; mt < 4; mt++)
        #pragma unroll
        for (int ks = 0; ks < 2; ks++)
            aoff[mt][ks] = swz(m_base + mt * 16 + (lane & 15), ks * 2 + (lane >> 4));
    #pragma unroll
    for (int n2 = 0; n2 < 2; n2++)
        #pragma unroll
        for (int ks = 0; ks < 2; ks++)
            boff[n2][ks] = swz(n_base + n2 * 16 + (lane & 15), ks * 2 + (lane >> 4));

    float acc[4][4][4];
    #pragma unroll
    for (int a = 0; a < 4; a++)
        #pragma unroll
        for (int b = 0; b < 4; b++)
            #pragma unroll
            for (int c = 0; c < 4; c++) acc[a][b][c] = 0.f;

    #pragma unroll
    for (int s = 0; s < 2; s++) {
        #pragma unroll
        for (int t = 0; t < 4; t++)
            #pragma unroll
            for (int i = 0; i < 2; i++)
                CP_ASYNC16(sb + s * G2_STAGE + t * TILE_B + soff[i],
                           base[t] + gofs[i] + s * 32);
        CP_COMMIT();
    }

    for (int kt = 0; kt < 32; kt++) {
        CP_WAIT(1);
        __syncthreads();
        if (kt + 2 < 32) {
            uint32_t so = (uint32_t)((kt + 2) % 3) * G2_STAGE;
            #pragma unroll
            for (int t = 0; t < 4; t++)
                #pragma unroll
                for (int i = 0; i < 2; i++)
                    CP_ASYNC16(sb + so + t * TILE_B + soff[i],
                               base[t] + gofs[i] + (kt + 2) * 32);
        }
        CP_COMMIT();
        uint32_t stb = sb + (uint32_t)(kt % 3) * G2_STAGE;
        #pragma unroll
        for (int ks = 0; ks < 2; ks++) {
            uint32_t ah[4][4], al[4][4], bh[2][4], bl[2][4];
            #pragma unroll
            for (int mt = 0; mt < 4; mt++) {
                LDSM_X4(ah[mt], stb + aoff[mt][ks]);
                LDSM_X4(al[mt], stb + TILE_B + aoff[mt][ks]);
            }
            #pragma unroll
            for (int n2 = 0; n2 < 2; n2++) {
                LDSM_X4(bh[n2], stb + 2 * TILE_B + boff[n2][ks]);
                LDSM_X4(bl[n2], stb + 3 * TILE_B + boff[n2][ks]);
            }
            #pragma unroll
            for (int mt = 0; mt < 4; mt++)
                #pragma unroll
                for (int nt = 0; nt < 4; nt++)
                    MMA_F16(acc[mt][nt], ah[mt], bh[nt >> 1][nt & 1],
                            bh[nt >> 1][(nt & 1) + 2]);
            #pragma unroll
            for (int mt = 0; mt < 4; mt++)
                #pragma unroll
                for (int nt = 0; nt < 4; nt++)
                    MMA_F16(acc[mt][nt], ah[mt], bl[nt >> 1][nt & 1],
                            bl[nt >> 1][(nt & 1) + 2]);
            #pragma unroll
            for (int mt = 0; mt < 4; mt++)
                #pragma unroll
                for (int nt = 0; nt < 4; nt++)
                    MMA_F16(acc[mt][nt], al[mt], bh[nt >> 1][nt & 1],
                            bh[nt >> 1][(nt & 1) + 2]);
        }
    }

    int g = lane >> 2, tg = lane & 3;
    #pragma unroll
    for (int mt = 0; mt < 4; mt++) {
        #pragma unroll
        for (int h = 0; h < 2; h++) {
            int m = m0 + m_base + mt * 16 + g + h * 8;
            float inv = g_ninv[m];
            #pragma unroll
            for (int nt = 0; nt < 4; nt++) {
                int f = n_base + nt * 8 + tg * 2;
                float2 v;
                v.x = (acc[mt][nt][h * 2 + 0] + ob[f + 0]) * inv;
                v.y = (acc[mt][nt][h * 2 + 1] + ob[f + 1]) * inv;
                *(float2*)&out[(size_t)m * C_Z + f] = v;
            }
        }
    }
}

// ---------------------------------------------------------------------------
extern "C" void kernel_launch(void* const* d_in, const int* in_sizes, int n_in,
                              void* d_out, int out_size)
{
    const float* act       = (const float*)d_in[0];
    const float* mask      = (const float*)d_in[1];
    const float* ln_scale  = (const float*)d_in[2];
    const float* ln_offset = (const float*)d_in[3];
    const float* left_w    = (const float*)d_in[4];
    const float* left_b    = (const float*)d_in[5];
    const float* right_w   = (const float*)d_in[6];
    const float* right_b   = (const float*)d_in[7];
    const float* output_w  = (const float*)d_in[8];
    const float* output_b  = (const float*)d_in[9];
    float* out = (float*)d_out;

    cudaFuncSetAttribute(gemm1_mma, cudaFuncAttributeMaxDynamicSharedMemorySize, G1_SMEM);
    cudaFuncSetAttribute(gemm2_mma, cudaFuncAttributeMaxDynamicSharedMemorySize, G2_SMEM);

    // order: prep(1), ln_proj(2), split_tr(3), gemm1(4 = profiler slot), gemm2(5)
    prep_kernel<<<576 + 128, 256>>>(mask, output_w);
    ln_proj_kernel<<<N_SEQ * N_RES, 256>>>(act, mask, ln_scale, ln_offset,
                                           left_w, left_b, right_w, right_b);
    split_tr_kernel<<<dim3(BC / 64, N_SEQ / 32, 2), 256>>>();
    gemm1_mma<<<dim3(BC / 128, BC / 128), 256, G1_SMEM>>>();
    gemm2_mma<<<NPAIR / 128, 256, G2_SMEM>>>(output_b, out);
}

// round 10
// speedup vs baseline: 1.6838x; 1.1086x over previous
#include <cuda_runtime.h>
#include <cuda_fp16.h>
#include <math.h>
#include <stdint.h>

#define N_SEQ 512
#define N_RES 384
#define C_M   256
#define C_OUT 32
#define C_Z   128
#define BC    (N_RES * C_OUT)     /* 12288  (b,c) flattened */
#define NPAIR (N_RES * N_RES)     /* 147456 (b,d) pairs     */
#define KCE   (C_OUT * C_OUT)     /* 1024   (c,e) flattened */

// ---------------- scratch (device globals; no allocation allowed) ----------
__device__ float g_L[(size_t)N_SEQ * BC];            // fp32 [a, bc]
__device__ float g_R[(size_t)N_SEQ * BC];            // fp32 [a, de]
__device__ float g_ninv[NPAIR];
// fp16 K-major operands: [bc|de][a]
__device__ __align__(128) __half g_Lhi[(size_t)BC * N_SEQ];
__device__ __align__(128) __half g_Llo[(size_t)BC * N_SEQ];
__device__ __align__(128) __half g_Rh [(size_t)BC * N_SEQ];
// inter, PERMUTED [(b,d),(c,e)], single fp16
__device__ __align__(128) __half g_iPhi[(size_t)NPAIR * KCE];  // 302 MB
// W transposed + split: [f][ce]
__device__ __align__(128) __half g_Wt_hi[(size_t)C_Z * KCE];
__device__ __align__(128) __half g_Wt_lo[(size_t)C_Z * KCE];

// ======================= PTX helpers (baseline sm_80 features) =============
__device__ __forceinline__ uint32_t smem_u32(const void* p) {
    uint32_t a;
    asm("{ .reg .u64 t; cvta.to.shared.u64 t, %1; cvt.u32.u64 %0, t; }"
        : "=r"(a) : "l"(p));
    return a;
}
#define LDSM_X4(r, addr) \
    asm volatile("ldmatrix.sync.aligned.m8n8.x4.shared.b16 {%0,%1,%2,%3}, [%4];" \
                 : "=r"((r)[0]), "=r"((r)[1]), "=r"((r)[2]), "=r"((r)[3]) \
                 : "r"(addr))
#define MMA_F16(d, a, b0, b1) \
    asm volatile("mma.sync.aligned.m16n8k16.row.col.f32.f16.f16.f32 " \
                 "{%0,%1,%2,%3},{%4,%5,%6,%7},{%8,%9},{%0,%1,%2,%3};" \
                 : "+f"((d)[0]), "+f"((d)[1]), "+f"((d)[2]), "+f"((d)[3]) \
                 : "r"((a)[0]), "r"((a)[1]), "r"((a)[2]), "r"((a)[3]), \
                   "r"(b0), "r"(b1))
#define CP_ASYNC16(dst, src) \
    asm volatile("cp.async.cg.shared.global [%0], [%1], 16;" \
                 :: "r"(dst), "l"(src) : "memory")
#define CP_COMMIT() asm volatile("cp.async.commit_group;" ::: "memory")
#define CP_WAIT(n)  asm volatile("cp.async.wait_group %0;" :: "n"(n) : "memory")

// XOR swizzle: chunk (m, c) of a [128 rows x 4 chunks-of-16B] tile.
__device__ __forceinline__ uint32_t swz(int m, int c) {
    int L = m * 4 + c;
    return (uint32_t)(((L >> 3) << 7) + ((((L & 7) ^ ((L >> 3) & 7))) << 4));
}

// ---------------- Kernel 1: LayerNorm + left/right projection + mask -------
__global__ __launch_bounds__(256) void ln_proj_kernel(
    const float* __restrict__ act, const float* __restrict__ mask,
    const float* __restrict__ ln_scale, const float* __restrict__ ln_offset,
    const float* __restrict__ left_w, const float* __restrict__ left_b,
    const float* __restrict__ right_w, const float* __restrict__ right_b)
{
    int row = blockIdx.x;              // row = a*N_RES + b
    int t = threadIdx.x;
    __shared__ float ys[C_M];
    __shared__ float red[16];
    __shared__ float ps[16][64];

    float x = act[(size_t)row * C_M + t];
    float s = x, s2 = x * x;
    #pragma unroll
    for (int o = 16; o > 0; o >>= 1) {
        s  += __shfl_down_sync(0xffffffffu, s, o);
        s2 += __shfl_down_sync(0xffffffffu, s2, o);
    }
    int wid = t >> 5, lane = t & 31;
    if (lane == 0) { red[wid] = s; red[wid + 8] = s2; }
    __syncthreads();
    float sum = 0.f, sumsq = 0.f;
    #pragma unroll
    for (int i = 0; i < 8; i++) { sum += red[i]; sumsq += red[i + 8]; }
    float mu  = sum * (1.0f / C_M);
    float var = sumsq * (1.0f / C_M) - mu * mu;
    float y = (x - mu) * rsqrtf(var + 1e-5f) * ln_scale[t] + ln_offset[t];
    ys[t] = y;
    __syncthreads();

    int og = t & 15;
    int ch = t >> 4;
    const float* Wp = (og < 8) ? (left_w + og * 4) : (right_w + (og - 8) * 4);
    float p0 = 0.f, p1 = 0.f, p2 = 0.f, p3 = 0.f;
    #pragma unroll
    for (int i = 0; i < 16; i++) {
        int k = ch * 16 + i;
        float4 w4 = *(const float4*)(Wp + (size_t)k * C_OUT);
        float yv = ys[k];
        p0 += yv * w4.x; p1 += yv * w4.y; p2 += yv * w4.z; p3 += yv * w4.w;
    }
    ps[ch][og * 4 + 0] = p0; ps[ch][og * 4 + 1] = p1;
    ps[ch][og * 4 + 2] = p2; ps[ch][og * 4 + 3] = p3;
    __syncthreads();

    if (t < 64) {
        float v = 0.f;
        #pragma unroll
        for (int c = 0; c < 16; c++) v += ps[c][t];
        float m = mask[row];
        int a = row / N_RES, b = row % N_RES;
        size_t idx = (size_t)a * BC + (size_t)b * C_OUT;
        if (t < 32) g_L[idx + t]        = m * (v + left_b[t]);
        else        g_R[idx + (t - 32)] = m * (v + right_b[t - 32]);
    }
}

// ------------- Kernel 1b: transpose + split/round to fp16 [bc][a] ----------
// z=0: L -> hi+lo split.  z=1: R -> single fp16 (rounded).
__global__ __launch_bounds__(256) void split_tr_kernel()
{
    __shared__ float t[32][65];
    const float* src = blockIdx.z ? g_R : g_L;
    int c0 = blockIdx.x * 64;
    int a0 = blockIdx.y * 32;
    for (int i = threadIdx.x; i < 32 * 64; i += 256) {
        int al = i >> 6, cl = i & 63;
        t[al][cl] = src[(size_t)(a0 + al) * BC + c0 + cl];
    }
    __syncthreads();
    if (blockIdx.z == 0) {
        for (int i = threadIdx.x; i < 64 * 32; i += 256) {
            int cl = i >> 5, al = i & 31;
            float x = t[al][cl];
            __half hi = __float2half_rn(x);
            __half lo = __float2half_rn(x - __half2float(hi));
            size_t o = (size_t)(c0 + cl) * N_SEQ + a0 + al;
            g_Lhi[o] = hi; g_Llo[o] = lo;
        }
    } else {
        for (int i = threadIdx.x; i < 64 * 32; i += 256) {
            int cl = i >> 5, al = i & 31;
            size_t o = (size_t)(c0 + cl) * N_SEQ + a0 + al;
            g_Rh[o] = __float2half_rn(t[al][cl]);
        }
    }
}

// ------ Kernel prep: norm reciprocal (blocks 0..575) + W split (576..703) --
__global__ __launch_bounds__(256) void prep_kernel(
    const float* __restrict__ mask, const float* __restrict__ W)
{
    if (blockIdx.x < 576) {
        int m = blockIdx.x * 256 + threadIdx.x;
        int b = m / N_RES, d = m % N_RES;
        float s = 0.f;
        for (int a = 0; a < N_SEQ; a++)
            s += mask[a * N_RES + b] * mask[a * N_RES + d];
        g_ninv[m] = 1.0f / (1e-3f + s);
    } else {
        __shared__ float t[32][33];
        int bb = blockIdx.x - 576;           // 0..127
        int k0 = (bb & 31) * 32;             // ce tile
        int f0 = (bb >> 5) * 32;             // f tile
        for (int i = threadIdx.x; i < 1024; i += 256) {
            int r = i >> 5, c = i & 31;
            t[r][c] = W[(size_t)(k0 + r) * C_Z + f0 + c];
        }
        __syncthreads();
        for (int i = threadIdx.x; i < 1024; i += 256) {
            int r = i >> 5, c = i & 31;
            float x = t[c][r];
            __half hi = __float2half_rn(x);
            __half lo = __float2half_rn(x - __half2float(hi));
            size_t o = (size_t)(f0 + r) * KCE + k0 + c;
            g_Wt_hi[o] = hi; g_Wt_lo[o] = lo;
        }
    }
}

// ============ smem geometry ================================================
#define TILE_B   8192                    /* 128 rows x 64B, XOR-swizzled */
#define G1_STAGE 24576                   /* 3 tiles: Ahi, Alo, Bh */
#define G1_SMEM  73728                   /* 3 stages; epilogue reuses 32KB */
#define G2_STAGE 24576                   /* 3 tiles: A, Whi, Wlo */
#define G2_SMEM  73728

// ---------------- Kernel 3: GEMM1 = L^T R (2-term fp16) --------------------
__global__ __launch_bounds__(256, 2) void gemm1_mma()
{
    extern __shared__ __align__(128) char smem[];
    uint32_t sb = smem_u32(smem);
    int tid = threadIdx.x, lane = tid & 31, wid = tid >> 5;
    int i0 = blockIdx.y * 128;     // bc (M)
    int j0 = blockIdx.x * 128;     // de (N)
    int m_base = (wid & 1) * 64, n_base = (wid >> 1) * 32;

    const __half* base[3] = {
        g_Lhi + (size_t)i0 * N_SEQ, g_Llo + (size_t)i0 * N_SEQ,
        g_Rh  + (size_t)j0 * N_SEQ };

    uint32_t soff[2]; int gofs[2];
    #pragma unroll
    for (int i = 0; i < 2; i++) {
        int ch = tid + (i << 8);
        int m = ch >> 2, c = ch & 3;
        soff[i] = swz(m, c);
        gofs[i] = m * N_SEQ + c * 8;
    }

    uint32_t aoff[4][2], boff[2][2];
    #pragma unroll
    for (int mt = 0; mt < 4; mt++)
        #pragma unroll
        for (int ks = 0; ks < 2; ks++)
            aoff[mt][ks] = swz(m_base + mt * 16 + (lane & 15), ks * 2 + (lane >> 4));
    #pragma unroll
    for (int n2 = 0; n2 < 2; n2++)
        #pragma unroll
        for (int ks = 0; ks < 2; ks++)
            boff[n2][ks] = swz(n_base + n2 * 16 + (lane & 15), ks * 2 + (lane >> 4));

    float acc[4][4][4];
    #pragma unroll
    for (int a = 0; a < 4; a++)
        #pragma unroll
        for (int b = 0; b < 4; b++)
            #pragma unroll
            for (int c = 0; c < 4; c++) acc[a][b][c] = 0.f;

    // prologue: stages 0,1 = K chunks 0,1
    #pragma unroll
    for (int s = 0; s < 2; s++) {
        #pragma unroll
        for (int t = 0; t < 3; t++)
            #pragma unroll
            for (int i = 0; i < 2; i++)
                CP_ASYNC16(sb + s * G1_STAGE + t * TILE_B + soff[i],
                           base[t] + gofs[i] + s * 32);
        CP_COMMIT();
    }

    for (int kt = 0; kt < 16; kt++) {
        CP_WAIT(1);
        __syncthreads();
        if (kt + 2 < 16) {
            uint32_t so = (uint32_t)((kt + 2) % 3) * G1_STAGE;
            #pragma unroll
            for (int t = 0; t < 3; t++)
                #pragma unroll
                for (int i = 0; i < 2; i++)
                    CP_ASYNC16(sb + so + t * TILE_B + soff[i],
                               base[t] + gofs[i] + (kt + 2) * 32);
        }
        CP_COMMIT();
        uint32_t stb = sb + (uint32_t)(kt % 3) * G1_STAGE;
        #pragma unroll
        for (int ks = 0; ks < 2; ks++) {
            uint32_t ah[4][4], al[4][4], bh[2][4];
            #pragma unroll
            for (int mt = 0; mt < 4; mt++) {
                LDSM_X4(ah[mt], stb + aoff[mt][ks]);
                LDSM_X4(al[mt], stb + TILE_B + aoff[mt][ks]);
            }
            #pragma unroll
            for (int n2 = 0; n2 < 2; n2++)
                LDSM_X4(bh[n2], stb + 2 * TILE_B + boff[n2][ks]);
            #pragma unroll
            for (int mt = 0; mt < 4; mt++)
                #pragma unroll
                for (int nt = 0; nt < 4; nt++)
                    MMA_F16(acc[mt][nt], ah[mt], bh[nt >> 1][nt & 1],
                            bh[nt >> 1][(nt & 1) + 2]);
            #pragma unroll
            for (int mt = 0; mt < 4; mt++)
                #pragma unroll
                for (int nt = 0; nt < 4; nt++)
                    MMA_F16(acc[mt][nt], al[mt], bh[nt >> 1][nt & 1],
                            bh[nt >> 1][(nt & 1) + 2]);
        }
    }

    // ---- epilogue: scatter into smem (single fp16, permuted), then copy ---
    __syncthreads();
    int g = lane >> 2, tg = lane & 3;
    #pragma unroll
    for (int mt = 0; mt < 4; mt++) {
        #pragma unroll
        for (int h = 0; h < 2; h++) {
            int rr = m_base + mt * 16 + g + h * 8;
            int bl = rr >> 5, c = rr & 31;
            #pragma unroll
            for (int nt = 0; nt < 4; nt++) {
                int q = n_base + nt * 8 + tg * 2;
                int dl = q >> 5, e = q & 31;
                int p = bl * 4 + dl;
                uint32_t off = (uint32_t)(p * 2048 + (c * 32 + e) * 2);
                *(__half2*)(smem + off) = __halves2half2(
                    __float2half_rn(acc[mt][nt][h * 2 + 0]),
                    __float2half_rn(acc[mt][nt][h * 2 + 1]));
            }
        }
    }
    __syncthreads();
    int b0 = blockIdx.y * 4, d0 = blockIdx.x * 4;
    #pragma unroll
    for (int i = 0; i < 8; i++) {
        int qc = tid + 256 * i;              // 16B chunk id, 2048 total
        int p = qc >> 7, off = qc & 127;
        size_t row = (size_t)((b0 + (p >> 2)) * N_RES + d0 + (p & 3)) * KCE + off * 8;
        *(uint4*)(g_iPhi + row) = *(const uint4*)(smem + qc * 16);
    }
}

// ---------------- Kernel 4: GEMM2 = interP @ (Whi+Wlo)^T + b, / norm -------
__global__ __launch_bounds__(256, 2) void gemm2_mma(
    const float* __restrict__ ob, float* __restrict__ out)
{
    extern __shared__ __align__(128) char smem[];
    uint32_t sb = smem_u32(smem);
    int tid = threadIdx.x, lane = tid & 31, wid = tid >> 5;
    int m0 = blockIdx.x * 128;
    int m_base = (wid & 1) * 64, n_base = (wid >> 1) * 32;

    const __half* base[3] = { g_iPhi + (size_t)m0 * KCE, g_Wt_hi, g_Wt_lo };

    uint32_t soff[2]; int gofs[2];
    #pragma unroll
    for (int i = 0; i < 2; i++) {
        int ch = tid + (i << 8);
        int m = ch >> 2, c = ch & 3;
        soff[i] = swz(m, c);
        gofs[i] = m * KCE + c * 8;
    }

    uint32_t aoff[4][2], boff[2][2];
    #pragma unroll
    for (int mt = 0; mt < 4; mt++)
        #pragma unroll
        for (int ks = 0; ks < 2; ks++)
            aoff[mt][ks] = swz(m_base + mt * 16 + (lane & 15), ks * 2 + (lane >> 4));
    #pragma unroll
    for (int n2 = 0; n2 < 2; n2++)
        #pragma unroll
        for (int ks = 0; ks < 2; ks++)
            boff[n2][ks] = swz(n_base + n2 * 16 + (lane & 15), ks * 2 + (lane >> 4));

    float acc[4][4][4];
    #pragma unroll
    for (int a = 0; a < 4; a++)
        #pragma unroll
        for (int b = 0; b < 4; b++)
            #pragma unroll
            for (int c = 0; c < 4; c++) acc[a][b][c] = 0.f;

    #pragma unroll
    for (int s = 0; s < 2; s++) {
        #pragma unroll
        for (int t = 0; t < 3; t++)
            #pragma unroll
            for (int i = 0; i < 2; i++)
                CP_ASYNC16(sb + s * G2_STAGE + t * TILE_B + soff[i],
                           base[t] + gofs[i] + s * 32);
        CP_COMMIT();
    }

    for (int kt = 0; kt < 32; kt++) {
        CP_WAIT(1);
        __syncthreads();
        if (kt + 2 < 32) {
            uint32_t so = (uint32_t)((kt + 2) % 3) * G2_STAGE;
            #pragma unroll
            for (int t = 0; t < 3; t++)
                #pragma unroll
                for (int i = 0; i < 2; i++)
                    CP_ASYNC16(sb + so + t * TILE_B + soff[i],
                               base[t] + gofs[i] + (kt + 2) * 32);
        }
        CP_COMMIT();
        uint32_t stb = sb + (uint32_t)(kt % 3) * G2_STAGE;
        #pragma unroll
        for (int ks = 0; ks < 2; ks++) {
            uint32_t ah[4][4], bh[2][4], bl[2][4];
            #pragma unroll
            for (int mt = 0; mt < 4; mt++)
                LDSM_X4(ah[mt], stb + aoff[mt][ks]);
            #pragma unroll
            for (int n2 = 0; n2 < 2; n2++) {
                LDSM_X4(bh[n2], stb + TILE_B + boff[n2][ks]);
                LDSM_X4(bl[n2], stb + 2 * TILE_B + boff[n2][ks]);
            }
            #pragma unroll
            for (int mt = 0; mt < 4; mt++)
                #pragma unroll
                for (int nt = 0; nt < 4; nt++)
                    MMA_F16(acc[mt][nt], ah[mt], bh[nt >> 1][nt & 1],
                            bh[nt >> 1][(nt & 1) + 2]);
            #pragma unroll
            for (int mt = 0; mt < 4; mt++)
                #pragma unroll
                for (int nt = 0; nt < 4; nt++)
                    MMA_F16(acc[mt][nt], ah[mt], bl[nt >> 1][nt & 1],
                            bl[nt >> 1][(nt & 1) + 2]);
        }
    }

    int g = lane >> 2, tg = lane & 3;
    #pragma unroll
    for (int mt = 0; mt < 4; mt++) {
        #pragma unroll
        for (int h = 0; h < 2; h++) {
            int m = m0 + m_base + mt * 16 + g + h * 8;
            float inv = g_ninv[m];
            #pragma unroll
            for (int nt = 0; nt < 4; nt++) {
                int f = n_base + nt * 8 + tg * 2;
                float2 v;
                v.x = (acc[mt][nt][h * 2 + 0] + ob[f + 0]) * inv;
                v.y = (acc[mt][nt][h * 2 + 1] + ob[f + 1]) * inv;
                *(float2*)&out[(size_t)m * C_Z + f] = v;
            }
        }
    }
}

// ---------------------------------------------------------------------------
extern "C" void kernel_launch(void* const* d_in, const int* in_sizes, int n_in,
                              void* d_out, int out_size)
{
    const float* act       = (const float*)d_in[0];
    const float* mask      = (const float*)d_in[1];
    const float* ln_scale  = (const float*)d_in[2];
    const float* ln_offset = (const float*)d_in[3];
    const float* left_w    = (const float*)d_in[4];
    const float* left_b    = (const float*)d_in[5];
    const float* right_w   = (const float*)d_in[6];
    const float* right_b   = (const float*)d_in[7];
    const float* output_w  = (const float*)d_in[8];
    const float* output_b  = (const float*)d_in[9];
    float* out = (float*)d_out;

    cudaFuncSetAttribute(gemm1_mma, cudaFuncAttributeMaxDynamicSharedMemorySize, G1_SMEM);
    cudaFuncSetAttribute(gemm2_mma, cudaFuncAttributeMaxDynamicSharedMemorySize, G2_SMEM);

    // order: prep(1), ln_proj(2), split_tr(3), gemm1(4 = profiler slot), gemm2(5)
    prep_kernel<<<576 + 128, 256>>>(mask, output_w);
    ln_proj_kernel<<<N_SEQ * N_RES, 256>>>(act, mask, ln_scale, ln_offset,
                                           left_w, left_b, right_w, right_b);
    split_tr_kernel<<<dim3(BC / 64, N_SEQ / 32, 2), 256>>>();
    gemm1_mma<<<dim3(BC / 128, BC / 128), 256, G1_SMEM>>>();
    gemm2_mma<<<NPAIR / 128, 256, G2_SMEM>>>(output_b, out);
}

// round 11
// speedup vs baseline: 2.2498x; 1.3362x over previous
#include <cuda_runtime.h>
#include <cuda_fp16.h>
#include <math.h>
#include <stdint.h>

#define N_SEQ 512
#define N_RES 384
#define C_M   256
#define C_OUT 32
#define C_Z   128
#define BC    (N_RES * C_OUT)     /* 12288  (b,c) flattened */
#define NPAIR (N_RES * N_RES)     /* 147456 (b,d) pairs     */
#define KCE   (C_OUT * C_OUT)     /* 1024   (c,e) flattened */

// ---------------- scratch (device globals; no allocation allowed) ----------
__device__ float g_L[(size_t)N_SEQ * BC];            // fp32 [a, bc]
__device__ float g_R[(size_t)N_SEQ * BC];            // fp32 [a, de]
__device__ float g_ninv[NPAIR];
// fp16 K-major operands: [bc|de][a]
__device__ __align__(128) __half g_Lhi[(size_t)BC * N_SEQ];
__device__ __align__(128) __half g_Llo[(size_t)BC * N_SEQ];
__device__ __align__(128) __half g_Rh [(size_t)BC * N_SEQ];
// inter, PERMUTED [(b,d),(c,e)], single fp16
__device__ __align__(128) __half g_iPhi[(size_t)NPAIR * KCE];  // 302 MB
// W transposed + split: [f][ce]
__device__ __align__(128) __half g_Wt_hi[(size_t)C_Z * KCE];
__device__ __align__(128) __half g_Wt_lo[(size_t)C_Z * KCE];
// projection weights, transposed: [og 64][k 256] (og<32 = left, og>=32 = right)
__device__ __align__(128) __half g_PwT[64 * C_M];

// ======================= PTX helpers (baseline sm_80 features) =============
__device__ __forceinline__ uint32_t smem_u32(const void* p) {
    uint32_t a;
    asm("{ .reg .u64 t; cvta.to.shared.u64 t, %1; cvt.u32.u64 %0, t; }"
        : "=r"(a) : "l"(p));
    return a;
}
#define LDSM_X4(r, addr) \
    asm volatile("ldmatrix.sync.aligned.m8n8.x4.shared.b16 {%0,%1,%2,%3}, [%4];" \
                 : "=r"((r)[0]), "=r"((r)[1]), "=r"((r)[2]), "=r"((r)[3]) \
                 : "r"(addr))
#define MMA_F16(d, a, b0, b1) \
    asm volatile("mma.sync.aligned.m16n8k16.row.col.f32.f16.f16.f32 " \
                 "{%0,%1,%2,%3},{%4,%5,%6,%7},{%8,%9},{%0,%1,%2,%3};" \
                 : "+f"((d)[0]), "+f"((d)[1]), "+f"((d)[2]), "+f"((d)[3]) \
                 : "r"((a)[0]), "r"((a)[1]), "r"((a)[2]), "r"((a)[3]), \
                   "r"(b0), "r"(b1))
#define CP_ASYNC16(dst, src) \
    asm volatile("cp.async.cg.shared.global [%0], [%1], 16;" \
                 :: "r"(dst), "l"(src) : "memory")
#define CP_COMMIT() asm volatile("cp.async.commit_group;" ::: "memory")
#define CP_WAIT(n)  asm volatile("cp.async.wait_group %0;" :: "n"(n) : "memory")

// XOR swizzle: chunk (m, c) of a [<=128 rows x 4 chunks-of-16B] tile.
__device__ __forceinline__ uint32_t swz(int m, int c) {
    int L = m * 4 + c;
    return (uint32_t)(((L >> 3) << 7) + ((((L & 7) ^ ((L >> 3) & 7))) << 4));
}

__device__ __forceinline__ uint32_t pack_h2(float a, float b) {
    __half2 p = __halves2half2(__float2half_rn(a), __float2half_rn(b));
    return *(uint32_t*)&p;
}

// ---------------- Kernel 1: LN + projection via tensor cores ---------------
// 64 rows per CTA. Phase 1: warp-per-row LN, y stored to smem as exact
// fp16 hi+lo split (swizzled). Phase 2: HMMA [64x256]@[256x64], 2-term.
#define YT_STRIDE 4112           /* 257*16: padded tile stride */
#define LNP_YHI 0
#define LNP_YLO 32896            /* 8*4112 */
#define LNP_W   65792
#define LNP_SMEM 98688           /* 65792 + 32896 */

__global__ __launch_bounds__(256, 2) void ln_proj_mma(
    const float* __restrict__ act, const float* __restrict__ mask,
    const float* __restrict__ ln_scale, const float* __restrict__ ln_offset,
    const float* __restrict__ left_b, const float* __restrict__ right_b)
{
    extern __shared__ __align__(128) char smem[];
    uint32_t sb = smem_u32(smem);
    int tid = threadIdx.x, lane = tid & 31, wid = tid >> 5;
    int r0 = blockIdx.x * 64;

    // stage W [64 og][256 k] into swizzled tiles (8 chunks of 16B per thread)
    #pragma unroll
    for (int i = 0; i < 8; i++) {
        int q = tid * 8 + i;              // 2048 chunks
        int row = q >> 5, c32 = q & 31;
        CP_ASYNC16(sb + LNP_W + (c32 >> 2) * YT_STRIDE + swz(row, c32 & 3),
                   g_PwT + row * C_M + c32 * 8);
    }
    CP_COMMIT();

    // LN: 8 rows per warp
    for (int it = 0; it < 8; it++) {
        int rl = wid + it * 8;            // 0..63
        int row = r0 + rl;
        const float4* ap = (const float4*)(act + (size_t)row * C_M + lane * 8);
        float4 x0 = ap[0], x1 = ap[1];
        float s  = x0.x + x0.y + x0.z + x0.w + x1.x + x1.y + x1.z + x1.w;
        float s2 = x0.x*x0.x + x0.y*x0.y + x0.z*x0.z + x0.w*x0.w
                 + x1.x*x1.x + x1.y*x1.y + x1.z*x1.z + x1.w*x1.w;
        #pragma unroll
        for (int o = 16; o > 0; o >>= 1) {
            s  += __shfl_xor_sync(0xffffffffu, s, o);
            s2 += __shfl_xor_sync(0xffffffffu, s2, o);
        }
        float mu = s * (1.0f / C_M);
        float var = s2 * (1.0f / C_M) - mu * mu;
        float rstd = rsqrtf(var + 1e-5f);
        float4 sc0 = *(const float4*)(ln_scale + lane * 8);
        float4 sc1 = *(const float4*)(ln_scale + lane * 8 + 4);
        float4 of0 = *(const float4*)(ln_offset + lane * 8);
        float4 of1 = *(const float4*)(ln_offset + lane * 8 + 4);
        float y[8];
        y[0] = (x0.x - mu) * rstd * sc0.x + of0.x;
        y[1] = (x0.y - mu) * rstd * sc0.y + of0.y;
        y[2] = (x0.z - mu) * rstd * sc0.z + of0.z;
        y[3] = (x0.w - mu) * rstd * sc0.w + of0.w;
        y[4] = (x1.x - mu) * rstd * sc1.x + of1.x;
        y[5] = (x1.y - mu) * rstd * sc1.y + of1.y;
        y[6] = (x1.z - mu) * rstd * sc1.z + of1.z;
        y[7] = (x1.w - mu) * rstd * sc1.w + of1.w;
        float hi[8];
        uint4 vh, vl;
        #pragma unroll
        for (int j = 0; j < 8; j++)
            hi[j] = __half2float(__float2half_rn(y[j]));
        vh.x = pack_h2(y[0], y[1]); vh.y = pack_h2(y[2], y[3]);
        vh.z = pack_h2(y[4], y[5]); vh.w = pack_h2(y[6], y[7]);
        vl.x = pack_h2(y[0]-hi[0], y[1]-hi[1]); vl.y = pack_h2(y[2]-hi[2], y[3]-hi[3]);
        vl.z = pack_h2(y[4]-hi[4], y[5]-hi[5]); vl.w = pack_h2(y[6]-hi[6], y[7]-hi[7]);
        uint32_t off = (lane >> 2) * YT_STRIDE + swz(rl, lane & 3);
        *(uint4*)(smem + LNP_YHI + off) = vh;
        *(uint4*)(smem + LNP_YLO + off) = vl;
    }
    CP_WAIT(0);
    __syncthreads();

    // MMA: warp w: m tile = w&3 (16 rows), n half = w>>2 (32 og)
    int m2 = wid & 3, n32 = wid >> 2;
    uint32_t aoff[2], boff[2][2];
    #pragma unroll
    for (int ks = 0; ks < 2; ks++) {
        aoff[ks] = swz(m2 * 16 + (lane & 15), ks * 2 + (lane >> 4));
        #pragma unroll
        for (int n2 = 0; n2 < 2; n2++)
            boff[n2][ks] = swz(n32 * 32 + n2 * 16 + (lane & 15), ks * 2 + (lane >> 4));
    }
    float acc[4][4];
    #pragma unroll
    for (int a = 0; a < 4; a++)
        #pragma unroll
        for (int c = 0; c < 4; c++) acc[a][c] = 0.f;

    #pragma unroll
    for (int kc = 0; kc < 8; kc++) {
        uint32_t yh = sb + LNP_YHI + kc * YT_STRIDE;
        uint32_t yl = sb + LNP_YLO + kc * YT_STRIDE;
        uint32_t wb = sb + LNP_W   + kc * YT_STRIDE;
        #pragma unroll
        for (int ks = 0; ks < 2; ks++) {
            uint32_t ah[4], al[4], b0[4], b1[4];
            LDSM_X4(ah, yh + aoff[ks]);
            LDSM_X4(al, yl + aoff[ks]);
            LDSM_X4(b0, wb + boff[0][ks]);
            LDSM_X4(b1, wb + boff[1][ks]);
            #pragma unroll
            for (int nt = 0; nt < 4; nt++) {
                uint32_t* bp = (nt < 2) ? b0 : b1;
                MMA_F16(acc[nt], ah, bp[nt & 1], bp[(nt & 1) + 2]);
            }
            #pragma unroll
            for (int nt = 0; nt < 4; nt++) {
                uint32_t* bp = (nt < 2) ? b0 : b1;
                MMA_F16(acc[nt], al, bp[nt & 1], bp[(nt & 1) + 2]);
            }
        }
    }

    // epilogue: v = mask * (acc + bias); write to g_L / g_R
    #pragma unroll
    for (int nt = 0; nt < 4; nt++) {
        int og = n32 * 32 + nt * 8 + (lane & 3) * 2;    // 0..63
        float b0v = n32 ? right_b[og - 32] : left_b[og];
        float b1v = n32 ? right_b[og - 31] : left_b[og + 1];
        #pragma unroll
        for (int h = 0; h < 2; h++) {
            int rg = r0 + m2 * 16 + (lane >> 2) + h * 8;
            float mv = mask[rg];
            int a = rg / N_RES, b = rg % N_RES;
            float2 v = make_float2(mv * (acc[nt][h * 2 + 0] + b0v),
                                   mv * (acc[nt][h * 2 + 1] + b1v));
            float* dst = n32 ? &g_R[(size_t)a * BC + b * 32 + og - 32]
                             : &g_L[(size_t)a * BC + b * 32 + og];
            *(float2*)dst = v;
        }
    }
}

// ------------- Kernel 1b: transpose + split/round to fp16 [bc][a] ----------
__global__ __launch_bounds__(256) void split_tr_kernel()
{
    __shared__ float t[32][65];
    const float* src = blockIdx.z ? g_R : g_L;
    int c0 = blockIdx.x * 64;
    int a0 = blockIdx.y * 32;
    for (int i = threadIdx.x; i < 32 * 64; i += 256) {
        int al = i >> 6, cl = i & 63;
        t[al][cl] = src[(size_t)(a0 + al) * BC + c0 + cl];
    }
    __syncthreads();
    if (blockIdx.z == 0) {
        for (int i = threadIdx.x; i < 64 * 32; i += 256) {
            int cl = i >> 5, al = i & 31;
            float x = t[al][cl];
            __half hi = __float2half_rn(x);
            __half lo = __float2half_rn(x - __half2float(hi));
            size_t o = (size_t)(c0 + cl) * N_SEQ + a0 + al;
            g_Lhi[o] = hi; g_Llo[o] = lo;
        }
    } else {
        for (int i = threadIdx.x; i < 64 * 32; i += 256) {
            int cl = i >> 5, al = i & 31;
            size_t o = (size_t)(c0 + cl) * N_SEQ + a0 + al;
            g_Rh[o] = __float2half_rn(t[al][cl]);
        }
    }
}

// ------ prep: norm recip (0..575) + W split (576..703) + PwT (704) ---------
__global__ __launch_bounds__(256) void prep_kernel(
    const float* __restrict__ mask, const float* __restrict__ W,
    const float* __restrict__ left_w, const float* __restrict__ right_w)
{
    if (blockIdx.x < 576) {
        int m = blockIdx.x * 256 + threadIdx.x;
        int b = m / N_RES, d = m % N_RES;
        float s = 0.f;
        for (int a = 0; a < N_SEQ; a++)
            s += mask[a * N_RES + b] * mask[a * N_RES + d];
        g_ninv[m] = 1.0f / (1e-3f + s);
    } else if (blockIdx.x < 704) {
        __shared__ float t[32][33];
        int bb = blockIdx.x - 576;
        int k0 = (bb & 31) * 32;
        int f0 = (bb >> 5) * 32;
        for (int i = threadIdx.x; i < 1024; i += 256) {
            int r = i >> 5, c = i & 31;
            t[r][c] = W[(size_t)(k0 + r) * C_Z + f0 + c];
        }
        __syncthreads();
        for (int i = threadIdx.x; i < 1024; i += 256) {
            int r = i >> 5, c = i & 31;
            float x = t[c][r];
            __half hi = __float2half_rn(x);
            __half lo = __float2half_rn(x - __half2float(hi));
            size_t o = (size_t)(f0 + r) * KCE + k0 + c;
            g_Wt_hi[o] = hi; g_Wt_lo[o] = lo;
        }
    } else {
        // PwT [64 og][256 k]: og<32 left_w, og>=32 right_w
        for (int i = 0; i < 64; i++) {
            int og = i, k = threadIdx.x;
            float v = (og < 32) ? left_w[k * C_OUT + og]
                                : right_w[k * C_OUT + og - 32];
            g_PwT[og * C_M + k] = __float2half_rn(v);
        }
    }
}

// ============ smem geometry ================================================
#define TILE_B   8192                    /* 128 rows x 64B, XOR-swizzled */
#define G1_STAGE 24576                   /* 3 tiles: Ahi, Alo, Bh */
#define G1_SMEM  73728
#define G2_STAGE 24576                   /* 3 tiles: A, Whi, Wlo */
#define G2_SMEM  73728

// ---------------- Kernel 3: GEMM1 = L^T R (2-term fp16) --------------------
__global__ __launch_bounds__(256, 2) void gemm1_mma()
{
    extern __shared__ __align__(128) char smem[];
    uint32_t sb = smem_u32(smem);
    int tid = threadIdx.x, lane = tid & 31, wid = tid >> 5;
    int i0 = blockIdx.y * 128;     // bc (M)
    int j0 = blockIdx.x * 128;     // de (N)
    int m_base = (wid & 1) * 64, n_base = (wid >> 1) * 32;

    const __half* base[3] = {
        g_Lhi + (size_t)i0 * N_SEQ, g_Llo + (size_t)i0 * N_SEQ,
        g_Rh  + (size_t)j0 * N_SEQ };

    uint32_t soff[2]; int gofs[2];
    #pragma unroll
    for (int i = 0; i < 2; i++) {
        int ch = tid + (i << 8);
        int m = ch >> 2, c = ch & 3;
        soff[i] = swz(m, c);
        gofs[i] = m * N_SEQ + c * 8;
    }

    uint32_t aoff[4][2], boff[2][2];
    #pragma unroll
    for (int mt = 0; mt < 4; mt++)
        #pragma unroll
        for (int ks = 0; ks < 2; ks++)
            aoff[mt][ks] = swz(m_base + mt * 16 + (lane & 15), ks * 2 + (lane >> 4));
    #pragma unroll
    for (int n2 = 0; n2 < 2; n2++)
        #pragma unroll
        for (int ks = 0; ks < 2; ks++)
            boff[n2][ks] = swz(n_base + n2 * 16 + (lane & 15), ks * 2 + (lane >> 4));

    float acc[4][4][4];
    #pragma unroll
    for (int a = 0; a < 4; a++)
        #pragma unroll
        for (int b = 0; b < 4; b++)
            #pragma unroll
            for (int c = 0; c < 4; c++) acc[a][b][c] = 0.f;

    #pragma unroll
    for (int s = 0; s < 2; s++) {
        #pragma unroll
        for (int t = 0; t < 3; t++)
            #pragma unroll
            for (int i = 0; i < 2; i++)
                CP_ASYNC16(sb + s * G1_STAGE + t * TILE_B + soff[i],
                           base[t] + gofs[i] + s * 32);
        CP_COMMIT();
    }

    for (int kt = 0; kt < 16; kt++) {
        CP_WAIT(1);
        __syncthreads();
        if (kt + 2 < 16) {
            uint32_t so = (uint32_t)((kt + 2) % 3) * G1_STAGE;
            #pragma unroll
            for (int t = 0; t < 3; t++)
                #pragma unroll
                for (int i = 0; i < 2; i++)
                    CP_ASYNC16(sb + so + t * TILE_B + soff[i],
                               base[t] + gofs[i] + (kt + 2) * 32);
        }
        CP_COMMIT();
        uint32_t stb = sb + (uint32_t)(kt % 3) * G1_STAGE;
        #pragma unroll
        for (int ks = 0; ks < 2; ks++) {
            uint32_t ah[4][4], al[4][4], bh[2][4];
            #pragma unroll
            for (int mt = 0; mt < 4; mt++) {
                LDSM_X4(ah[mt], stb + aoff[mt][ks]);
                LDSM_X4(al[mt], stb + TILE_B + aoff[mt][ks]);
            }
            #pragma unroll
            for (int n2 = 0; n2 < 2; n2++)
                LDSM_X4(bh[n2], stb + 2 * TILE_B + boff[n2][ks]);
            #pragma unroll
            for (int mt = 0; mt < 4; mt++)
                #pragma unroll
                for (int nt = 0; nt < 4; nt++)
                    MMA_F16(acc[mt][nt], ah[mt], bh[nt >> 1][nt & 1],
                            bh[nt >> 1][(nt & 1) + 2]);
            #pragma unroll
            for (int mt = 0; mt < 4; mt++)
                #pragma unroll
                for (int nt = 0; nt < 4; nt++)
                    MMA_F16(acc[mt][nt], al[mt], bh[nt >> 1][nt & 1],
                            bh[nt >> 1][(nt & 1) + 2]);
        }
    }

    // epilogue: scatter into smem (single fp16, permuted), then coalesced copy
    __syncthreads();
    int g = lane >> 2, tg = lane & 3;
    #pragma unroll
    for (int mt = 0; mt < 4; mt++) {
        #pragma unroll
        for (int h = 0; h < 2; h++) {
            int rr = m_base + mt * 16 + g + h * 8;
            int bl = rr >> 5, c = rr & 31;
            #pragma unroll
            for (int nt = 0; nt < 4; nt++) {
                int q = n_base + nt * 8 + tg * 2;
                int dl = q >> 5, e = q & 31;
                int p = bl * 4 + dl;
                uint32_t off = (uint32_t)(p * 2048 + (c * 32 + e) * 2);
                *(__half2*)(smem + off) = __halves2half2(
                    __float2half_rn(acc[mt][nt][h * 2 + 0]),
                    __float2half_rn(acc[mt][nt][h * 2 + 1]));
            }
        }
    }
    __syncthreads();
    int b0 = blockIdx.y * 4, d0 = blockIdx.x * 4;
    #pragma unroll
    for (int i = 0; i < 8; i++) {
        int qc = tid + 256 * i;
        int p = qc >> 7, off = qc & 127;
        size_t row = (size_t)((b0 + (p >> 2)) * N_RES + d0 + (p & 3)) * KCE + off * 8;
        *(uint4*)(g_iPhi + row) = *(const uint4*)(smem + qc * 16);
    }
}

// ---------------- Kernel 4: GEMM2 = interP @ (Whi+Wlo)^T + b, / norm -------
__global__ __launch_bounds__(256, 2) void gemm2_mma(
    const float* __restrict__ ob, float* __restrict__ out)
{
    extern __shared__ __align__(128) char smem[];
    uint32_t sb = smem_u32(smem);
    int tid = threadIdx.x, lane = tid & 31, wid = tid >> 5;
    int m0 = blockIdx.x * 128;
    int m_base = (wid & 1) * 64, n_base = (wid >> 1) * 32;

    const __half* base[3] = { g_iPhi + (size_t)m0 * KCE, g_Wt_hi, g_Wt_lo };

    uint32_t soff[2]; int gofs[2];
    #pragma unroll
    for (int i = 0; i < 2; i++) {
        int ch = tid + (i << 8);
        int m = ch >> 2, c = ch & 3;
        soff[i] = swz(m, c);
        gofs[i] = m * KCE + c * 8;
    }

    uint32_t aoff[4][2], boff[2][2];
    #pragma unroll
    for (int mt = 0; mt < 4; mt++)
        #pragma unroll
        for (int ks = 0; ks < 2; ks++)
            aoff[mt][ks] = swz(m_base + mt * 16 + (lane & 15), ks * 2 + (lane >> 4));
    #pragma unroll
    for (int n2 = 0; n2 < 2; n2++)
        #pragma unroll
        for (int ks = 0; ks < 2; ks++)
            boff[n2][ks] = swz(n_base + n2 * 16 + (lane & 15), ks * 2 + (lane >> 4));

    float acc[4][4][4];
    #pragma unroll
    for (int a = 0; a < 4; a++)
        #pragma unroll
        for (int b = 0; b < 4; b++)
            #pragma unroll
            for (int c = 0; c < 4; c++) acc[a][b][c] = 0.f;

    #pragma unroll
    for (int s = 0; s < 2; s++) {
        #pragma unroll
        for (int t = 0; t < 3; t++)
            #pragma unroll
            for (int i = 0; i < 2; i++)
                CP_ASYNC16(sb + s * G2_STAGE + t * TILE_B + soff[i],
                           base[t] + gofs[i] + s * 32);
        CP_COMMIT();
    }

    for (int kt = 0; kt < 32; kt++) {
        CP_WAIT(1);
        __syncthreads();
        if (kt + 2 < 32) {
            uint32_t so = (uint32_t)((kt + 2) % 3) * G2_STAGE;
            #pragma unroll
            for (int t = 0; t < 3; t++)
                #pragma unroll
                for (int i = 0; i < 2; i++)
                    CP_ASYNC16(sb + so + t * TILE_B + soff[i],
                               base[t] + gofs[i] + (kt + 2) * 32);
        }
        CP_COMMIT();
        uint32_t stb = sb + (uint32_t)(kt % 3) * G2_STAGE;
        #pragma unroll
        for (int ks = 0; ks < 2; ks++) {
            uint32_t ah[4][4], bh[2][4], bl[2][4];
            #pragma unroll
            for (int mt = 0; mt < 4; mt++)
                LDSM_X4(ah[mt], stb + aoff[mt][ks]);
            #pragma unroll
            for (int n2 = 0; n2 < 2; n2++) {
                LDSM_X4(bh[n2], stb + TILE_B + boff[n2][ks]);
                LDSM_X4(bl[n2], stb + 2 * TILE_B + boff[n2][ks]);
            }
            #pragma unroll
            for (int mt = 0; mt < 4; mt++)
                #pragma unroll
                for (int nt = 0; nt < 4; nt++)
                    MMA_F16(acc[mt][nt], ah[mt], bh[nt >> 1][nt & 1],
                            bh[nt >> 1][(nt & 1) + 2]);
            #pragma unroll
            for (int mt = 0; mt < 4; mt++)
                #pragma unroll
                for (int nt = 0; nt < 4; nt++)
                    MMA_F16(acc[mt][nt], ah[mt], bl[nt >> 1][nt & 1],
                            bl[nt >> 1][(nt & 1) + 2]);
        }
    }

    int g = lane >> 2, tg = lane & 3;
    #pragma unroll
    for (int mt = 0; mt < 4; mt++) {
        #pragma unroll
        for (int h = 0; h < 2; h++) {
            int m = m0 + m_base + mt * 16 + g + h * 8;
            float inv = g_ninv[m];
            #pragma unroll
            for (int nt = 0; nt < 4; nt++) {
                int f = n_base + nt * 8 + tg * 2;
                float2 v;
                v.x = (acc[mt][nt][h * 2 + 0] + ob[f + 0]) * inv;
                v.y = (acc[mt][nt][h * 2 + 1] + ob[f + 1]) * inv;
                *(float2*)&out[(size_t)m * C_Z + f] = v;
            }
        }
    }
}

// ---------------------------------------------------------------------------
extern "C" void kernel_launch(void* const* d_in, const int* in_sizes, int n_in,
                              void* d_out, int out_size)
{
    const float* act       = (const float*)d_in[0];
    const float* mask      = (const float*)d_in[1];
    const float* ln_scale  = (const float*)d_in[2];
    const float* ln_offset = (const float*)d_in[3];
    const float* left_w    = (const float*)d_in[4];
    const float* left_b    = (const float*)d_in[5];
    const float* right_w   = (const float*)d_in[6];
    const float* right_b   = (const float*)d_in[7];
    const float* output_w  = (const float*)d_in[8];
    const float* output_b  = (const float*)d_in[9];
    float* out = (float*)d_out;

    cudaFuncSetAttribute(ln_proj_mma, cudaFuncAttributeMaxDynamicSharedMemorySize, LNP_SMEM);
    cudaFuncSetAttribute(gemm1_mma, cudaFuncAttributeMaxDynamicSharedMemorySize, G1_SMEM);
    cudaFuncSetAttribute(gemm2_mma, cudaFuncAttributeMaxDynamicSharedMemorySize, G2_SMEM);

    // order: prep(1), ln_proj_mma(2), split_tr(3), gemm1(4 = profiler slot), gemm2(5)
    prep_kernel<<<705, 256>>>(mask, output_w, left_w, right_w);
    ln_proj_mma<<<N_SEQ * N_RES / 64, 256, LNP_SMEM>>>(act, mask, ln_scale, ln_offset,
                                                       left_b, right_b);
    split_tr_kernel<<<dim3(BC / 64, N_SEQ / 32, 2), 256>>>();
    gemm1_mma<<<dim3(BC / 128, BC / 128), 256, G1_SMEM>>>();
    gemm2_mma<<<NPAIR / 128, 256, G2_SMEM>>>(output_b, out);
}

// round 12
// speedup vs baseline: 3.4067x; 1.5142x over previous
#include <cuda_runtime.h>
#include <cuda_fp16.h>
#include <math.h>
#include <stdint.h>

#define N_SEQ 512
#define N_RES 384
#define C_M   256
#define C_OUT 32
#define C_Z   128
#define BC    (N_RES * C_OUT)     /* 12288  (b,c) flattened */
#define NPAIR (N_RES * N_RES)     /* 147456 (b,d) pairs     */
#define KCE   (C_OUT * C_OUT)     /* 1024   (c,e) flattened */

// ---------------- scratch (device globals; no allocation allowed) ----------
__device__ float g_L[(size_t)N_SEQ * BC];            // fp32 [a, bc]
__device__ float g_R[(size_t)N_SEQ * BC];            // fp32 [a, de]
__device__ float g_ninv[NPAIR];
// fp16 K-major operands: [bc|de][a]
__device__ __align__(128) __half g_Lh[(size_t)BC * N_SEQ];
__device__ __align__(128) __half g_Rh[(size_t)BC * N_SEQ];
// inter, PERMUTED [(b,d),(c,e)], single fp16
__device__ __align__(128) __half g_iPhi[(size_t)NPAIR * KCE];  // 302 MB
// W transposed + split: [f][ce]
__device__ __align__(128) __half g_Wt_hi[(size_t)C_Z * KCE];
__device__ __align__(128) __half g_Wt_lo[(size_t)C_Z * KCE];
// projection weights, transposed: [og 64][k 256] (og<32 = left, og>=32 = right)
__device__ __align__(128) __half g_PwT[64 * C_M];

// ======================= PTX helpers (baseline sm_80 features) =============
__device__ __forceinline__ uint32_t smem_u32(const void* p) {
    uint32_t a;
    asm("{ .reg .u64 t; cvta.to.shared.u64 t, %1; cvt.u32.u64 %0, t; }"
        : "=r"(a) : "l"(p));
    return a;
}
#define LDSM_X4(r, addr) \
    asm volatile("ldmatrix.sync.aligned.m8n8.x4.shared.b16 {%0,%1,%2,%3}, [%4];" \
                 : "=r"((r)[0]), "=r"((r)[1]), "=r"((r)[2]), "=r"((r)[3]) \
                 : "r"(addr))
#define MMA_F16(d, a, b0, b1) \
    asm volatile("mma.sync.aligned.m16n8k16.row.col.f32.f16.f16.f32 " \
                 "{%0,%1,%2,%3},{%4,%5,%6,%7},{%8,%9},{%0,%1,%2,%3};" \
                 : "+f"((d)[0]), "+f"((d)[1]), "+f"((d)[2]), "+f"((d)[3]) \
                 : "r"((a)[0]), "r"((a)[1]), "r"((a)[2]), "r"((a)[3]), \
                   "r"(b0), "r"(b1))
#define CP_ASYNC16(dst, src) \
    asm volatile("cp.async.cg.shared.global [%0], [%1], 16;" \
                 :: "r"(dst), "l"(src) : "memory")
#define CP_COMMIT() asm volatile("cp.async.commit_group;" ::: "memory")
#define CP_WAIT(n)  asm volatile("cp.async.wait_group %0;" :: "n"(n) : "memory")

// XOR swizzle: chunk (m, c) of a [<=128 rows x 4 chunks-of-16B] tile.
__device__ __forceinline__ uint32_t swz(int m, int c) {
    int L = m * 4 + c;
    return (uint32_t)(((L >> 3) << 7) + ((((L & 7) ^ ((L >> 3) & 7))) << 4));
}

__device__ __forceinline__ uint32_t pack_h2(float a, float b) {
    __half2 p = __halves2half2(__float2half_rn(a), __float2half_rn(b));
    return *(uint32_t*)&p;
}

// ---------------- Kernel 1: LN + projection via tensor cores ---------------
#define YT_STRIDE 4112           /* 257*16: padded tile stride */
#define LNP_YHI 0
#define LNP_YLO 32896            /* 8*4112 */
#define LNP_W   65792
#define LNP_SMEM 98688

__global__ __launch_bounds__(256, 2) void ln_proj_mma(
    const float* __restrict__ act, const float* __restrict__ mask,
    const float* __restrict__ ln_scale, const float* __restrict__ ln_offset,
    const float* __restrict__ left_b, const float* __restrict__ right_b)
{
    extern __shared__ __align__(128) char smem[];
    uint32_t sb = smem_u32(smem);
    int tid = threadIdx.x, lane = tid & 31, wid = tid >> 5;
    int r0 = blockIdx.x * 64;

    #pragma unroll
    for (int i = 0; i < 8; i++) {
        int q = tid * 8 + i;
        int row = q >> 5, c32 = q & 31;
        CP_ASYNC16(sb + LNP_W + (c32 >> 2) * YT_STRIDE + swz(row, c32 & 3),
                   g_PwT + row * C_M + c32 * 8);
    }
    CP_COMMIT();

    for (int it = 0; it < 8; it++) {
        int rl = wid + it * 8;
        int row = r0 + rl;
        const float4* ap = (const float4*)(act + (size_t)row * C_M + lane * 8);
        float4 x0 = ap[0], x1 = ap[1];
        float s  = x0.x + x0.y + x0.z + x0.w + x1.x + x1.y + x1.z + x1.w;
        float s2 = x0.x*x0.x + x0.y*x0.y + x0.z*x0.z + x0.w*x0.w
                 + x1.x*x1.x + x1.y*x1.y + x1.z*x1.z + x1.w*x1.w;
        #pragma unroll
        for (int o = 16; o > 0; o >>= 1) {
            s  += __shfl_xor_sync(0xffffffffu, s, o);
            s2 += __shfl_xor_sync(0xffffffffu, s2, o);
        }
        float mu = s * (1.0f / C_M);
        float var = s2 * (1.0f / C_M) - mu * mu;
        float rstd = rsqrtf(var + 1e-5f);
        float4 sc0 = *(const float4*)(ln_scale + lane * 8);
        float4 sc1 = *(const float4*)(ln_scale + lane * 8 + 4);
        float4 of0 = *(const float4*)(ln_offset + lane * 8);
        float4 of1 = *(const float4*)(ln_offset + lane * 8 + 4);
        float y[8];
        y[0] = (x0.x - mu) * rstd * sc0.x + of0.x;
        y[1] = (x0.y - mu) * rstd * sc0.y + of0.y;
        y[2] = (x0.z - mu) * rstd * sc0.z + of0.z;
        y[3] = (x0.w - mu) * rstd * sc0.w + of0.w;
        y[4] = (x1.x - mu) * rstd * sc1.x + of1.x;
        y[5] = (x1.y - mu) * rstd * sc1.y + of1.y;
        y[6] = (x1.z - mu) * rstd * sc1.z + of1.z;
        y[7] = (x1.w - mu) * rstd * sc1.w + of1.w;
        float hi[8];
        uint4 vh, vl;
        #pragma unroll
        for (int j = 0; j < 8; j++)
            hi[j] = __half2float(__float2half_rn(y[j]));
        vh.x = pack_h2(y[0], y[1]); vh.y = pack_h2(y[2], y[3]);
        vh.z = pack_h2(y[4], y[5]); vh.w = pack_h2(y[6], y[7]);
        vl.x = pack_h2(y[0]-hi[0], y[1]-hi[1]); vl.y = pack_h2(y[2]-hi[2], y[3]-hi[3]);
        vl.z = pack_h2(y[4]-hi[4], y[5]-hi[5]); vl.w = pack_h2(y[6]-hi[6], y[7]-hi[7]);
        uint32_t off = (lane >> 2) * YT_STRIDE + swz(rl, lane & 3);
        *(uint4*)(smem + LNP_YHI + off) = vh;
        *(uint4*)(smem + LNP_YLO + off) = vl;
    }
    CP_WAIT(0);
    __syncthreads();

    int m2 = wid & 3, n32 = wid >> 2;
    uint32_t aoff[2], boff[2][2];
    #pragma unroll
    for (int ks = 0; ks < 2; ks++) {
        aoff[ks] = swz(m2 * 16 + (lane & 15), ks * 2 + (lane >> 4));
        #pragma unroll
        for (int n2 = 0; n2 < 2; n2++)
            boff[n2][ks] = swz(n32 * 32 + n2 * 16 + (lane & 15), ks * 2 + (lane >> 4));
    }
    float acc[4][4];
    #pragma unroll
    for (int a = 0; a < 4; a++)
        #pragma unroll
        for (int c = 0; c < 4; c++) acc[a][c] = 0.f;

    #pragma unroll
    for (int kc = 0; kc < 8; kc++) {
        uint32_t yh = sb + LNP_YHI + kc * YT_STRIDE;
        uint32_t yl = sb + LNP_YLO + kc * YT_STRIDE;
        uint32_t wb = sb + LNP_W   + kc * YT_STRIDE;
        #pragma unroll
        for (int ks = 0; ks < 2; ks++) {
            uint32_t ah[4], al[4], b0[4], b1[4];
            LDSM_X4(ah, yh + aoff[ks]);
            LDSM_X4(al, yl + aoff[ks]);
            LDSM_X4(b0, wb + boff[0][ks]);
            LDSM_X4(b1, wb + boff[1][ks]);
            #pragma unroll
            for (int nt = 0; nt < 4; nt++) {
                uint32_t* bp = (nt < 2) ? b0 : b1;
                MMA_F16(acc[nt], ah, bp[nt & 1], bp[(nt & 1) + 2]);
            }
            #pragma unroll
            for (int nt = 0; nt < 4; nt++) {
                uint32_t* bp = (nt < 2) ? b0 : b1;
                MMA_F16(acc[nt], al, bp[nt & 1], bp[(nt & 1) + 2]);
            }
        }
    }

    #pragma unroll
    for (int nt = 0; nt < 4; nt++) {
        int og = n32 * 32 + nt * 8 + (lane & 3) * 2;
        float b0v = n32 ? right_b[og - 32] : left_b[og];
        float b1v = n32 ? right_b[og - 31] : left_b[og + 1];
        #pragma unroll
        for (int h = 0; h < 2; h++) {
            int rg = r0 + m2 * 16 + (lane >> 2) + h * 8;
            float mv = mask[rg];
            int a = rg / N_RES, b = rg % N_RES;
            float2 v = make_float2(mv * (acc[nt][h * 2 + 0] + b0v),
                                   mv * (acc[nt][h * 2 + 1] + b1v));
            float* dst = n32 ? &g_R[(size_t)a * BC + b * 32 + og - 32]
                             : &g_L[(size_t)a * BC + b * 32 + og];
            *(float2*)dst = v;
        }
    }
}

// ------------- Kernel 1b: transpose + round to single fp16 [bc][a] ---------
__global__ __launch_bounds__(256) void split_tr_kernel()
{
    __shared__ float t[32][65];
    const float* src = blockIdx.z ? g_R : g_L;
    __half* dst = blockIdx.z ? g_Rh : g_Lh;
    int c0 = blockIdx.x * 64;
    int a0 = blockIdx.y * 32;
    for (int i = threadIdx.x; i < 32 * 64; i += 256) {
        int al = i >> 6, cl = i & 63;
        t[al][cl] = src[(size_t)(a0 + al) * BC + c0 + cl];
    }
    __syncthreads();
    for (int i = threadIdx.x; i < 64 * 32; i += 256) {
        int cl = i >> 5, al = i & 31;
        dst[(size_t)(c0 + cl) * N_SEQ + a0 + al] = __float2half_rn(t[al][cl]);
    }
}

// ------ prep: norm recip (0..575) + W split (576..703) + PwT (704) ---------
__global__ __launch_bounds__(256) void prep_kernel(
    const float* __restrict__ mask, const float* __restrict__ W,
    const float* __restrict__ left_w, const float* __restrict__ right_w)
{
    if (blockIdx.x < 576) {
        int m = blockIdx.x * 256 + threadIdx.x;
        int b = m / N_RES, d = m % N_RES;
        float s = 0.f;
        for (int a = 0; a < N_SEQ; a++)
            s += mask[a * N_RES + b] * mask[a * N_RES + d];
        g_ninv[m] = 1.0f / (1e-3f + s);
    } else if (blockIdx.x < 704) {
        __shared__ float t[32][33];
        int bb = blockIdx.x - 576;
        int k0 = (bb & 31) * 32;
        int f0 = (bb >> 5) * 32;
        for (int i = threadIdx.x; i < 1024; i += 256) {
            int r = i >> 5, c = i & 31;
            t[r][c] = W[(size_t)(k0 + r) * C_Z + f0 + c];
        }
        __syncthreads();
        for (int i = threadIdx.x; i < 1024; i += 256) {
            int r = i >> 5, c = i & 31;
            float x = t[c][r];
            __half hi = __float2half_rn(x);
            __half lo = __float2half_rn(x - __half2float(hi));
            size_t o = (size_t)(f0 + r) * KCE + k0 + c;
            g_Wt_hi[o] = hi; g_Wt_lo[o] = lo;
        }
    } else {
        for (int i = 0; i < 64; i++) {
            int og = i, k = threadIdx.x;
            float v = (og < 32) ? left_w[k * C_OUT + og]
                                : right_w[k * C_OUT + og - 32];
            g_PwT[og * C_M + k] = __float2half_rn(v);
        }
    }
}

// ============ smem geometry ================================================
#define TILE_B   8192                    /* 128 rows x 64B, XOR-swizzled */
#define G1_STAGE 16384                   /* 2 tiles: Lh, Rh */
#define G1_SMEM  49152                   /* 3 stages; epilogue reuses 32KB */
#define G2_STAGE 24576                   /* 3 tiles: A, Whi, Wlo */
#define G2_SMEM  73728

// ---------------- Kernel 3: GEMM1 = L^T R (single-term fp16) ---------------
__global__ __launch_bounds__(256, 2) void gemm1_mma()
{
    extern __shared__ __align__(128) char smem[];
    uint32_t sb = smem_u32(smem);
    int tid = threadIdx.x, lane = tid & 31, wid = tid >> 5;
    int i0 = blockIdx.y * 128;     // bc (M)
    int j0 = blockIdx.x * 128;     // de (N)
    int m_base = (wid & 1) * 64, n_base = (wid >> 1) * 32;

    const __half* base[2] = {
        g_Lh + (size_t)i0 * N_SEQ, g_Rh + (size_t)j0 * N_SEQ };

    uint32_t soff[2]; int gofs[2];
    #pragma unroll
    for (int i = 0; i < 2; i++) {
        int ch = tid + (i << 8);
        int m = ch >> 2, c = ch & 3;
        soff[i] = swz(m, c);
        gofs[i] = m * N_SEQ + c * 8;
    }

    uint32_t aoff[4][2], boff[2][2];
    #pragma unroll
    for (int mt = 0; mt < 4; mt++)
        #pragma unroll
        for (int ks = 0; ks < 2; ks++)
            aoff[mt][ks] = swz(m_base + mt * 16 + (lane & 15), ks * 2 + (lane >> 4));
    #pragma unroll
    for (int n2 = 0; n2 < 2; n2++)
        #pragma unroll
        for (int ks = 0; ks < 2; ks++)
            boff[n2][ks] = swz(n_base + n2 * 16 + (lane & 15), ks * 2 + (lane >> 4));

    float acc[4][4][4];
    #pragma unroll
    for (int a = 0; a < 4; a++)
        #pragma unroll
        for (int b = 0; b < 4; b++)
            #pragma unroll
            for (int c = 0; c < 4; c++) acc[a][b][c] = 0.f;

    #pragma unroll
    for (int s = 0; s < 2; s++) {
        #pragma unroll
        for (int t = 0; t < 2; t++)
            #pragma unroll
            for (int i = 0; i < 2; i++)
                CP_ASYNC16(sb + s * G1_STAGE + t * TILE_B + soff[i],
                           base[t] + gofs[i] + s * 32);
        CP_COMMIT();
    }

    for (int kt = 0; kt < 16; kt++) {
        CP_WAIT(1);
        __syncthreads();
        if (kt + 2 < 16) {
            uint32_t so = (uint32_t)((kt + 2) % 3) * G1_STAGE;
            #pragma unroll
            for (int t = 0; t < 2; t++)
                #pragma unroll
                for (int i = 0; i < 2; i++)
                    CP_ASYNC16(sb + so + t * TILE_B + soff[i],
                               base[t] + gofs[i] + (kt + 2) * 32);
        }
        CP_COMMIT();
        uint32_t stb = sb + (uint32_t)(kt % 3) * G1_STAGE;
        #pragma unroll
        for (int ks = 0; ks < 2; ks++) {
            uint32_t ah[4][4], bh[2][4];
            #pragma unroll
            for (int mt = 0; mt < 4; mt++)
                LDSM_X4(ah[mt], stb + aoff[mt][ks]);
            #pragma unroll
            for (int n2 = 0; n2 < 2; n2++)
                LDSM_X4(bh[n2], stb + TILE_B + boff[n2][ks]);
            #pragma unroll
            for (int mt = 0; mt < 4; mt++)
                #pragma unroll
                for (int nt = 0; nt < 4; nt++)
                    MMA_F16(acc[mt][nt], ah[mt], bh[nt >> 1][nt & 1],
                            bh[nt >> 1][(nt & 1) + 2]);
        }
    }

    // epilogue: scatter into smem (single fp16, permuted), then coalesced copy
    __syncthreads();
    int g = lane >> 2, tg = lane & 3;
    #pragma unroll
    for (int mt = 0; mt < 4; mt++) {
        #pragma unroll
        for (int h = 0; h < 2; h++) {
            int rr = m_base + mt * 16 + g + h * 8;
            int bl = rr >> 5, c = rr & 31;
            #pragma unroll
            for (int nt = 0; nt < 4; nt++) {
                int q = n_base + nt * 8 + tg * 2;
                int dl = q >> 5, e = q & 31;
                int p = bl * 4 + dl;
                uint32_t off = (uint32_t)(p * 2048 + (c * 32 + e) * 2);
                *(__half2*)(smem + off) = __halves2half2(
                    __float2half_rn(acc[mt][nt][h * 2 + 0]),
                    __float2half_rn(acc[mt][nt][h * 2 + 1]));
            }
        }
    }
    __syncthreads();
    int b0 = blockIdx.y * 4, d0 = blockIdx.x * 4;
    #pragma unroll
    for (int i = 0; i < 8; i++) {
        int qc = tid + 256 * i;
        int p = qc >> 7, off = qc & 127;
        size_t row = (size_t)((b0 + (p >> 2)) * N_RES + d0 + (p & 3)) * KCE + off * 8;
        *(uint4*)(g_iPhi + row) = *(const uint4*)(smem + qc * 16);
    }
}

// ---------------- Kernel 4: GEMM2 = interP @ (Whi+Wlo)^T + b, / norm -------
__global__ __launch_bounds__(256, 2) void gemm2_mma(
    const float* __restrict__ ob, float* __restrict__ out)
{
    extern __shared__ __align__(128) char smem[];
    uint32_t sb = smem_u32(smem);
    int tid = threadIdx.x, lane = tid & 31, wid = tid >> 5;
    int m0 = blockIdx.x * 128;
    int m_base = (wid & 1) * 64, n_base = (wid >> 1) * 32;

    const __half* base[3] = { g_iPhi + (size_t)m0 * KCE, g_Wt_hi, g_Wt_lo };

    uint32_t soff[2]; int gofs[2];
    #pragma unroll
    for (int i = 0; i < 2; i++) {
        int ch = tid + (i << 8);
        int m = ch >> 2, c = ch & 3;
        soff[i] = swz(m, c);
        gofs[i] = m * KCE + c * 8;
    }

    uint32_t aoff[4][2], boff[2][2];
    #pragma unroll
    for (int mt = 0; mt < 4; mt++)
        #pragma unroll
        for (int ks = 0; ks < 2; ks++)
            aoff[mt][ks] = swz(m_base + mt * 16 + (lane & 15), ks * 2 + (lane >> 4));
    #pragma unroll
    for (int n2 = 0; n2 < 2; n2++)
        #pragma unroll
        for (int ks = 0; ks < 2; ks++)
            boff[n2][ks] = swz(n_base + n2 * 16 + (lane & 15), ks * 2 + (lane >> 4));

    float acc[4][4][4];
    #pragma unroll
    for (int a = 0; a < 4; a++)
        #pragma unroll
        for (int b = 0; b < 4; b++)
            #pragma unroll
            for (int c = 0; c < 4; c++) acc[a][b][c] = 0.f;

    #pragma unroll
    for (int s = 0; s < 2; s++) {
        #pragma unroll
        for (int t = 0; t < 3; t++)
            #pragma unroll
            for (int i = 0; i < 2; i++)
                CP_ASYNC16(sb + s * G2_STAGE + t * TILE_B + soff[i],
                           base[t] + gofs[i] + s * 32);
        CP_COMMIT();
    }

    for (int kt = 0; kt < 32; kt++) {
        CP_WAIT(1);
        __syncthreads();
        if (kt + 2 < 32) {
            uint32_t so = (uint32_t)((kt + 2) % 3) * G2_STAGE;
            #pragma unroll
            for (int t = 0; t < 3; t++)
                #pragma unroll
                for (int i = 0; i < 2; i++)
                    CP_ASYNC16(sb + so + t * TILE_B + soff[i],
                               base[t] + gofs[i] + (kt + 2) * 32);
        }
        CP_COMMIT();
        uint32_t stb = sb + (uint32_t)(kt % 3) * G2_STAGE;
        #pragma unroll
        for (int ks = 0; ks < 2; ks++) {
            uint32_t ah[4][4], bh[2][4], bl[2][4];
            #pragma unroll
            for (int mt = 0; mt < 4; mt++)
                LDSM_X4(ah[mt], stb + aoff[mt][ks]);
            #pragma unroll
            for (int n2 = 0; n2 < 2; n2++) {
                LDSM_X4(bh[n2], stb + TILE_B + boff[n2][ks]);
                LDSM_X4(bl[n2], stb + 2 * TILE_B + boff[n2][ks]);
            }
            #pragma unroll
            for (int mt = 0; mt < 4; mt++)
                #pragma unroll
                for (int nt = 0; nt < 4; nt++)
                    MMA_F16(acc[mt][nt], ah[mt], bh[nt >> 1][nt & 1],
                            bh[nt >> 1][(nt & 1) + 2]);
            #pragma unroll
            for (int mt = 0; mt < 4; mt++)
                #pragma unroll
                for (int nt = 0; nt < 4; nt++)
                    MMA_F16(acc[mt][nt], ah[mt], bl[nt >> 1][nt & 1],
                            bl[nt >> 1][(nt & 1) + 2]);
        }
    }

    int g = lane >> 2, tg = lane & 3;
    #pragma unroll
    for (int mt = 0; mt < 4; mt++) {
        #pragma unroll
        for (int h = 0; h < 2; h++) {
            int m = m0 + m_base + mt * 16 + g + h * 8;
            float inv = g_ninv[m];
            #pragma unroll
            for (int nt = 0; nt < 4; nt++) {
                int f = n_base + nt * 8 + tg * 2;
                float2 v;
                v.x = (acc[mt][nt][h * 2 + 0] + ob[f + 0]) * inv;
                v.y = (acc[mt][nt][h * 2 + 1] + ob[f + 1]) * inv;
                *(float2*)&out[(size_t)m * C_Z + f] = v;
            }
        }
    }
}

// ---------------------------------------------------------------------------
extern "C" void kernel_launch(void* const* d_in, const int* in_sizes, int n_in,
                              void* d_out, int out_size)
{
    const float* act       = (const float*)d_in[0];
    const float* mask      = (const float*)d_in[1];
    const float* ln_scale  = (const float*)d_in[2];
    const float* ln_offset = (const float*)d_in[3];
    const float* left_w    = (const float*)d_in[4];
    const float* left_b    = (const float*)d_in[5];
    const float* right_w   = (const float*)d_in[6];
    const float* right_b   = (const float*)d_in[7];
    const float* output_w  = (const float*)d_in[8];
    const float* output_b  = (const float*)d_in[9];
    float* out = (float*)d_out;

    cudaFuncSetAttribute(ln_proj_mma, cudaFuncAttributeMaxDynamicSharedMemorySize, LNP_SMEM);
    cudaFuncSetAttribute(gemm1_mma, cudaFuncAttributeMaxDynamicSharedMemorySize, G1_SMEM);
    cudaFuncSetAttribute(gemm2_mma, cudaFuncAttributeMaxDynamicSharedMemorySize, G2_SMEM);

    // order: prep(1), ln_proj_mma(2), split_tr(3), gemm1(4 = profiler slot), gemm2(5)
    prep_kernel<<<705, 256>>>(mask, output_w, left_w, right_w);
    ln_proj_mma<<<N_SEQ * N_RES / 64, 256, LNP_SMEM>>>(act, mask, ln_scale, ln_offset,
                                                       left_b, right_b);
    split_tr_kernel<<<dim3(BC / 64, N_SEQ / 32, 2), 256>>>();
    gemm1_mma<<<dim3(BC / 128, BC / 128), 256, G1_SMEM>>>();
    gemm2_mma<<<NPAIR / 128, 256, G2_SMEM>>>(output_b, out);
}

// round 13
// speedup vs baseline: 3.9910x; 1.1715x over previous
#include <cuda_runtime.h>
#include <cuda_fp16.h>
#include <math.h>
#include <stdint.h>

#define N_SEQ 512
#define N_RES 384
#define C_M   256
#define C_OUT 32
#define C_Z   128
#define BC    (N_RES * C_OUT)     /* 12288  (b,c) flattened */
#define NPAIR (N_RES * N_RES)     /* 147456 (b,d) pairs     */
#define KCE   (C_OUT * C_OUT)     /* 1024   (c,e) flattened */

// ---------------- scratch (device globals; no allocation allowed) ----------
__device__ float g_ninv[NPAIR];
// fp16 K-major operands: [bc|de][a]  (written directly by ln_proj_mma)
__device__ __align__(128) __half g_Lh[(size_t)BC * N_SEQ];
__device__ __align__(128) __half g_Rh[(size_t)BC * N_SEQ];
// inter, PERMUTED [(b,d),(c,e)], single fp16
__device__ __align__(128) __half g_iPhi[(size_t)NPAIR * KCE];  // 302 MB
// W transposed: [f][ce], single fp16
__device__ __align__(128) __half g_Wt[(size_t)C_Z * KCE];
// projection weights, transposed: [og 64][k 256] (og<32 = left, og>=32 = right)
__device__ __align__(128) __half g_PwT[64 * C_M];

// ======================= PTX helpers (baseline sm_80 features) =============
__device__ __forceinline__ uint32_t smem_u32(const void* p) {
    uint32_t a;
    asm("{ .reg .u64 t; cvta.to.shared.u64 t, %1; cvt.u32.u64 %0, t; }"
        : "=r"(a) : "l"(p));
    return a;
}
#define LDSM_X4(r, addr) \
    asm volatile("ldmatrix.sync.aligned.m8n8.x4.shared.b16 {%0,%1,%2,%3}, [%4];" \
                 : "=r"((r)[0]), "=r"((r)[1]), "=r"((r)[2]), "=r"((r)[3]) \
                 : "r"(addr))
#define MMA_F16(d, a, b0, b1) \
    asm volatile("mma.sync.aligned.m16n8k16.row.col.f32.f16.f16.f32 " \
                 "{%0,%1,%2,%3},{%4,%5,%6,%7},{%8,%9},{%0,%1,%2,%3};" \
                 : "+f"((d)[0]), "+f"((d)[1]), "+f"((d)[2]), "+f"((d)[3]) \
                 : "r"((a)[0]), "r"((a)[1]), "r"((a)[2]), "r"((a)[3]), \
                   "r"(b0), "r"(b1))
#define CP_ASYNC16(dst, src) \
    asm volatile("cp.async.cg.shared.global [%0], [%1], 16;" \
                 :: "r"(dst), "l"(src) : "memory")
#define CP_COMMIT() asm volatile("cp.async.commit_group;" ::: "memory")
#define CP_WAIT(n)  asm volatile("cp.async.wait_group %0;" :: "n"(n) : "memory")

// XOR swizzle: chunk (m, c) of a [<=128 rows x 4 chunks-of-16B] tile.
__device__ __forceinline__ uint32_t swz(int m, int c) {
    int L = m * 4 + c;
    return (uint32_t)(((L >> 3) << 7) + ((((L & 7) ^ ((L >> 3) & 7))) << 4));
}

__device__ __forceinline__ uint32_t pack_h2(float a, float b) {
    __half2 p = __halves2half2(__float2half_rn(a), __float2half_rn(b));
    return *(uint32_t*)&p;
}

// ---------------- Kernel 1: LN + projection via tensor cores ---------------
// b-major blocks: one b, 64 consecutive a per CTA. Epilogue writes g_Lh/g_Rh
// DIRECTLY in transposed K-major [bc][a] layout (a contiguous for fixed b,og).
#define YT_STRIDE 4112           /* 257*16: padded tile stride */
#define LNP_YHI 0
#define LNP_YLO 32896            /* 8*4112 */
#define LNP_W   65792
#define LNP_SMEM 98688

__global__ __launch_bounds__(256, 2) void ln_proj_mma(
    const float* __restrict__ act, const float* __restrict__ mask,
    const float* __restrict__ ln_scale, const float* __restrict__ ln_offset,
    const float* __restrict__ left_b, const float* __restrict__ right_b)
{
    extern __shared__ __align__(128) char smem[];
    uint32_t sb = smem_u32(smem);
    int tid = threadIdx.x, lane = tid & 31, wid = tid >> 5;
    int b  = blockIdx.x % N_RES;
    int a0 = (blockIdx.x / N_RES) * 64;

    #pragma unroll
    for (int i = 0; i < 8; i++) {
        int q = tid * 8 + i;
        int row = q >> 5, c32 = q & 31;
        CP_ASYNC16(sb + LNP_W + (c32 >> 2) * YT_STRIDE + swz(row, c32 & 3),
                   g_PwT + row * C_M + c32 * 8);
    }
    CP_COMMIT();

    for (int it = 0; it < 8; it++) {
        int rl = wid + it * 8;                 // 0..63 : a = a0 + rl
        size_t row = (size_t)(a0 + rl) * N_RES + b;
        const float4* ap = (const float4*)(act + row * C_M + lane * 8);
        float4 x0 = ap[0], x1 = ap[1];
        float s  = x0.x + x0.y + x0.z + x0.w + x1.x + x1.y + x1.z + x1.w;
        float s2 = x0.x*x0.x + x0.y*x0.y + x0.z*x0.z + x0.w*x0.w
                 + x1.x*x1.x + x1.y*x1.y + x1.z*x1.z + x1.w*x1.w;
        #pragma unroll
        for (int o = 16; o > 0; o >>= 1) {
            s  += __shfl_xor_sync(0xffffffffu, s, o);
            s2 += __shfl_xor_sync(0xffffffffu, s2, o);
        }
        float mu = s * (1.0f / C_M);
        float var = s2 * (1.0f / C_M) - mu * mu;
        float rstd = rsqrtf(var + 1e-5f);
        float4 sc0 = *(const float4*)(ln_scale + lane * 8);
        float4 sc1 = *(const float4*)(ln_scale + lane * 8 + 4);
        float4 of0 = *(const float4*)(ln_offset + lane * 8);
        float4 of1 = *(const float4*)(ln_offset + lane * 8 + 4);
        float y[8];
        y[0] = (x0.x - mu) * rstd * sc0.x + of0.x;
        y[1] = (x0.y - mu) * rstd * sc0.y + of0.y;
        y[2] = (x0.z - mu) * rstd * sc0.z + of0.z;
        y[3] = (x0.w - mu) * rstd * sc0.w + of0.w;
        y[4] = (x1.x - mu) * rstd * sc1.x + of1.x;
        y[5] = (x1.y - mu) * rstd * sc1.y + of1.y;
        y[6] = (x1.z - mu) * rstd * sc1.z + of1.z;
        y[7] = (x1.w - mu) * rstd * sc1.w + of1.w;
        float hi[8];
        uint4 vh, vl;
        #pragma unroll
        for (int j = 0; j < 8; j++)
            hi[j] = __half2float(__float2half_rn(y[j]));
        vh.x = pack_h2(y[0], y[1]); vh.y = pack_h2(y[2], y[3]);
        vh.z = pack_h2(y[4], y[5]); vh.w = pack_h2(y[6], y[7]);
        vl.x = pack_h2(y[0]-hi[0], y[1]-hi[1]); vl.y = pack_h2(y[2]-hi[2], y[3]-hi[3]);
        vl.z = pack_h2(y[4]-hi[4], y[5]-hi[5]); vl.w = pack_h2(y[6]-hi[6], y[7]-hi[7]);
        uint32_t off = (lane >> 2) * YT_STRIDE + swz(rl, lane & 3);
        *(uint4*)(smem + LNP_YHI + off) = vh;
        *(uint4*)(smem + LNP_YLO + off) = vl;
    }
    CP_WAIT(0);
    __syncthreads();

    int m2 = wid & 3, n32 = wid >> 2;
    uint32_t aoff[2], boff[2][2];
    #pragma unroll
    for (int ks = 0; ks < 2; ks++) {
        aoff[ks] = swz(m2 * 16 + (lane & 15), ks * 2 + (lane >> 4));
        #pragma unroll
        for (int n2 = 0; n2 < 2; n2++)
            boff[n2][ks] = swz(n32 * 32 + n2 * 16 + (lane & 15), ks * 2 + (lane >> 4));
    }
    float acc[4][4];
    #pragma unroll
    for (int a = 0; a < 4; a++)
        #pragma unroll
        for (int c = 0; c < 4; c++) acc[a][c] = 0.f;

    #pragma unroll
    for (int kc = 0; kc < 8; kc++) {
        uint32_t yh = sb + LNP_YHI + kc * YT_STRIDE;
        uint32_t yl = sb + LNP_YLO + kc * YT_STRIDE;
        uint32_t wb = sb + LNP_W   + kc * YT_STRIDE;
        #pragma unroll
        for (int ks = 0; ks < 2; ks++) {
            uint32_t ah[4], al[4], b0[4], b1[4];
            LDSM_X4(ah, yh + aoff[ks]);
            LDSM_X4(al, yl + aoff[ks]);
            LDSM_X4(b0, wb + boff[0][ks]);
            LDSM_X4(b1, wb + boff[1][ks]);
            #pragma unroll
            for (int nt = 0; nt < 4; nt++) {
                uint32_t* bp = (nt < 2) ? b0 : b1;
                MMA_F16(acc[nt], ah, bp[nt & 1], bp[(nt & 1) + 2]);
            }
            #pragma unroll
            for (int nt = 0; nt < 4; nt++) {
                uint32_t* bp = (nt < 2) ? b0 : b1;
                MMA_F16(acc[nt], al, bp[nt & 1], bp[(nt & 1) + 2]);
            }
        }
    }

    // epilogue: v = mask * (acc + bias); write TRANSPOSED fp16 to g_Lh / g_Rh
    __half* dstb = n32 ? g_Rh : g_Lh;
    #pragma unroll
    for (int nt = 0; nt < 4; nt++) {
        int og = (n32 ? (n32 * 32) : 0) + nt * 8 + (lane & 3) * 2 - (n32 ? 32 : 0);
        // og in [0,32) local to left/right
        int ogl = nt * 8 + (lane & 3) * 2;
        float b0v = n32 ? right_b[ogl] : left_b[ogl];
        float b1v = n32 ? right_b[ogl + 1] : left_b[ogl + 1];
        (void)og;
        #pragma unroll
        for (int h = 0; h < 2; h++) {
            int a = a0 + m2 * 16 + (lane >> 2) + h * 8;
            float mv = mask[(size_t)a * N_RES + b];
            float vx = mv * (acc[nt][h * 2 + 0] + b0v);
            float vy = mv * (acc[nt][h * 2 + 1] + b1v);
            dstb[(size_t)(b * 32 + ogl)     * N_SEQ + a] = __float2half_rn(vx);
            dstb[(size_t)(b * 32 + ogl + 1) * N_SEQ + a] = __float2half_rn(vy);
        }
    }
}

// ------ prep: norm recip (0..575) + W transpose (576..703) + PwT (704) -----
__global__ __launch_bounds__(256) void prep_kernel(
    const float* __restrict__ mask, const float* __restrict__ W,
    const float* __restrict__ left_w, const float* __restrict__ right_w)
{
    if (blockIdx.x < 576) {
        int m = blockIdx.x * 256 + threadIdx.x;
        int b = m / N_RES, d = m % N_RES;
        float s = 0.f;
        for (int a = 0; a < N_SEQ; a++)
            s += mask[a * N_RES + b] * mask[a * N_RES + d];
        g_ninv[m] = 1.0f / (1e-3f + s);
    } else if (blockIdx.x < 704) {
        __shared__ float t[32][33];
        int bb = blockIdx.x - 576;
        int k0 = (bb & 31) * 32;
        int f0 = (bb >> 5) * 32;
        for (int i = threadIdx.x; i < 1024; i += 256) {
            int r = i >> 5, c = i & 31;
            t[r][c] = W[(size_t)(k0 + r) * C_Z + f0 + c];
        }
        __syncthreads();
        for (int i = threadIdx.x; i < 1024; i += 256) {
            int r = i >> 5, c = i & 31;
            g_Wt[(size_t)(f0 + r) * KCE + k0 + c] = __float2half_rn(t[c][r]);
        }
    } else {
        for (int i = 0; i < 64; i++) {
            int og = i, k = threadIdx.x;
            float v = (og < 32) ? left_w[k * C_OUT + og]
                                : right_w[k * C_OUT + og - 32];
            g_PwT[og * C_M + k] = __float2half_rn(v);
        }
    }
}

// ============ smem geometry ================================================
#define TILE_B   8192                    /* 128 rows x 64B, XOR-swizzled */
#define G_STAGE  16384                   /* 2 tiles */
#define G_SMEM   49152                   /* 3 stages; gemm1 epi reuses 32KB */

// ---------------- Kernel 3: GEMM1 = L^T R (single-term fp16) ---------------
__global__ __launch_bounds__(256, 2) void gemm1_mma()
{
    extern __shared__ __align__(128) char smem[];
    uint32_t sb = smem_u32(smem);
    int tid = threadIdx.x, lane = tid & 31, wid = tid >> 5;
    int i0 = blockIdx.y * 128;     // bc (M)
    int j0 = blockIdx.x * 128;     // de (N)
    int m_base = (wid & 1) * 64, n_base = (wid >> 1) * 32;

    const __half* base[2] = {
        g_Lh + (size_t)i0 * N_SEQ, g_Rh + (size_t)j0 * N_SEQ };

    uint32_t soff[2]; int gofs[2];
    #pragma unroll
    for (int i = 0; i < 2; i++) {
        int ch = tid + (i << 8);
        int m = ch >> 2, c = ch & 3;
        soff[i] = swz(m, c);
        gofs[i] = m * N_SEQ + c * 8;
    }

    uint32_t aoff[4][2], boff[2][2];
    #pragma unroll
    for (int mt = 0; mt < 4; mt++)
        #pragma unroll
        for (int ks = 0; ks < 2; ks++)
            aoff[mt][ks] = swz(m_base + mt * 16 + (lane & 15), ks * 2 + (lane >> 4));
    #pragma unroll
    for (int n2 = 0; n2 < 2; n2++)
        #pragma unroll
        for (int ks = 0; ks < 2; ks++)
            boff[n2][ks] = swz(n_base + n2 * 16 + (lane & 15), ks * 2 + (lane >> 4));

    float acc[4][4][4];
    #pragma unroll
    for (int a = 0; a < 4; a++)
        #pragma unroll
        for (int b = 0; b < 4; b++)
            #pragma unroll
            for (int c = 0; c < 4; c++) acc[a][b][c] = 0.f;

    #pragma unroll
    for (int s = 0; s < 2; s++) {
        #pragma unroll
        for (int t = 0; t < 2; t++)
            #pragma unroll
            for (int i = 0; i < 2; i++)
                CP_ASYNC16(sb + s * G_STAGE + t * TILE_B + soff[i],
                           base[t] + gofs[i] + s * 32);
        CP_COMMIT();
    }

    for (int kt = 0; kt < 16; kt++) {
        CP_WAIT(1);
        __syncthreads();
        if (kt + 2 < 16) {
            uint32_t so = (uint32_t)((kt + 2) % 3) * G_STAGE;
            #pragma unroll
            for (int t = 0; t < 2; t++)
                #pragma unroll
                for (int i = 0; i < 2; i++)
                    CP_ASYNC16(sb + so + t * TILE_B + soff[i],
                               base[t] + gofs[i] + (kt + 2) * 32);
        }
        CP_COMMIT();
        uint32_t stb = sb + (uint32_t)(kt % 3) * G_STAGE;
        #pragma unroll
        for (int ks = 0; ks < 2; ks++) {
            uint32_t ah[4][4], bh[2][4];
            #pragma unroll
            for (int mt = 0; mt < 4; mt++)
                LDSM_X4(ah[mt], stb + aoff[mt][ks]);
            #pragma unroll
            for (int n2 = 0; n2 < 2; n2++)
                LDSM_X4(bh[n2], stb + TILE_B + boff[n2][ks]);
            #pragma unroll
            for (int mt = 0; mt < 4; mt++)
                #pragma unroll
                for (int nt = 0; nt < 4; nt++)
                    MMA_F16(acc[mt][nt], ah[mt], bh[nt >> 1][nt & 1],
                            bh[nt >> 1][(nt & 1) + 2]);
        }
    }

    // epilogue: scatter into smem (single fp16, permuted), then coalesced copy
    __syncthreads();
    int g = lane >> 2, tg = lane & 3;
    #pragma unroll
    for (int mt = 0; mt < 4; mt++) {
        #pragma unroll
        for (int h = 0; h < 2; h++) {
            int rr = m_base + mt * 16 + g + h * 8;
            int bl = rr >> 5, c = rr & 31;
            #pragma unroll
            for (int nt = 0; nt < 4; nt++) {
                int q = n_base + nt * 8 + tg * 2;
                int dl = q >> 5, e = q & 31;
                int p = bl * 4 + dl;
                uint32_t off = (uint32_t)(p * 2048 + (c * 32 + e) * 2);
                *(__half2*)(smem + off) = __halves2half2(
                    __float2half_rn(acc[mt][nt][h * 2 + 0]),
                    __float2half_rn(acc[mt][nt][h * 2 + 1]));
            }
        }
    }
    __syncthreads();
    int b0 = blockIdx.y * 4, d0 = blockIdx.x * 4;
    #pragma unroll
    for (int i = 0; i < 8; i++) {
        int qc = tid + 256 * i;
        int p = qc >> 7, off = qc & 127;
        size_t row = (size_t)((b0 + (p >> 2)) * N_RES + d0 + (p & 3)) * KCE + off * 8;
        *(uint4*)(g_iPhi + row) = *(const uint4*)(smem + qc * 16);
    }
}

// ---------------- Kernel 4: GEMM2 = interP @ Wt^T + b, / norm (1-term) -----
__global__ __launch_bounds__(256, 2) void gemm2_mma(
    const float* __restrict__ ob, float* __restrict__ out)
{
    extern __shared__ __align__(128) char smem[];
    uint32_t sb = smem_u32(smem);
    int tid = threadIdx.x, lane = tid & 31, wid = tid >> 5;
    int m0 = blockIdx.x * 128;
    int m_base = (wid & 1) * 64, n_base = (wid >> 1) * 32;

    const __half* base[2] = { g_iPhi + (size_t)m0 * KCE, g_Wt };

    uint32_t soff[2]; int gofs[2];
    #pragma unroll
    for (int i = 0; i < 2; i++) {
        int ch = tid + (i << 8);
        int m = ch >> 2, c = ch & 3;
        soff[i] = swz(m, c);
        gofs[i] = m * KCE + c * 8;
    }

    uint32_t aoff[4][2], boff[2][2];
    #pragma unroll
    for (int mt = 0; mt < 4; mt++)
        #pragma unroll
        for (int ks = 0; ks < 2; ks++)
            aoff[mt][ks] = swz(m_base + mt * 16 + (lane & 15), ks * 2 + (lane >> 4));
    #pragma unroll
    for (int n2 = 0; n2 < 2; n2++)
        #pragma unroll
        for (int ks = 0; ks < 2; ks++)
            boff[n2][ks] = swz(n_base + n2 * 16 + (lane & 15), ks * 2 + (lane >> 4));

    float acc[4][4][4];
    #pragma unroll
    for (int a = 0; a < 4; a++)
        #pragma unroll
        for (int b = 0; b < 4; b++)
            #pragma unroll
            for (int c = 0; c < 4; c++) acc[a][b][c] = 0.f;

    #pragma unroll
    for (int s = 0; s < 2; s++) {
        #pragma unroll
        for (int t = 0; t < 2; t++)
            #pragma unroll
            for (int i = 0; i < 2; i++)
                CP_ASYNC16(sb + s * G_STAGE + t * TILE_B + soff[i],
                           base[t] + gofs[i] + s * 32);
        CP_COMMIT();
    }

    for (int kt = 0; kt < 32; kt++) {
        CP_WAIT(1);
        __syncthreads();
        if (kt + 2 < 32) {
            uint32_t so = (uint32_t)((kt + 2) % 3) * G_STAGE;
            #pragma unroll
            for (int t = 0; t < 2; t++)
                #pragma unroll
                for (int i = 0; i < 2; i++)
                    CP_ASYNC16(sb + so + t * TILE_B + soff[i],
                               base[t] + gofs[i] + (kt + 2) * 32);
        }
        CP_COMMIT();
        uint32_t stb = sb + (uint32_t)(kt % 3) * G_STAGE;
        #pragma unroll
        for (int ks = 0; ks < 2; ks++) {
            uint32_t ah[4][4], bh[2][4];
            #pragma unroll
            for (int mt = 0; mt < 4; mt++)
                LDSM_X4(ah[mt], stb + aoff[mt][ks]);
            #pragma unroll
            for (int n2 = 0; n2 < 2; n2++)
                LDSM_X4(bh[n2], stb + TILE_B + boff[n2][ks]);
            #pragma unroll
            for (int mt = 0; mt < 4; mt++)
                #pragma unroll
                for (int nt = 0; nt < 4; nt++)
                    MMA_F16(acc[mt][nt], ah[mt], bh[nt >> 1][nt & 1],
                            bh[nt >> 1][(nt & 1) + 2]);
        }
    }

    int g = lane >> 2, tg = lane & 3;
    #pragma unroll
    for (int mt = 0; mt < 4; mt++) {
        #pragma unroll
        for (int h = 0; h < 2; h++) {
            int m = m0 + m_base + mt * 16 + g + h * 8;
            float inv = g_ninv[m];
            #pragma unroll
            for (int nt = 0; nt < 4; nt++) {
                int f = n_base + nt * 8 + tg * 2;
                float2 v;
                v.x = (acc[mt][nt][h * 2 + 0] + ob[f + 0]) * inv;
                v.y = (acc[mt][nt][h * 2 + 1] + ob[f + 1]) * inv;
                *(float2*)&out[(size_t)m * C_Z + f] = v;
            }
        }
    }
}

// ---------------------------------------------------------------------------
extern "C" void kernel_launch(void* const* d_in, const int* in_sizes, int n_in,
                              void* d_out, int out_size)
{
    const float* act       = (const float*)d_in[0];
    const float* mask      = (const float*)d_in[1];
    const float* ln_scale  = (const float*)d_in[2];
    const float* ln_offset = (const float*)d_in[3];
    const float* left_w    = (const float*)d_in[4];
    const float* left_b    = (const float*)d_in[5];
    const float* right_w   = (const float*)d_in[6];
    const float* right_b   = (const float*)d_in[7];
    const float* output_w  = (const float*)d_in[8];
    const float* output_b  = (const float*)d_in[9];
    float* out = (float*)d_out;

    cudaFuncSetAttribute(ln_proj_mma, cudaFuncAttributeMaxDynamicSharedMemorySize, LNP_SMEM);
    cudaFuncSetAttribute(gemm1_mma, cudaFuncAttributeMaxDynamicSharedMemorySize, G_SMEM);
    cudaFuncSetAttribute(gemm2_mma, cudaFuncAttributeMaxDynamicSharedMemorySize, G_SMEM);

    // launches: prep(1), ln_proj_mma(2), gemm1(3), gemm2(4 = profiler slot)
    prep_kernel<<<705, 256>>>(mask, output_w, left_w, right_w);
    ln_proj_mma<<<N_SEQ * N_RES / 64, 256, LNP_SMEM>>>(act, mask, ln_scale, ln_offset,
                                                       left_b, right_b);
    gemm1_mma<<<dim3(BC / 128, BC / 128), 256, G_SMEM>>>();
    gemm2_mma<<<NPAIR / 128, 256, G_SMEM>>>(output_b, out);
}